// round 10
// baseline (speedup 1.0000x reference)
#include <cuda_runtime.h>
#include <cuda_bf16.h>
#include <mma.h>
#include <math.h>
#include <stdint.h>
#include <stdio.h>

using namespace nvcuda;

#define NN   30000
#define TT   16
#define DE   32
#define HE   128
#define F3   384
#define NE0  300000
#define NE   330000
#define NT   3000
#define HD   256
#define OUTL 25

// ---------------- scratch ----------------
__device__ __align__(256) float g_EMB[NN*TT*DE];
__device__ __align__(256) float g_GX[(long)NN*TT*F3];
__device__ __align__(256) float g_H[NN*HE];
__device__ __align__(256) float g_H2[NN*HE];
__device__ __align__(256) float g_HENC[NN*HE];
__device__ __align__(256) float g_F1[NN*F3];
__device__ __align__(256) float g_O1[NN*F3];
__device__ __align__(256) float g_F2[NN*F3];
__device__ __align__(256) float g_O2[NN*F3];
__device__ __align__(256) float g_asv[NN*3];
__device__ __align__(256) float g_adv[NN*3];
__device__ __align__(256) float g_ENC[NT*HE];
__device__ __align__(256) float g_X0[NT*4*HD];
__device__ __align__(256) float g_c0[NT*HD];
__device__ __align__(256) float g_c1[NT*HD];
__device__ __align__(256) float g_h0a[NT*HD];
__device__ __align__(256) float g_h0b[NT*HD];
__device__ __align__(256) float g_h1a[NT*HD];
__device__ __align__(256) float g_h1b[NT*HD];
__device__ int g_cnt[NN];
__device__ int g_offs[NN+1];
__device__ int g_cur[NN];
__device__ int g_ssrc[NE];
__device__ float g_gbxp[F3];
__device__ float g_gbhp[F3];
__device__ float g_l0bp[4*HD];
__device__ float g_l1bp[4*HD];
__device__ unsigned long long g_ts[16];
#define WT_TOTAL 1250000
__device__ __align__(256) __nv_bfloat16 g_WThi[WT_TOTAL];
__device__ __align__(256) __nv_bfloat16 g_WTlo[WT_TOTAL];

__device__ __forceinline__ float sigf(float x){ return 1.f/(1.f+__expf(-x)); }
__device__ __forceinline__ float lk01(float x){ return x>=0.f? x : 0.1f*x; }

// ---------------- timing stamps ----------------
__global__ void stamp(int i){
    if (threadIdx.x == 0) {
        unsigned long long t;
        asm volatile("mov.u64 %0, %%globaltimer;" : "=l"(t));
        g_ts[i] = t;
    }
}
__global__ void stamp_print(){
    if (threadIdx.x == 0) {
        double d[11];
        for (int i = 0; i < 10; ++i) d[i] = (double)(g_ts[i+1]-g_ts[i])*1e-3;
        d[10] = (double)(g_ts[10]-g_ts[0])*1e-3;
        printf("TSus pA=%.0f gx=%.0f pB=%.0f csr=%.0f gru=%.0f dyn=%.0f gat1=%.0f gat2=%.0f fcx=%.0f dec=%.0f tot=%.0f\n",
               d[0],d[1],d[2],d[3],d[4],d[5],d[6],d[7],d[8],d[9],d[10]);
    }
}

// ---------------- utility ----------------
__global__ void zero_f(float* __restrict__ p, long n){
    long i = (long)blockIdx.x*blockDim.x + threadIdx.x;
    if (i < n) p[i] = 0.f;
}
__global__ void zero_i(int* __restrict__ p, int n){
    int i = blockIdx.x*blockDim.x + threadIdx.x;
    if (i < n) p[i] = 0;
}

// W[K,N] fp32 -> bf16 hi/lo at [np*ldk + kofs + k], np = (n % (N/P))*P + n/(N/P)
__global__ void wsplitp(const float* __restrict__ W, __nv_bfloat16* __restrict__ hi,
                        __nv_bfloat16* __restrict__ lo, int K, int N, int P,
                        int ldk, int kofs)
{
    int idx = blockIdx.x*blockDim.x + threadIdx.x;
    if (idx >= K*N) return;
    int k = idx / N, n = idx - k*N;
    int Gp = N / P;
    int np = (n % Gp)*P + n/Gp;
    float v = W[idx];
    __nv_bfloat16 h = __float2bfloat16(v);
    hi[(long)np*ldk + kofs + k] = h;
    lo[(long)np*ldk + kofs + k] = __float2bfloat16(v - __bfloat162float(h));
}

__global__ void bperm(const float* __restrict__ b, float* __restrict__ bp, int N, int P)
{
    int n = blockIdx.x*blockDim.x + threadIdx.x;
    if (n >= N) return;
    int Gp = N / P;
    bp[(n % Gp)*P + n/Gp] = b[n];
}

typedef wmma::fragment<wmma::matrix_a, 16,16,16, __nv_bfloat16, wmma::row_major> FragA;
typedef wmma::fragment<wmma::matrix_b, 16,16,16, __nv_bfloat16, wmma::col_major> FragB;
typedef wmma::fragment<wmma::accumulator, 16,16,16, float> FragC;

// ---------------- generic WMMA bf16x3 GEMM ----------------
// PRE: leaky on A load; ACT: leaky on output; rowidx: gather A rows.
#define WBM 128
#define WBN 64
#define WBK 32
#define SKA 40
#define SKB 40
#define SCC 72
#define MMA_SMEM 36864

template<int PRE, int ACT>
__global__ void __launch_bounds__(256,2)
mma_gemm(const float* __restrict__ A1, const __nv_bfloat16* __restrict__ W1h,
         const __nv_bfloat16* __restrict__ W1l, int K1,
         const float* __restrict__ bias, const int* __restrict__ rowidx,
         float* __restrict__ C, int M, int N)
{
    extern __shared__ char smc[];
    __nv_bfloat16* Ah = (__nv_bfloat16*)smc;
    __nv_bfloat16* Al = Ah + WBM*SKA;
    __nv_bfloat16* Bh = Al + WBM*SKA;
    __nv_bfloat16* Bl = Bh + WBN*SKB;
    float* Cs = (float*)smc;

    const int tid = threadIdx.x, wid = tid >> 5;
    const int warp_m = wid >> 1, warp_n = wid & 1;
    const long bm = (long)blockIdx.y * WBM;
    const int bn = blockIdx.x * WBN;

    FragC acc[2][2];
    #pragma unroll
    for (int mm = 0; mm < 2; ++mm)
        #pragma unroll
        for (int nn = 0; nn < 2; ++nn)
            wmma::fill_fragment(acc[mm][nn], 0.f);

    for (int k0 = 0; k0 < K1; k0 += WBK) {
        #pragma unroll
        for (int i = 0; i < 4; ++i) {
            int li = tid + (i << 8);
            int r = li >> 3, c = (li & 7) << 2;
            float4 v = make_float4(0.f,0.f,0.f,0.f);
            if (bm + r < M) {
                long ar = rowidx ? (long)rowidx[bm + r] : (bm + r);
                v = *(const float4*)(A1 + ar*K1 + k0 + c);
            }
            if (PRE) { v.x=lk01(v.x); v.y=lk01(v.y); v.z=lk01(v.z); v.w=lk01(v.w); }
            __nv_bfloat16 hx = __float2bfloat16(v.x);
            __nv_bfloat16 hy = __float2bfloat16(v.y);
            __nv_bfloat16 hz = __float2bfloat16(v.z);
            __nv_bfloat16 hw = __float2bfloat16(v.w);
            int o = r*SKA + c;
            Ah[o]   = hx; Ah[o+1] = hy; Ah[o+2] = hz; Ah[o+3] = hw;
            Al[o]   = __float2bfloat16(v.x - __bfloat162float(hx));
            Al[o+1] = __float2bfloat16(v.y - __bfloat162float(hy));
            Al[o+2] = __float2bfloat16(v.z - __bfloat162float(hz));
            Al[o+3] = __float2bfloat16(v.w - __bfloat162float(hw));
        }
        {
            int r = tid >> 2, c = (tid & 3) << 3;
            long go = (long)(bn + r)*K1 + k0 + c;
            *(uint4*)&Bh[r*SKB + c] = *(const uint4*)(W1h + go);
            *(uint4*)&Bl[r*SKB + c] = *(const uint4*)(W1l + go);
        }
        __syncthreads();

        #pragma unroll
        for (int kk = 0; kk < WBK; kk += 16) {
            FragA ah[2], al[2];
            FragB bh[2], bl[2];
            #pragma unroll
            for (int mm = 0; mm < 2; ++mm) {
                int ro = (warp_m*32 + mm*16)*SKA + kk;
                wmma::load_matrix_sync(ah[mm], Ah + ro, SKA);
                wmma::load_matrix_sync(al[mm], Al + ro, SKA);
            }
            #pragma unroll
            for (int nn = 0; nn < 2; ++nn) {
                int no = (warp_n*32 + nn*16)*SKB + kk;
                wmma::load_matrix_sync(bh[nn], Bh + no, SKB);
                wmma::load_matrix_sync(bl[nn], Bl + no, SKB);
            }
            #pragma unroll
            for (int mm = 0; mm < 2; ++mm)
                #pragma unroll
                for (int nn = 0; nn < 2; ++nn) {
                    wmma::mma_sync(acc[mm][nn], ah[mm], bh[nn], acc[mm][nn]);
                    wmma::mma_sync(acc[mm][nn], ah[mm], bl[nn], acc[mm][nn]);
                    wmma::mma_sync(acc[mm][nn], al[mm], bh[nn], acc[mm][nn]);
                }
        }
        __syncthreads();
    }

    #pragma unroll
    for (int mm = 0; mm < 2; ++mm)
        #pragma unroll
        for (int nn = 0; nn < 2; ++nn)
            wmma::store_matrix_sync(Cs + (warp_m*32 + mm*16)*SCC + warp_n*32 + nn*16,
                                    acc[mm][nn], SCC, wmma::mem_row_major);
    __syncthreads();

    #pragma unroll
    for (int i = 0; i < 8; ++i) {
        int li = tid + (i << 8);
        int r = li >> 4, c = (li & 15) << 2;
        long row = bm + r;
        if (row >= M) continue;
        float4 v = *(float4*)&Cs[r*SCC + c];
        int col = bn + c;
        if (bias) {
            float4 bb = *(const float4*)(bias + col);
            v.x += bb.x; v.y += bb.y; v.z += bb.z; v.w += bb.w;
        }
        if (ACT) { v.x=lk01(v.x); v.y=lk01(v.y); v.z=lk01(v.z); v.w=lk01(v.w); }
        *(float4*)(C + row*(long)N + col) = v;
    }
}

// ---------------- GRU step GEMM with fused gates ----------------
#define GLDC 100
#define GRU_SMEM 51200

__global__ void __launch_bounds__(256,2)
gru_step(const float* __restrict__ Hin, const __nv_bfloat16* __restrict__ Wh,
         const __nv_bfloat16* __restrict__ Wl, float* __restrict__ Hout, int t)
{
    extern __shared__ char sm[];
    __nv_bfloat16* Ah = (__nv_bfloat16*)sm;           // [128][40]
    __nv_bfloat16* Al = Ah + 128*SKA;
    __nv_bfloat16* Bh = Al + 128*SKA;                 // [96][40]
    __nv_bfloat16* Bl = Bh + 96*SKB;
    float* Cs = (float*)sm;                           // [128][100]

    const int tid = threadIdx.x, wid = tid >> 5;
    const int warp_m = wid >> 1, warp_n = wid & 1;
    const long bm = (long)blockIdx.y * 128;
    const int bn = blockIdx.x * 96;

    FragC acc[2][3];
    #pragma unroll
    for (int mf = 0; mf < 2; ++mf)
        #pragma unroll
        for (int nf = 0; nf < 3; ++nf)
            wmma::fill_fragment(acc[mf][nf], 0.f);

    for (int k0 = 0; k0 < HE; k0 += WBK) {
        #pragma unroll
        for (int i = 0; i < 4; ++i) {
            int li = tid + (i << 8);
            int r = li >> 3, c = (li & 7) << 2;
            float4 v = make_float4(0.f,0.f,0.f,0.f);
            if (bm + r < NN) v = *(const float4*)(Hin + (bm+r)*HE + k0 + c);
            __nv_bfloat16 hx = __float2bfloat16(v.x);
            __nv_bfloat16 hy = __float2bfloat16(v.y);
            __nv_bfloat16 hz = __float2bfloat16(v.z);
            __nv_bfloat16 hw = __float2bfloat16(v.w);
            int o = r*SKA + c;
            Ah[o]   = hx; Ah[o+1] = hy; Ah[o+2] = hz; Ah[o+3] = hw;
            Al[o]   = __float2bfloat16(v.x - __bfloat162float(hx));
            Al[o+1] = __float2bfloat16(v.y - __bfloat162float(hy));
            Al[o+2] = __float2bfloat16(v.z - __bfloat162float(hz));
            Al[o+3] = __float2bfloat16(v.w - __bfloat162float(hw));
        }
        #pragma unroll
        for (int i = 0; i < 2; ++i) {
            int li = tid + (i << 8);
            if (li < 384) {
                int r = li >> 2, c = (li & 3) << 3;
                long go = (long)(bn + r)*HE + k0 + c;
                *(uint4*)&Bh[r*SKB + c] = *(const uint4*)(Wh + go);
                *(uint4*)&Bl[r*SKB + c] = *(const uint4*)(Wl + go);
            }
        }
        __syncthreads();

        #pragma unroll
        for (int kk = 0; kk < WBK; kk += 16) {
            FragA ah[2], al[2];
            #pragma unroll
            for (int mf = 0; mf < 2; ++mf) {
                int ro = (warp_m*32 + mf*16)*SKA + kk;
                wmma::load_matrix_sync(ah[mf], Ah + ro, SKA);
                wmma::load_matrix_sync(al[mf], Al + ro, SKA);
            }
            #pragma unroll
            for (int nf = 0; nf < 3; ++nf) {
                int no = (warp_n*48 + nf*16)*SKB + kk;
                FragB bh, bl;
                wmma::load_matrix_sync(bh, Bh + no, SKB);
                wmma::load_matrix_sync(bl, Bl + no, SKB);
                #pragma unroll
                for (int mf = 0; mf < 2; ++mf) {
                    wmma::mma_sync(acc[mf][nf], ah[mf], bh, acc[mf][nf]);
                    wmma::mma_sync(acc[mf][nf], ah[mf], bl, acc[mf][nf]);
                    wmma::mma_sync(acc[mf][nf], al[mf], bh, acc[mf][nf]);
                }
            }
        }
        __syncthreads();
    }

    #pragma unroll
    for (int mf = 0; mf < 2; ++mf)
        #pragma unroll
        for (int nf = 0; nf < 3; ++nf)
            wmma::store_matrix_sync(Cs + (warp_m*32 + mf*16)*GLDC + warp_n*48 + nf*16,
                                    acc[mf][nf], GLDC, wmma::mem_row_major);
    __syncthreads();

    #pragma unroll
    for (int i = 0; i < 16; ++i) {
        int li = tid + (i << 8);
        int r = li >> 5, q = li & 31;
        long node = bm + r;
        if (node < NN) {
            int jg = blockIdx.x*32 + q;
            const float* gsr = Cs + r*GLDC + 3*q;
            float ghr = gsr[0] + g_gbhp[3*jg+0];
            float ghz = gsr[1] + g_gbhp[3*jg+1];
            float ghn = gsr[2] + g_gbhp[3*jg+2];
            const float* gx = g_GX + (node*TT + t)*F3 + 3*jg;
            float rr = sigf(gx[0] + ghr);
            float zz = sigf(gx[1] + ghz);
            float nn2 = tanhf(gx[2] + rr*ghn);
            float hold = Hin[node*HE + jg];
            Hout[node*HE + jg] = (1.f - zz)*nn2 + zz*hold;
        }
    }
}

// ---------------- decoder step GEMM with fused LSTM gates ----------------
template<int L1>
__global__ void __launch_bounds__(256,2)
dec_gemm(const float* __restrict__ A1, const float* __restrict__ A2,
         const __nv_bfloat16* __restrict__ Wh, const __nv_bfloat16* __restrict__ Wl,
         const float* __restrict__ pre, float* __restrict__ cbuf,
         float* __restrict__ hout, int first)
{
    extern __shared__ char sm[];
    __nv_bfloat16* Ah = (__nv_bfloat16*)sm;
    __nv_bfloat16* Al = Ah + 128*SKA;
    __nv_bfloat16* Bh = Al + 128*SKA;
    __nv_bfloat16* Bl = Bh + 64*SKB;
    float* Cs = (float*)sm;

    const int tid = threadIdx.x, wid = tid >> 5;
    const int warp_m = wid >> 1, warp_n = wid & 1;
    const long bm = (long)blockIdx.y * 128;
    const int bn = blockIdx.x * 64;
    const int KTOT = L1 ? 2*HD : HD;

    FragC acc[2][2];
    #pragma unroll
    for (int mm = 0; mm < 2; ++mm)
        #pragma unroll
        for (int nn = 0; nn < 2; ++nn)
            wmma::fill_fragment(acc[mm][nn], 0.f);

    for (int k0 = 0; k0 < KTOT; k0 += WBK) {
        const float* A = (L1 && k0 >= HD) ? A2 : A1;
        const int ka = k0 & (HD-1);
        #pragma unroll
        for (int i = 0; i < 4; ++i) {
            int li = tid + (i << 8);
            int r = li >> 3, c = (li & 7) << 2;
            float4 v = make_float4(0.f,0.f,0.f,0.f);
            if (bm + r < NT) v = *(const float4*)(A + (bm+r)*HD + ka + c);
            __nv_bfloat16 hx = __float2bfloat16(v.x);
            __nv_bfloat16 hy = __float2bfloat16(v.y);
            __nv_bfloat16 hz = __float2bfloat16(v.z);
            __nv_bfloat16 hw = __float2bfloat16(v.w);
            int o = r*SKA + c;
            Ah[o]   = hx; Ah[o+1] = hy; Ah[o+2] = hz; Ah[o+3] = hw;
            Al[o]   = __float2bfloat16(v.x - __bfloat162float(hx));
            Al[o+1] = __float2bfloat16(v.y - __bfloat162float(hy));
            Al[o+2] = __float2bfloat16(v.z - __bfloat162float(hz));
            Al[o+3] = __float2bfloat16(v.w - __bfloat162float(hw));
        }
        {
            int r = tid >> 2, c = (tid & 3) << 3;
            long go = (long)(bn + r)*KTOT + k0 + c;
            *(uint4*)&Bh[r*SKB + c] = *(const uint4*)(Wh + go);
            *(uint4*)&Bl[r*SKB + c] = *(const uint4*)(Wl + go);
        }
        __syncthreads();

        #pragma unroll
        for (int kk = 0; kk < WBK; kk += 16) {
            FragA ah[2], al[2];
            FragB bh[2], bl[2];
            #pragma unroll
            for (int mm = 0; mm < 2; ++mm) {
                int ro = (warp_m*32 + mm*16)*SKA + kk;
                wmma::load_matrix_sync(ah[mm], Ah + ro, SKA);
                wmma::load_matrix_sync(al[mm], Al + ro, SKA);
            }
            #pragma unroll
            for (int nn = 0; nn < 2; ++nn) {
                int no = (warp_n*32 + nn*16)*SKB + kk;
                wmma::load_matrix_sync(bh[nn], Bh + no, SKB);
                wmma::load_matrix_sync(bl[nn], Bl + no, SKB);
            }
            #pragma unroll
            for (int mm = 0; mm < 2; ++mm)
                #pragma unroll
                for (int nn = 0; nn < 2; ++nn) {
                    wmma::mma_sync(acc[mm][nn], ah[mm], bh[nn], acc[mm][nn]);
                    wmma::mma_sync(acc[mm][nn], ah[mm], bl[nn], acc[mm][nn]);
                    wmma::mma_sync(acc[mm][nn], al[mm], bh[nn], acc[mm][nn]);
                }
        }
        __syncthreads();
    }

    #pragma unroll
    for (int mm = 0; mm < 2; ++mm)
        #pragma unroll
        for (int nn = 0; nn < 2; ++nn)
            wmma::store_matrix_sync(Cs + (warp_m*32 + mm*16)*68 + warp_n*32 + nn*16,
                                    acc[mm][nn], 68, wmma::mem_row_major);
    __syncthreads();

    #pragma unroll
    for (int i = 0; i < 8; ++i) {
        int li = tid + (i << 8);
        int r = li >> 4, q = li & 15;
        long row = bm + r;
        if (row < NT) {
            int j = blockIdx.x*16 + q;
            const float* gs = Cs + r*68 + 4*q;
            const float* pp = L1 ? (pre + bn + 4*q) : (pre + row*(4*HD) + bn + 4*q);
            float ig = sigf(gs[0] + pp[0]);
            float fg = sigf(gs[1] + pp[1]);
            float gg = tanhf(gs[2] + pp[2]);
            float og = sigf(gs[3] + pp[3]);
            float c = first ? 0.f : cbuf[row*HD + j];
            c = fg*c + ig*gg;
            cbuf[row*HD + j] = c;
            hout[row*HD + j] = og*tanhf(c);
        }
    }
}

// ---------------- encoder embedding ----------------
__global__ void emb_kernel(const float* __restrict__ x, const float* __restrict__ ipW,
                           const float* __restrict__ ipb)
{
    long i = (long)blockIdx.x*blockDim.x + threadIdx.x;
    if (i >= (long)NN*TT*DE) return;
    long row = i >> 5; int j = (int)(i & 31);
    float v = x[row*2]*ipW[j] + x[row*2+1]*ipW[DE+j] + ipb[j];
    g_EMB[i] = lk01(v);
}

// ---------------- CSR build ----------------
__global__ void edge_count(const int* __restrict__ ei){
    int e = blockIdx.x*blockDim.x + threadIdx.x;
    if (e >= NE) return;
    int d = (e < NE0) ? ei[NE0+e] : (e - NE0);
    atomicAdd(&g_cnt[d], 1);
}
__global__ void scan_kernel(){
    __shared__ int sh[1024];
    __shared__ int run;
    int tid = threadIdx.x;
    if (tid == 0) run = 0;
    __syncthreads();
    for (int base = 0; base < NN; base += 1024) {
        int v = (base + tid < NN) ? g_cnt[base + tid] : 0;
        sh[tid] = v; __syncthreads();
        for (int off = 1; off < 1024; off <<= 1) {
            int tv = (tid >= off) ? sh[tid-off] : 0;
            __syncthreads();
            sh[tid] += tv;
            __syncthreads();
        }
        if (base + tid < NN) g_offs[base + tid + 1] = run + sh[tid];
        __syncthreads();
        if (tid == 0) run += sh[1023];
        __syncthreads();
    }
    if (tid == 0) g_offs[0] = 0;
}
__global__ void copy_cur(){
    int i = blockIdx.x*blockDim.x + threadIdx.x;
    if (i < NN) g_cur[i] = g_offs[i];
}
__global__ void edge_scatter(const int* __restrict__ ei){
    int e = blockIdx.x*blockDim.x + threadIdx.x;
    if (e >= NE) return;
    int s, d;
    if (e < NE0) { s = ei[e]; d = ei[NE0+e]; } else { s = e - NE0; d = s; }
    int pos = atomicAdd(&g_cur[d], 1);
    g_ssrc[pos] = s;
}

// ---------------- GAT ----------------
__global__ void attn_coef(const float* __restrict__ F, const float* __restrict__ a_s,
                          const float* __restrict__ a_d)
{
    int w = (blockIdx.x*blockDim.x + threadIdx.x) >> 5;
    if (w >= NN*3) return;
    int lane = threadIdx.x & 31;
    int node = w / 3, h = w - node*3;
    const float* f = F + (long)node*F3 + h*HE;
    const float* As_ = a_s + h*HE;
    const float* Ad_ = a_d + h*HE;
    float s1 = 0.f, s2 = 0.f;
    #pragma unroll
    for (int c = lane; c < HE; c += 32) { float fv = f[c]; s1 += fv*As_[c]; s2 += fv*Ad_[c]; }
    #pragma unroll
    for (int o = 16; o; o >>= 1) {
        s1 += __shfl_down_sync(0xffffffffu, s1, o);
        s2 += __shfl_down_sync(0xffffffffu, s2, o);
    }
    if (lane == 0) { g_asv[w] = s1; g_adv[w] = s2; }
}

__global__ void gat_agg(const float* __restrict__ F, const float* __restrict__ bias,
                        float* __restrict__ O)
{
    int w = (blockIdx.x*blockDim.x + threadIdx.x) >> 5;
    if (w >= NN) return;
    int lane = threadIdx.x & 31;
    int beg = g_offs[w], end = g_offs[w+1];
    float ad0 = g_adv[w*3], ad1 = g_adv[w*3+1], ad2 = g_adv[w*3+2];
    float m0 = -1e30f, m1 = -1e30f, m2 = -1e30f;
    float d0 = 0.f, d1 = 0.f, d2 = 0.f;
    float acc[12];
    #pragma unroll
    for (int q = 0; q < 12; ++q) acc[q] = 0.f;

    for (int p = beg; p < end; ++p) {
        int s = g_ssrc[p];
        float e0 = g_asv[s*3]   + ad0; e0 = (e0 >= 0.f) ? e0 : 0.2f*e0;
        float e1 = g_asv[s*3+1] + ad1; e1 = (e1 >= 0.f) ? e1 : 0.2f*e1;
        float e2 = g_asv[s*3+2] + ad2; e2 = (e2 >= 0.f) ? e2 : 0.2f*e2;
        const float* f = F + (long)s*F3;
        {
            float nm = fmaxf(m0, e0); float sc = __expf(m0-nm); float wv = __expf(e0-nm);
            d0 = d0*sc + wv;
            #pragma unroll
            for (int q = 0; q < 4; ++q) acc[q] = acc[q]*sc + wv*f[q*32 + lane];
            m0 = nm;
        }
        {
            float nm = fmaxf(m1, e1); float sc = __expf(m1-nm); float wv = __expf(e1-nm);
            d1 = d1*sc + wv;
            #pragma unroll
            for (int q = 0; q < 4; ++q) acc[4+q] = acc[4+q]*sc + wv*f[HE + q*32 + lane];
            m1 = nm;
        }
        {
            float nm = fmaxf(m2, e2); float sc = __expf(m2-nm); float wv = __expf(e2-nm);
            d2 = d2*sc + wv;
            #pragma unroll
            for (int q = 0; q < 4; ++q) acc[8+q] = acc[8+q]*sc + wv*f[2*HE + q*32 + lane];
            m2 = nm;
        }
    }
    float* o = O + (long)w*F3;
    #pragma unroll
    for (int q = 0; q < 4; ++q) {
        int c0 = q*32 + lane;
        o[c0]        = acc[q]  /d0 + bias[c0];
        o[HE + c0]   = acc[4+q]/d1 + bias[HE + c0];
        o[2*HE + c0] = acc[8+q]/d2 + bias[2*HE + c0];
    }
}

// ---------------- output head ----------------
__global__ void out_head(const float* __restrict__ h1, const float* __restrict__ opW,
                         const float* __restrict__ opb, float* __restrict__ out, int t)
{
    int w = (blockIdx.x*blockDim.x + threadIdx.x) >> 5;
    if (w >= NT) return;
    int lane = threadIdx.x & 31;
    const float* h = h1 + (long)w*HD;
    float s0 = 0.f, s1 = 0.f;
    #pragma unroll
    for (int k = lane; k < HD; k += 32) {
        float hv = h[k];
        s0 += hv*opW[k*2];
        s1 += hv*opW[k*2+1];
    }
    #pragma unroll
    for (int o = 16; o; o >>= 1) {
        s0 += __shfl_down_sync(0xffffffffu, s0, o);
        s1 += __shfl_down_sync(0xffffffffu, s1, o);
    }
    if (lane == 0) {
        long base = ((long)w*OUTL + t)*2;
        out[base]   = s0 + opb[0];
        out[base+1] = s1 + opb[1];
    }
}

// ---------------- host ----------------
template<int PRE, int ACT>
static inline void mmagemm(const float* A, const __nv_bfloat16* Wh, const __nv_bfloat16* Wl, int K,
                           const float* bias, const int* ridx, float* C, long M, int N)
{
    dim3 g(N/WBN, (unsigned)((M + WBM - 1)/WBM));
    mma_gemm<PRE,ACT><<<g, 256, MMA_SMEM>>>(A, Wh, Wl, K, bias, ridx, C, (int)M, N);
}

extern "C" void kernel_launch(void* const* d_in, const int* in_sizes, int n_in,
                              void* d_out, int out_size)
{
    const float* x    = (const float*)d_in[0];
    const int*   ei   = (const int*)  d_in[1];
    const int*   tgt  = (const int*)  d_in[2];
    const float* ipW  = (const float*)d_in[3];
    const float* ipb  = (const float*)d_in[4];
    const float* gWx  = (const float*)d_in[5];
    const float* gWh  = (const float*)d_in[6];
    const float* gbx  = (const float*)d_in[7];
    const float* gbh  = (const float*)d_in[8];
    const float* dynW = (const float*)d_in[9];
    const float* dynb = (const float*)d_in[10];
    const float* g1W  = (const float*)d_in[11];
    const float* g1as = (const float*)d_in[12];
    const float* g1ad = (const float*)d_in[13];
    const float* g1b  = (const float*)d_in[14];
    const float* g2W  = (const float*)d_in[15];
    const float* g2as = (const float*)d_in[16];
    const float* g2ad = (const float*)d_in[17];
    const float* g2b  = (const float*)d_in[18];
    const float* fcW  = (const float*)d_in[19];
    const float* fcb  = (const float*)d_in[20];
    const float* l0Wx = (const float*)d_in[21];
    const float* l0Wh = (const float*)d_in[22];
    const float* l0b  = (const float*)d_in[23];
    const float* l1Wx = (const float*)d_in[24];
    const float* l1Wh = (const float*)d_in[25];
    const float* l1b  = (const float*)d_in[26];
    const float* opW  = (const float*)d_in[27];
    const float* opb  = (const float*)d_in[28];
    float* out = (float*)d_out;
    (void)in_sizes; (void)n_in; (void)out_size;

    float *EMB,*GX,*H,*H2,*HENC,*F1,*O1,*F2,*O2,*ENC,*X0,*c0,*c1,*h0a,*h0b,*h1a,*h1b;
    float *gbxp,*gbhp,*l0bp,*l1bp;
    __nv_bfloat16 *WTh,*WTl;
    cudaGetSymbolAddress((void**)&EMB,  g_EMB);
    cudaGetSymbolAddress((void**)&GX,   g_GX);
    cudaGetSymbolAddress((void**)&H,    g_H);
    cudaGetSymbolAddress((void**)&H2,   g_H2);
    cudaGetSymbolAddress((void**)&HENC, g_HENC);
    cudaGetSymbolAddress((void**)&F1,   g_F1);
    cudaGetSymbolAddress((void**)&O1,   g_O1);
    cudaGetSymbolAddress((void**)&F2,   g_F2);
    cudaGetSymbolAddress((void**)&O2,   g_O2);
    cudaGetSymbolAddress((void**)&ENC,  g_ENC);
    cudaGetSymbolAddress((void**)&X0,   g_X0);
    cudaGetSymbolAddress((void**)&c0,   g_c0);
    cudaGetSymbolAddress((void**)&c1,   g_c1);
    cudaGetSymbolAddress((void**)&h0a,  g_h0a);
    cudaGetSymbolAddress((void**)&h0b,  g_h0b);
    cudaGetSymbolAddress((void**)&h1a,  g_h1a);
    cudaGetSymbolAddress((void**)&h1b,  g_h1b);
    cudaGetSymbolAddress((void**)&gbxp, g_gbxp);
    cudaGetSymbolAddress((void**)&gbhp, g_gbhp);
    cudaGetSymbolAddress((void**)&l0bp, g_l0bp);
    cudaGetSymbolAddress((void**)&l1bp, g_l1bp);
    cudaGetSymbolAddress((void**)&WTh,  g_WThi);
    cudaGetSymbolAddress((void**)&WTl,  g_WTlo);
    int *cntp;
    cudaGetSymbolAddress((void**)&cntp, g_cnt);

    static int attr_set = 0;
    if (!attr_set) {
        cudaFuncSetAttribute(gru_step, cudaFuncAttributeMaxDynamicSharedMemorySize, GRU_SMEM);
        attr_set = 1;
    }

    // weight offsets (elements)
    const int o_gWx  = 0;                      // [384'][32]  P=3
    const int o_gWh  = 12288;                  // [384'][128] P=3
    const int o_g1W  = 61440;                  // [384][128]
    const int o_g2W  = 110592;                 // [384][384]
    const int o_l0Wx = 258048;                 // [1024'][128] P=4
    const int o_l0Wh = 389120;                 // [1024'][256] P=4
    const int o_l1   = 651264;                 // [1024'][512] packed P=4
    const int o_dyn  = 1175552;                // [128][128]
    const int o_fc   = 1191936;                // [128][384]

    // ---- prologue ordered so ncu (-s 5) captures the GX mma_gemm ----
    stamp<<<1,32>>>(0);                                                  // L0
    wsplitp<<<(32*384+255)/256,256>>>(gWx, WTh+o_gWx, WTl+o_gWx, 32, 384, 3, 32, 0);  // L1
    bperm<<<2,256>>>(gbx, gbxp, 384, 3);                                 // L2
    emb_kernel<<<(int)(((long)NN*TT*DE + 255)/256),256>>>(x, ipW, ipb);  // L3
    stamp<<<1,32>>>(1);                                                  // L4
    mmagemm<0,0>(EMB, WTh+o_gWx, WTl+o_gWx, 32, gbxp, nullptr, GX, (long)NN*TT, F3); // L5: ncu
    stamp<<<1,32>>>(2);

    // ---- remaining weight prep ----
    wsplitp<<<(128*384+255)/256,256>>>(gWh,  WTh+o_gWh,  WTl+o_gWh,  128, 384, 3, 128, 0);
    wsplitp<<<(128*384+255)/256,256>>>(g1W,  WTh+o_g1W,  WTl+o_g1W,  128, 384, 1, 128, 0);
    wsplitp<<<(384*384+255)/256,256>>>(g2W,  WTh+o_g2W,  WTl+o_g2W,  384, 384, 1, 384, 0);
    wsplitp<<<(128*1024+255)/256,256>>>(l0Wx, WTh+o_l0Wx, WTl+o_l0Wx, 128, 1024, 4, 128, 0);
    wsplitp<<<(256*1024+255)/256,256>>>(l0Wh, WTh+o_l0Wh, WTl+o_l0Wh, 256, 1024, 4, 256, 0);
    wsplitp<<<(256*1024+255)/256,256>>>(l1Wx, WTh+o_l1,   WTl+o_l1,   256, 1024, 4, 512, 0);
    wsplitp<<<(256*1024+255)/256,256>>>(l1Wh, WTh+o_l1,   WTl+o_l1,   256, 1024, 4, 512, 256);
    wsplitp<<<(128*128+255)/256,256>>>(dynW, WTh+o_dyn,  WTl+o_dyn,  128, 128, 1, 128, 0);
    wsplitp<<<(384*128+255)/256,256>>>(fcW,  WTh+o_fc,   WTl+o_fc,   384, 128, 1, 384, 0);
    bperm<<<2,256>>>(gbh, gbhp, 384, 3);
    bperm<<<4,256>>>(l0b, l0bp, 1024, 4);
    bperm<<<4,256>>>(l1b, l1bp, 1024, 4);
    stamp<<<1,32>>>(3);

    // ---- CSR build ----
    zero_i<<<(NN+255)/256,256>>>(cntp, NN);
    edge_count<<<(NE+255)/256,256>>>(ei);
    scan_kernel<<<1,1024>>>();
    copy_cur<<<(NN+255)/256,256>>>();
    edge_scatter<<<(NE+255)/256,256>>>(ei);
    stamp<<<1,32>>>(4);

    // ---- GRU ----
    zero_f<<<(int)(((long)NN*HE + 255)/256),256>>>(H, (long)NN*HE);
    {
        dim3 gg(F3/96, (NN+127)/128);
        for (int t = 0; t < TT; ++t) {
            const float* hin  = (t & 1) ? H2 : H;
            float*       hout = (t & 1) ? H  : H2;
            gru_step<<<gg, 256, GRU_SMEM>>>(hin, WTh+o_gWh, WTl+o_gWh, hout, t);
        }
    }
    stamp<<<1,32>>>(5);

    // hist_enc = leaky( leaky(H) @ dynW + dynb )  (mma, PRE+ACT)
    mmagemm<1,1>(H, WTh+o_dyn, WTl+o_dyn, HE, dynb, nullptr, HENC, NN, HE);
    stamp<<<1,32>>>(6);

    // ---- GAT layer 1 ----
    mmagemm<0,0>(HENC, WTh+o_g1W, WTl+o_g1W, HE, nullptr, nullptr, F1, NN, F3);
    attn_coef<<<(NN*3*32+255)/256,256>>>(F1, g1as, g1ad);
    gat_agg<<<(NN*32+255)/256,256>>>(F1, g1b, O1);
    stamp<<<1,32>>>(7);

    // ---- GAT layer 2 ----
    mmagemm<0,0>(O1, WTh+o_g2W, WTl+o_g2W, F3, nullptr, nullptr, F2, NN, F3);
    attn_coef<<<(NN*3*32+255)/256,256>>>(F2, g2as, g2ad);
    gat_agg<<<(NN*32+255)/256,256>>>(F2, g2b, O2);
    stamp<<<1,32>>>(8);

    // ---- fc (gather+ACT) + X0 ----
    mmagemm<0,1>(O2, WTh+o_fc, WTl+o_fc, F3, fcb, tgt, ENC, NT, HE);
    mmagemm<0,0>(ENC, WTh+o_l0Wx, WTl+o_l0Wx, HE, l0bp, nullptr, X0, NT, 4*HD);
    zero_f<<<((NT*HD)+255)/256,256>>>(h0a, (long)NT*HD);
    zero_f<<<((NT*HD)+255)/256,256>>>(h1a, (long)NT*HD);
    stamp<<<1,32>>>(9);

    // ---- decoder ----
    {
        dim3 gd(16, (NT+127)/128);
        for (int t = 0; t < OUTL; ++t) {
            float* h0in  = (t & 1) ? h0b : h0a;
            float* h0out = (t & 1) ? h0a : h0b;
            float* h1in  = (t & 1) ? h1b : h1a;
            float* h1out = (t & 1) ? h1a : h1b;
            dec_gemm<0><<<gd, 256, MMA_SMEM>>>(h0in, nullptr, WTh+o_l0Wh, WTl+o_l0Wh,
                                               X0, c0, h0out, t == 0);
            dec_gemm<1><<<gd, 256, MMA_SMEM>>>(h0out, h1in, WTh+o_l1, WTl+o_l1,
                                               l1bp, c1, h1out, t == 0);
            out_head<<<(NT*32+255)/256,256>>>(h1out, opW, opb, out, t);
        }
    }
    stamp<<<1,32>>>(10);
    stamp_print<<<1,32>>>();
}

// round 11
// speedup vs baseline: 1.1051x; 1.1051x over previous
#include <cuda_runtime.h>
#include <cuda_bf16.h>
#include <mma.h>
#include <math.h>
#include <stdint.h>

using namespace nvcuda;

#define NN   30000
#define TT   16
#define DE   32
#define HE   128
#define F3   384
#define NE0  300000
#define NE   330000
#define NT   3000
#define HD   256
#define OUTL 25

// ---------------- scratch ----------------
__device__ __align__(256) float g_EMB[NN*TT*DE];
__device__ __align__(256) float g_H[NN*HE];
__device__ __align__(256) float g_H2[NN*HE];
__device__ __align__(256) float g_HENC[NN*HE];
__device__ __align__(256) float g_F1[NN*F3];
__device__ __align__(256) float g_O1[NN*F3];
__device__ __align__(256) float g_F2[NN*F3];
__device__ __align__(256) float g_O2[NN*F3];
__device__ __align__(256) float g_asv[NN*3];
__device__ __align__(256) float g_adv[NN*3];
__device__ __align__(256) float g_ENC[NT*HE];
__device__ __align__(256) float g_X0[NT*4*HD];
__device__ __align__(256) float g_c0[NT*HD];
__device__ __align__(256) float g_c1[NT*HD];
__device__ __align__(256) float g_h0a[NT*HD];
__device__ __align__(256) float g_h0b[NT*HD];
__device__ __align__(256) float g_h1a[NT*HD];
__device__ __align__(256) float g_h1b[NT*HD];
__device__ int g_cnt[NN];
__device__ int g_offs[NN+1];
__device__ int g_cur[NN];
__device__ int g_ssrc[NE];
__device__ float g_grub[512];      // packed GRU gate biases
__device__ float g_l0bp[4*HD];
__device__ float g_l1bp[4*HD];
#define WT_TOTAL 1330000
__device__ __align__(256) __nv_bfloat16 g_WThi[WT_TOTAL];
__device__ __align__(256) __nv_bfloat16 g_WTlo[WT_TOTAL];

__device__ __forceinline__ float sigf(float x){ return 1.f/(1.f+__expf(-x)); }
__device__ __forceinline__ float lk01(float x){ return x>=0.f? x : 0.1f*x; }

// ---------------- utility ----------------
__global__ void zero_f(float* __restrict__ p, long n){
    long i = (long)blockIdx.x*blockDim.x + threadIdx.x;
    if (i < n) p[i] = 0.f;
}
__global__ void zero_i(int* __restrict__ p, int n){
    int i = blockIdx.x*blockDim.x + threadIdx.x;
    if (i < n) p[i] = 0;
}

// W[K,N] fp32 -> bf16 hi/lo at [np*ldk + kofs + k], np = (n % (N/P))*P + n/(N/P)
__global__ void wsplitp(const float* __restrict__ W, __nv_bfloat16* __restrict__ hi,
                        __nv_bfloat16* __restrict__ lo, int K, int N, int P,
                        int ldk, int kofs)
{
    int idx = blockIdx.x*blockDim.x + threadIdx.x;
    if (idx >= K*N) return;
    int k = idx / N, n = idx - k*N;
    int Gp = N / P;
    int np = (n % Gp)*P + n/Gp;
    float v = W[idx];
    __nv_bfloat16 h = __float2bfloat16(v);
    hi[(long)np*ldk + kofs + k] = h;
    lo[(long)np*ldk + kofs + k] = __float2bfloat16(v - __bfloat162float(h));
}

// GRU packed-weight scatter into [512][160]:
// per unit j: col 4j+0 = r (Wx rows 128..159 | Wh rows 0..127)
//             col 4j+1 = z (same)
//             col 4j+2 = gh_n (Wh only), col 4j+3 = gx_n (Wx only)
// mode 0: W = gWh [128][384], kbase=0;  mode 1: W = gWx [32][384], kbase=128.
__global__ void wscat_gru(const float* __restrict__ W, __nv_bfloat16* __restrict__ hi,
                          __nv_bfloat16* __restrict__ lo, int K, int kbase, int mode)
{
    int idx = blockIdx.x*blockDim.x + threadIdx.x;
    if (idx >= K*F3) return;
    int k = idx / F3, n = idx - k*F3;
    int g = n / HE, j = n - g*HE;
    int cp = 4*j + ((g < 2) ? g : (mode ? 3 : 2));
    float v = W[idx];
    __nv_bfloat16 h = __float2bfloat16(v);
    long o = (long)cp*160 + kbase + k;
    hi[o] = h;
    lo[o] = __float2bfloat16(v - __bfloat162float(h));
}

__global__ void grub_kernel(const float* __restrict__ gbx, const float* __restrict__ gbh)
{
    int j = threadIdx.x;
    if (j < HE) {
        g_grub[4*j+0] = gbx[j]       + gbh[j];
        g_grub[4*j+1] = gbx[HE+j]    + gbh[HE+j];
        g_grub[4*j+2] = gbh[2*HE+j];
        g_grub[4*j+3] = gbx[2*HE+j];
    }
}

__global__ void bperm(const float* __restrict__ b, float* __restrict__ bp, int N, int P)
{
    int n = blockIdx.x*blockDim.x + threadIdx.x;
    if (n >= N) return;
    int Gp = N / P;
    bp[(n % Gp)*P + n/Gp] = b[n];
}

typedef wmma::fragment<wmma::matrix_a, 16,16,16, __nv_bfloat16, wmma::row_major> FragA;
typedef wmma::fragment<wmma::matrix_b, 16,16,16, __nv_bfloat16, wmma::col_major> FragB;
typedef wmma::fragment<wmma::accumulator, 16,16,16, float> FragC;

// ---------------- generic WMMA bf16x3 GEMM ----------------
#define WBM 128
#define WBN 64
#define WBK 32
#define SKA 40
#define SKB 40
#define SCC 72
#define MMA_SMEM 36864

template<int PRE, int ACT>
__global__ void __launch_bounds__(256,2)
mma_gemm(const float* __restrict__ A1, const __nv_bfloat16* __restrict__ W1h,
         const __nv_bfloat16* __restrict__ W1l, int K1,
         const float* __restrict__ bias, const int* __restrict__ rowidx,
         float* __restrict__ C, int M, int N)
{
    extern __shared__ char smc[];
    __nv_bfloat16* Ah = (__nv_bfloat16*)smc;
    __nv_bfloat16* Al = Ah + WBM*SKA;
    __nv_bfloat16* Bh = Al + WBM*SKA;
    __nv_bfloat16* Bl = Bh + WBN*SKB;
    float* Cs = (float*)smc;

    const int tid = threadIdx.x, wid = tid >> 5;
    const int warp_m = wid >> 1, warp_n = wid & 1;
    const long bm = (long)blockIdx.y * WBM;
    const int bn = blockIdx.x * WBN;

    FragC acc[2][2];
    #pragma unroll
    for (int mm = 0; mm < 2; ++mm)
        #pragma unroll
        for (int nn = 0; nn < 2; ++nn)
            wmma::fill_fragment(acc[mm][nn], 0.f);

    for (int k0 = 0; k0 < K1; k0 += WBK) {
        #pragma unroll
        for (int i = 0; i < 4; ++i) {
            int li = tid + (i << 8);
            int r = li >> 3, c = (li & 7) << 2;
            float4 v = make_float4(0.f,0.f,0.f,0.f);
            if (bm + r < M) {
                long ar = rowidx ? (long)rowidx[bm + r] : (bm + r);
                v = *(const float4*)(A1 + ar*K1 + k0 + c);
            }
            if (PRE) { v.x=lk01(v.x); v.y=lk01(v.y); v.z=lk01(v.z); v.w=lk01(v.w); }
            __nv_bfloat16 hx = __float2bfloat16(v.x);
            __nv_bfloat16 hy = __float2bfloat16(v.y);
            __nv_bfloat16 hz = __float2bfloat16(v.z);
            __nv_bfloat16 hw = __float2bfloat16(v.w);
            int o = r*SKA + c;
            Ah[o]   = hx; Ah[o+1] = hy; Ah[o+2] = hz; Ah[o+3] = hw;
            Al[o]   = __float2bfloat16(v.x - __bfloat162float(hx));
            Al[o+1] = __float2bfloat16(v.y - __bfloat162float(hy));
            Al[o+2] = __float2bfloat16(v.z - __bfloat162float(hz));
            Al[o+3] = __float2bfloat16(v.w - __bfloat162float(hw));
        }
        {
            int r = tid >> 2, c = (tid & 3) << 3;
            long go = (long)(bn + r)*K1 + k0 + c;
            *(uint4*)&Bh[r*SKB + c] = *(const uint4*)(W1h + go);
            *(uint4*)&Bl[r*SKB + c] = *(const uint4*)(W1l + go);
        }
        __syncthreads();

        #pragma unroll
        for (int kk = 0; kk < WBK; kk += 16) {
            FragA ah[2], al[2];
            FragB bh[2], bl[2];
            #pragma unroll
            for (int mm = 0; mm < 2; ++mm) {
                int ro = (warp_m*32 + mm*16)*SKA + kk;
                wmma::load_matrix_sync(ah[mm], Ah + ro, SKA);
                wmma::load_matrix_sync(al[mm], Al + ro, SKA);
            }
            #pragma unroll
            for (int nn = 0; nn < 2; ++nn) {
                int no = (warp_n*32 + nn*16)*SKB + kk;
                wmma::load_matrix_sync(bh[nn], Bh + no, SKB);
                wmma::load_matrix_sync(bl[nn], Bl + no, SKB);
            }
            #pragma unroll
            for (int mm = 0; mm < 2; ++mm)
                #pragma unroll
                for (int nn = 0; nn < 2; ++nn) {
                    wmma::mma_sync(acc[mm][nn], ah[mm], bh[nn], acc[mm][nn]);
                    wmma::mma_sync(acc[mm][nn], ah[mm], bl[nn], acc[mm][nn]);
                    wmma::mma_sync(acc[mm][nn], al[mm], bh[nn], acc[mm][nn]);
                }
        }
        __syncthreads();
    }

    #pragma unroll
    for (int mm = 0; mm < 2; ++mm)
        #pragma unroll
        for (int nn = 0; nn < 2; ++nn)
            wmma::store_matrix_sync(Cs + (warp_m*32 + mm*16)*SCC + warp_n*32 + nn*16,
                                    acc[mm][nn], SCC, wmma::mem_row_major);
    __syncthreads();

    #pragma unroll
    for (int i = 0; i < 8; ++i) {
        int li = tid + (i << 8);
        int r = li >> 4, c = (li & 15) << 2;
        long row = bm + r;
        if (row >= M) continue;
        float4 v = *(float4*)&Cs[r*SCC + c];
        int col = bn + c;
        if (bias) {
            float4 bb = *(const float4*)(bias + col);
            v.x += bb.x; v.y += bb.y; v.z += bb.z; v.w += bb.w;
        }
        if (ACT) { v.x=lk01(v.x); v.y=lk01(v.y); v.z=lk01(v.z); v.w=lk01(v.w); }
        *(float4*)(C + row*(long)N + col) = v;
    }
}

// ---------------- GRU step: one GEMM (K=160 = Hin 128 | EMB_t 32), fused gates ----------------
// Packed weights [512][160]; per unit j cols 4j+{0,1,2,3} = r, z, gh_n, gx_n.
__global__ void __launch_bounds__(256,2)
gru_step2(const float* __restrict__ Hin, const __nv_bfloat16* __restrict__ Wh,
          const __nv_bfloat16* __restrict__ Wl, float* __restrict__ Hout, int t)
{
    extern __shared__ char sm[];
    __nv_bfloat16* Ah = (__nv_bfloat16*)sm;
    __nv_bfloat16* Al = Ah + 128*SKA;
    __nv_bfloat16* Bh = Al + 128*SKA;
    __nv_bfloat16* Bl = Bh + 64*SKB;
    float* Cs = (float*)sm;

    const int tid = threadIdx.x, wid = tid >> 5;
    const int warp_m = wid >> 1, warp_n = wid & 1;
    const long bm = (long)blockIdx.y * 128;
    const int bn = blockIdx.x * 64;

    FragC acc[2][2];
    #pragma unroll
    for (int mm = 0; mm < 2; ++mm)
        #pragma unroll
        for (int nn = 0; nn < 2; ++nn)
            wmma::fill_fragment(acc[mm][nn], 0.f);

    #pragma unroll
    for (int ch = 0; ch < 5; ++ch) {
        const int k0 = ch << 5;
        #pragma unroll
        for (int i = 0; i < 4; ++i) {
            int li = tid + (i << 8);
            int r = li >> 3, c = (li & 7) << 2;
            float4 v = make_float4(0.f,0.f,0.f,0.f);
            long node = bm + r;
            if (node < NN) {
                if (ch < 4) v = *(const float4*)(Hin + node*HE + k0 + c);
                else        v = *(const float4*)(g_EMB + (node*TT + t)*DE + c);
            }
            __nv_bfloat16 hx = __float2bfloat16(v.x);
            __nv_bfloat16 hy = __float2bfloat16(v.y);
            __nv_bfloat16 hz = __float2bfloat16(v.z);
            __nv_bfloat16 hw = __float2bfloat16(v.w);
            int o = r*SKA + c;
            Ah[o]   = hx; Ah[o+1] = hy; Ah[o+2] = hz; Ah[o+3] = hw;
            Al[o]   = __float2bfloat16(v.x - __bfloat162float(hx));
            Al[o+1] = __float2bfloat16(v.y - __bfloat162float(hy));
            Al[o+2] = __float2bfloat16(v.z - __bfloat162float(hz));
            Al[o+3] = __float2bfloat16(v.w - __bfloat162float(hw));
        }
        {
            int r = tid >> 2, c = (tid & 3) << 3;
            long go = (long)(bn + r)*160 + k0 + c;
            *(uint4*)&Bh[r*SKB + c] = *(const uint4*)(Wh + go);
            *(uint4*)&Bl[r*SKB + c] = *(const uint4*)(Wl + go);
        }
        __syncthreads();

        #pragma unroll
        for (int kk = 0; kk < WBK; kk += 16) {
            FragA ah[2], al[2];
            FragB bh[2], bl[2];
            #pragma unroll
            for (int mm = 0; mm < 2; ++mm) {
                int ro = (warp_m*32 + mm*16)*SKA + kk;
                wmma::load_matrix_sync(ah[mm], Ah + ro, SKA);
                wmma::load_matrix_sync(al[mm], Al + ro, SKA);
            }
            #pragma unroll
            for (int nn = 0; nn < 2; ++nn) {
                int no = (warp_n*32 + nn*16)*SKB + kk;
                wmma::load_matrix_sync(bh[nn], Bh + no, SKB);
                wmma::load_matrix_sync(bl[nn], Bl + no, SKB);
            }
            #pragma unroll
            for (int mm = 0; mm < 2; ++mm)
                #pragma unroll
                for (int nn = 0; nn < 2; ++nn) {
                    wmma::mma_sync(acc[mm][nn], ah[mm], bh[nn], acc[mm][nn]);
                    wmma::mma_sync(acc[mm][nn], ah[mm], bl[nn], acc[mm][nn]);
                    wmma::mma_sync(acc[mm][nn], al[mm], bh[nn], acc[mm][nn]);
                }
        }
        __syncthreads();
    }

    #pragma unroll
    for (int mm = 0; mm < 2; ++mm)
        #pragma unroll
        for (int nn = 0; nn < 2; ++nn)
            wmma::store_matrix_sync(Cs + (warp_m*32 + mm*16)*68 + warp_n*32 + nn*16,
                                    acc[mm][nn], 68, wmma::mem_row_major);
    __syncthreads();

    // gate epilogue: 128 rows x 16 units
    #pragma unroll
    for (int i = 0; i < 8; ++i) {
        int li = tid + (i << 8);
        int r = li >> 4, q = li & 15;
        long node = bm + r;
        if (node < NN) {
            int j = blockIdx.x*16 + q;
            const float* gs = Cs + r*68 + 4*q;
            float rr  = sigf(gs[0] + g_grub[4*j+0]);
            float zz  = sigf(gs[1] + g_grub[4*j+1]);
            float ghn = gs[2] + g_grub[4*j+2];
            float gxn = gs[3] + g_grub[4*j+3];
            float nn2 = tanhf(gxn + rr*ghn);
            float hold = Hin[node*HE + j];
            Hout[node*HE + j] = (1.f - zz)*nn2 + zz*hold;
        }
    }
}

// ---------------- decoder step GEMM with fused LSTM gates ----------------
template<int L1>
__global__ void __launch_bounds__(256,2)
dec_gemm(const float* __restrict__ A1, const float* __restrict__ A2,
         const __nv_bfloat16* __restrict__ Wh, const __nv_bfloat16* __restrict__ Wl,
         const float* __restrict__ pre, float* __restrict__ cbuf,
         float* __restrict__ hout, int first)
{
    extern __shared__ char sm[];
    __nv_bfloat16* Ah = (__nv_bfloat16*)sm;
    __nv_bfloat16* Al = Ah + 128*SKA;
    __nv_bfloat16* Bh = Al + 128*SKA;
    __nv_bfloat16* Bl = Bh + 64*SKB;
    float* Cs = (float*)sm;

    const int tid = threadIdx.x, wid = tid >> 5;
    const int warp_m = wid >> 1, warp_n = wid & 1;
    const long bm = (long)blockIdx.y * 128;
    const int bn = blockIdx.x * 64;
    const int KTOT = L1 ? 2*HD : HD;

    FragC acc[2][2];
    #pragma unroll
    for (int mm = 0; mm < 2; ++mm)
        #pragma unroll
        for (int nn = 0; nn < 2; ++nn)
            wmma::fill_fragment(acc[mm][nn], 0.f);

    for (int k0 = 0; k0 < KTOT; k0 += WBK) {
        const float* A = (L1 && k0 >= HD) ? A2 : A1;
        const int ka = k0 & (HD-1);
        #pragma unroll
        for (int i = 0; i < 4; ++i) {
            int li = tid + (i << 8);
            int r = li >> 3, c = (li & 7) << 2;
            float4 v = make_float4(0.f,0.f,0.f,0.f);
            if (bm + r < NT) v = *(const float4*)(A + (bm+r)*HD + ka + c);
            __nv_bfloat16 hx = __float2bfloat16(v.x);
            __nv_bfloat16 hy = __float2bfloat16(v.y);
            __nv_bfloat16 hz = __float2bfloat16(v.z);
            __nv_bfloat16 hw = __float2bfloat16(v.w);
            int o = r*SKA + c;
            Ah[o]   = hx; Ah[o+1] = hy; Ah[o+2] = hz; Ah[o+3] = hw;
            Al[o]   = __float2bfloat16(v.x - __bfloat162float(hx));
            Al[o+1] = __float2bfloat16(v.y - __bfloat162float(hy));
            Al[o+2] = __float2bfloat16(v.z - __bfloat162float(hz));
            Al[o+3] = __float2bfloat16(v.w - __bfloat162float(hw));
        }
        {
            int r = tid >> 2, c = (tid & 3) << 3;
            long go = (long)(bn + r)*KTOT + k0 + c;
            *(uint4*)&Bh[r*SKB + c] = *(const uint4*)(Wh + go);
            *(uint4*)&Bl[r*SKB + c] = *(const uint4*)(Wl + go);
        }
        __syncthreads();

        #pragma unroll
        for (int kk = 0; kk < WBK; kk += 16) {
            FragA ah[2], al[2];
            FragB bh[2], bl[2];
            #pragma unroll
            for (int mm = 0; mm < 2; ++mm) {
                int ro = (warp_m*32 + mm*16)*SKA + kk;
                wmma::load_matrix_sync(ah[mm], Ah + ro, SKA);
                wmma::load_matrix_sync(al[mm], Al + ro, SKA);
            }
            #pragma unroll
            for (int nn = 0; nn < 2; ++nn) {
                int no = (warp_n*32 + nn*16)*SKB + kk;
                wmma::load_matrix_sync(bh[nn], Bh + no, SKB);
                wmma::load_matrix_sync(bl[nn], Bl + no, SKB);
            }
            #pragma unroll
            for (int mm = 0; mm < 2; ++mm)
                #pragma unroll
                for (int nn = 0; nn < 2; ++nn) {
                    wmma::mma_sync(acc[mm][nn], ah[mm], bh[nn], acc[mm][nn]);
                    wmma::mma_sync(acc[mm][nn], ah[mm], bl[nn], acc[mm][nn]);
                    wmma::mma_sync(acc[mm][nn], al[mm], bh[nn], acc[mm][nn]);
                }
        }
        __syncthreads();
    }

    #pragma unroll
    for (int mm = 0; mm < 2; ++mm)
        #pragma unroll
        for (int nn = 0; nn < 2; ++nn)
            wmma::store_matrix_sync(Cs + (warp_m*32 + mm*16)*68 + warp_n*32 + nn*16,
                                    acc[mm][nn], 68, wmma::mem_row_major);
    __syncthreads();

    #pragma unroll
    for (int i = 0; i < 8; ++i) {
        int li = tid + (i << 8);
        int r = li >> 4, q = li & 15;
        long row = bm + r;
        if (row < NT) {
            int j = blockIdx.x*16 + q;
            const float* gs = Cs + r*68 + 4*q;
            const float* pp = L1 ? (pre + bn + 4*q) : (pre + row*(4*HD) + bn + 4*q);
            float ig = sigf(gs[0] + pp[0]);
            float fg = sigf(gs[1] + pp[1]);
            float gg = tanhf(gs[2] + pp[2]);
            float og = sigf(gs[3] + pp[3]);
            float c = first ? 0.f : cbuf[row*HD + j];
            c = fg*c + ig*gg;
            cbuf[row*HD + j] = c;
            hout[row*HD + j] = og*tanhf(c);
        }
    }
}

// ---------------- encoder embedding ----------------
__global__ void emb_kernel(const float* __restrict__ x, const float* __restrict__ ipW,
                           const float* __restrict__ ipb)
{
    long i = (long)blockIdx.x*blockDim.x + threadIdx.x;
    if (i >= (long)NN*TT*DE) return;
    long row = i >> 5; int j = (int)(i & 31);
    float v = x[row*2]*ipW[j] + x[row*2+1]*ipW[DE+j] + ipb[j];
    g_EMB[i] = lk01(v);
}

// ---------------- CSR build ----------------
__global__ void edge_count(const int* __restrict__ ei){
    int e = blockIdx.x*blockDim.x + threadIdx.x;
    if (e >= NE) return;
    int d = (e < NE0) ? ei[NE0+e] : (e - NE0);
    atomicAdd(&g_cnt[d], 1);
}
__global__ void scan_kernel(){
    __shared__ int sh[1024];
    __shared__ int run;
    int tid = threadIdx.x;
    if (tid == 0) run = 0;
    __syncthreads();
    for (int base = 0; base < NN; base += 1024) {
        int v = (base + tid < NN) ? g_cnt[base + tid] : 0;
        sh[tid] = v; __syncthreads();
        for (int off = 1; off < 1024; off <<= 1) {
            int tv = (tid >= off) ? sh[tid-off] : 0;
            __syncthreads();
            sh[tid] += tv;
            __syncthreads();
        }
        if (base + tid < NN) g_offs[base + tid + 1] = run + sh[tid];
        __syncthreads();
        if (tid == 0) run += sh[1023];
        __syncthreads();
    }
    if (tid == 0) g_offs[0] = 0;
}
__global__ void copy_cur(){
    int i = blockIdx.x*blockDim.x + threadIdx.x;
    if (i < NN) g_cur[i] = g_offs[i];
}
__global__ void edge_scatter(const int* __restrict__ ei){
    int e = blockIdx.x*blockDim.x + threadIdx.x;
    if (e >= NE) return;
    int s, d;
    if (e < NE0) { s = ei[e]; d = ei[NE0+e]; } else { s = e - NE0; d = s; }
    int pos = atomicAdd(&g_cur[d], 1);
    g_ssrc[pos] = s;
}

// ---------------- GAT ----------------
__global__ void attn_coef(const float* __restrict__ F, const float* __restrict__ a_s,
                          const float* __restrict__ a_d)
{
    int w = (blockIdx.x*blockDim.x + threadIdx.x) >> 5;
    if (w >= NN*3) return;
    int lane = threadIdx.x & 31;
    int node = w / 3, h = w - node*3;
    const float* f = F + (long)node*F3 + h*HE;
    const float* As_ = a_s + h*HE;
    const float* Ad_ = a_d + h*HE;
    float s1 = 0.f, s2 = 0.f;
    #pragma unroll
    for (int c = lane; c < HE; c += 32) { float fv = f[c]; s1 += fv*As_[c]; s2 += fv*Ad_[c]; }
    #pragma unroll
    for (int o = 16; o; o >>= 1) {
        s1 += __shfl_down_sync(0xffffffffu, s1, o);
        s2 += __shfl_down_sync(0xffffffffu, s2, o);
    }
    if (lane == 0) { g_asv[w] = s1; g_adv[w] = s2; }
}

__global__ void gat_agg(const float* __restrict__ F, const float* __restrict__ bias,
                        float* __restrict__ O)
{
    int w = (blockIdx.x*blockDim.x + threadIdx.x) >> 5;
    if (w >= NN) return;
    int lane = threadIdx.x & 31;
    int beg = g_offs[w], end = g_offs[w+1];
    float ad0 = g_adv[w*3], ad1 = g_adv[w*3+1], ad2 = g_adv[w*3+2];
    float m0 = -1e30f, m1 = -1e30f, m2 = -1e30f;
    float d0 = 0.f, d1 = 0.f, d2 = 0.f;
    float acc[12];
    #pragma unroll
    for (int q = 0; q < 12; ++q) acc[q] = 0.f;

    for (int p = beg; p < end; ++p) {
        int s = g_ssrc[p];
        float e0 = g_asv[s*3]   + ad0; e0 = (e0 >= 0.f) ? e0 : 0.2f*e0;
        float e1 = g_asv[s*3+1] + ad1; e1 = (e1 >= 0.f) ? e1 : 0.2f*e1;
        float e2 = g_asv[s*3+2] + ad2; e2 = (e2 >= 0.f) ? e2 : 0.2f*e2;
        const float* f = F + (long)s*F3;
        {
            float nm = fmaxf(m0, e0); float sc = __expf(m0-nm); float wv = __expf(e0-nm);
            d0 = d0*sc + wv;
            #pragma unroll
            for (int q = 0; q < 4; ++q) acc[q] = acc[q]*sc + wv*f[q*32 + lane];
            m0 = nm;
        }
        {
            float nm = fmaxf(m1, e1); float sc = __expf(m1-nm); float wv = __expf(e1-nm);
            d1 = d1*sc + wv;
            #pragma unroll
            for (int q = 0; q < 4; ++q) acc[4+q] = acc[4+q]*sc + wv*f[HE + q*32 + lane];
            m1 = nm;
        }
        {
            float nm = fmaxf(m2, e2); float sc = __expf(m2-nm); float wv = __expf(e2-nm);
            d2 = d2*sc + wv;
            #pragma unroll
            for (int q = 0; q < 4; ++q) acc[8+q] = acc[8+q]*sc + wv*f[2*HE + q*32 + lane];
            m2 = nm;
        }
    }
    float* o = O + (long)w*F3;
    #pragma unroll
    for (int q = 0; q < 4; ++q) {
        int c0 = q*32 + lane;
        o[c0]        = acc[q]  /d0 + bias[c0];
        o[HE + c0]   = acc[4+q]/d1 + bias[HE + c0];
        o[2*HE + c0] = acc[8+q]/d2 + bias[2*HE + c0];
    }
}

// ---------------- output head ----------------
__global__ void out_head(const float* __restrict__ h1, const float* __restrict__ opW,
                         const float* __restrict__ opb, float* __restrict__ out, int t)
{
    int w = (blockIdx.x*blockDim.x + threadIdx.x) >> 5;
    if (w >= NT) return;
    int lane = threadIdx.x & 31;
    const float* h = h1 + (long)w*HD;
    float s0 = 0.f, s1 = 0.f;
    #pragma unroll
    for (int k = lane; k < HD; k += 32) {
        float hv = h[k];
        s0 += hv*opW[k*2];
        s1 += hv*opW[k*2+1];
    }
    #pragma unroll
    for (int o = 16; o; o >>= 1) {
        s0 += __shfl_down_sync(0xffffffffu, s0, o);
        s1 += __shfl_down_sync(0xffffffffu, s1, o);
    }
    if (lane == 0) {
        long base = ((long)w*OUTL + t)*2;
        out[base]   = s0 + opb[0];
        out[base+1] = s1 + opb[1];
    }
}

// ---------------- host ----------------
template<int PRE, int ACT>
static inline void mmagemm(const float* A, const __nv_bfloat16* Wh, const __nv_bfloat16* Wl, int K,
                           const float* bias, const int* ridx, float* C, long M, int N)
{
    dim3 g(N/WBN, (unsigned)((M + WBM - 1)/WBM));
    mma_gemm<PRE,ACT><<<g, 256, MMA_SMEM>>>(A, Wh, Wl, K, bias, ridx, C, (int)M, N);
}

extern "C" void kernel_launch(void* const* d_in, const int* in_sizes, int n_in,
                              void* d_out, int out_size)
{
    const float* x    = (const float*)d_in[0];
    const int*   ei   = (const int*)  d_in[1];
    const int*   tgt  = (const int*)  d_in[2];
    const float* ipW  = (const float*)d_in[3];
    const float* ipb  = (const float*)d_in[4];
    const float* gWx  = (const float*)d_in[5];
    const float* gWh  = (const float*)d_in[6];
    const float* gbx  = (const float*)d_in[7];
    const float* gbh  = (const float*)d_in[8];
    const float* dynW = (const float*)d_in[9];
    const float* dynb = (const float*)d_in[10];
    const float* g1W  = (const float*)d_in[11];
    const float* g1as = (const float*)d_in[12];
    const float* g1ad = (const float*)d_in[13];
    const float* g1b  = (const float*)d_in[14];
    const float* g2W  = (const float*)d_in[15];
    const float* g2as = (const float*)d_in[16];
    const float* g2ad = (const float*)d_in[17];
    const float* g2b  = (const float*)d_in[18];
    const float* fcW  = (const float*)d_in[19];
    const float* fcb  = (const float*)d_in[20];
    const float* l0Wx = (const float*)d_in[21];
    const float* l0Wh = (const float*)d_in[22];
    const float* l0b  = (const float*)d_in[23];
    const float* l1Wx = (const float*)d_in[24];
    const float* l1Wh = (const float*)d_in[25];
    const float* l1b  = (const float*)d_in[26];
    const float* opW  = (const float*)d_in[27];
    const float* opb  = (const float*)d_in[28];
    float* out = (float*)d_out;
    (void)in_sizes; (void)n_in; (void)out_size;

    float *H,*H2,*HENC,*F1,*O1,*F2,*O2,*ENC,*X0,*c0,*c1,*h0a,*h0b,*h1a,*h1b;
    float *l0bp,*l1bp;
    __nv_bfloat16 *WTh,*WTl;
    cudaGetSymbolAddress((void**)&H,    g_H);
    cudaGetSymbolAddress((void**)&H2,   g_H2);
    cudaGetSymbolAddress((void**)&HENC, g_HENC);
    cudaGetSymbolAddress((void**)&F1,   g_F1);
    cudaGetSymbolAddress((void**)&O1,   g_O1);
    cudaGetSymbolAddress((void**)&F2,   g_F2);
    cudaGetSymbolAddress((void**)&O2,   g_O2);
    cudaGetSymbolAddress((void**)&ENC,  g_ENC);
    cudaGetSymbolAddress((void**)&X0,   g_X0);
    cudaGetSymbolAddress((void**)&c0,   g_c0);
    cudaGetSymbolAddress((void**)&c1,   g_c1);
    cudaGetSymbolAddress((void**)&h0a,  g_h0a);
    cudaGetSymbolAddress((void**)&h0b,  g_h0b);
    cudaGetSymbolAddress((void**)&h1a,  g_h1a);
    cudaGetSymbolAddress((void**)&h1b,  g_h1b);
    cudaGetSymbolAddress((void**)&l0bp, g_l0bp);
    cudaGetSymbolAddress((void**)&l1bp, g_l1bp);
    cudaGetSymbolAddress((void**)&WTh,  g_WThi);
    cudaGetSymbolAddress((void**)&WTl,  g_WTlo);
    int *cntp;
    cudaGetSymbolAddress((void**)&cntp, g_cnt);

    // weight offsets (elements)
    const int o_g1W  = 61440;                  // [384][128]
    const int o_g2W  = 110592;                 // [384][384]
    const int o_l0Wx = 258048;                 // [1024'][128] P=4
    const int o_l0Wh = 389120;                 // [1024'][256] P=4
    const int o_l1   = 651264;                 // [1024'][512] packed P=4
    const int o_dyn  = 1175552;                // [128][128]
    const int o_fc   = 1191936;                // [128][384]
    const int o_gru  = 1241088;                // [512][160] packed GRU

    // ---- weight prep ----
    zero_f<<<(40960+255)/256,256>>>((float*)(WTh+o_gru), 40960);  // 81920 bf16
    zero_f<<<(40960+255)/256,256>>>((float*)(WTl+o_gru), 40960);
    wscat_gru<<<(128*F3+255)/256,256>>>(gWh, WTh+o_gru, WTl+o_gru, 128, 0,   0);
    wscat_gru<<<(32*F3+255)/256,256>>>(gWx,  WTh+o_gru, WTl+o_gru, 32,  128, 1);
    grub_kernel<<<1,128>>>(gbx, gbh);
    wsplitp<<<(128*384+255)/256,256>>>(g1W,  WTh+o_g1W,  WTl+o_g1W,  128, 384, 1, 128, 0);
    wsplitp<<<(384*384+255)/256,256>>>(g2W,  WTh+o_g2W,  WTl+o_g2W,  384, 384, 1, 384, 0);
    wsplitp<<<(128*1024+255)/256,256>>>(l0Wx, WTh+o_l0Wx, WTl+o_l0Wx, 128, 1024, 4, 128, 0);
    wsplitp<<<(256*1024+255)/256,256>>>(l0Wh, WTh+o_l0Wh, WTl+o_l0Wh, 256, 1024, 4, 256, 0);
    wsplitp<<<(256*1024+255)/256,256>>>(l1Wx, WTh+o_l1,   WTl+o_l1,   256, 1024, 4, 512, 0);
    wsplitp<<<(256*1024+255)/256,256>>>(l1Wh, WTh+o_l1,   WTl+o_l1,   256, 1024, 4, 512, 256);
    wsplitp<<<(128*128+255)/256,256>>>(dynW, WTh+o_dyn,  WTl+o_dyn,  128, 128, 1, 128, 0);
    wsplitp<<<(384*128+255)/256,256>>>(fcW,  WTh+o_fc,   WTl+o_fc,   384, 128, 1, 384, 0);
    bperm<<<4,256>>>(l0b, l0bp, 1024, 4);
    bperm<<<4,256>>>(l1b, l1bp, 1024, 4);

    // ---- CSR build ----
    zero_i<<<(NN+255)/256,256>>>(cntp, NN);
    edge_count<<<(NE+255)/256,256>>>(ei);
    scan_kernel<<<1,1024>>>();
    copy_cur<<<(NN+255)/256,256>>>();
    edge_scatter<<<(NE+255)/256,256>>>(ei);

    // ---- encoder: emb + fused GRU (no GX buffer) ----
    emb_kernel<<<(int)(((long)NN*TT*DE + 255)/256),256>>>(x, ipW, ipb);
    zero_f<<<(int)(((long)NN*HE + 255)/256),256>>>(H, (long)NN*HE);
    {
        dim3 gg(8, (NN+127)/128);
        for (int t = 0; t < TT; ++t) {
            const float* hin  = (t & 1) ? H2 : H;
            float*       hout = (t & 1) ? H  : H2;
            gru_step2<<<gg, 256, MMA_SMEM>>>(hin, WTh+o_gru, WTl+o_gru, hout, t);
        }
        // TT=16 even: final state in g_H
    }

    // hist_enc = leaky( leaky(H) @ dynW + dynb )
    mmagemm<1,1>(H, WTh+o_dyn, WTl+o_dyn, HE, dynb, nullptr, HENC, NN, HE);

    // ---- GAT layer 1 ----
    mmagemm<0,0>(HENC, WTh+o_g1W, WTl+o_g1W, HE, nullptr, nullptr, F1, NN, F3);
    attn_coef<<<(NN*3*32+255)/256,256>>>(F1, g1as, g1ad);
    gat_agg<<<(NN*32+255)/256,256>>>(F1, g1b, O1);

    // ---- GAT layer 2 ----
    mmagemm<0,0>(O1, WTh+o_g2W, WTl+o_g2W, F3, nullptr, nullptr, F2, NN, F3);
    attn_coef<<<(NN*3*32+255)/256,256>>>(F2, g2as, g2ad);
    gat_agg<<<(NN*32+255)/256,256>>>(F2, g2b, O2);

    // ---- target gather + fc + X0 ----
    mmagemm<0,1>(O2, WTh+o_fc, WTl+o_fc, F3, fcb, tgt, ENC, NT, HE);
    mmagemm<0,0>(ENC, WTh+o_l0Wx, WTl+o_l0Wx, HE, l0bp, nullptr, X0, NT, 4*HD);
    zero_f<<<((NT*HD)+255)/256,256>>>(h0a, (long)NT*HD);
    zero_f<<<((NT*HD)+255)/256,256>>>(h1a, (long)NT*HD);

    // ---- decoder ----
    {
        dim3 gd(16, (NT+127)/128);
        for (int t = 0; t < OUTL; ++t) {
            float* h0in  = (t & 1) ? h0b : h0a;
            float* h0out = (t & 1) ? h0a : h0b;
            float* h1in  = (t & 1) ? h1b : h1a;
            float* h1out = (t & 1) ? h1a : h1b;
            dec_gemm<0><<<gd, 256, MMA_SMEM>>>(h0in, nullptr, WTh+o_l0Wh, WTl+o_l0Wh,
                                               X0, c0, h0out, t == 0);
            dec_gemm<1><<<gd, 256, MMA_SMEM>>>(h0out, h1in, WTh+o_l1, WTl+o_l1,
                                               l1bp, c1, h1out, t == 0);
            out_head<<<(NT*32+255)/256,256>>>(h1out, opW, opb, out, t);
        }
    }
}

// round 12
// speedup vs baseline: 1.1730x; 1.0615x over previous
#include <cuda_runtime.h>
#include <cuda_bf16.h>
#include <mma.h>
#include <math.h>
#include <stdint.h>

using namespace nvcuda;

#define NN   30000
#define TT   16
#define DE   32
#define HE   128
#define F3   384
#define NE0  300000
#define NE   330000
#define NT   3000
#define HD   256
#define OUTL 25

// ---------------- scratch ----------------
__device__ __align__(256) float g_EMB[NN*TT*DE];
__device__ __align__(256) float g_H[NN*HE];
__device__ __align__(256) float g_H2[NN*HE];
__device__ __align__(256) float g_HENC[NN*HE];
__device__ __align__(256) float g_F1[NN*F3];
__device__ __align__(256) float g_O1[NN*F3];
__device__ __align__(256) float g_F2[NN*F3];
__device__ __align__(256) float g_O2[NN*F3];
__device__ __align__(256) float g_asv[NN*3];
__device__ __align__(256) float g_adv[NN*3];
__device__ __align__(256) float g_ENC[NT*HE];
__device__ __align__(256) float g_X0[NT*4*HD];
__device__ __align__(256) float g_c0[NT*HD];
__device__ __align__(256) float g_c1[NT*HD];
__device__ __align__(256) float g_h0a[NT*HD];
__device__ __align__(256) float g_h0b[NT*HD];
__device__ __align__(256) float g_h1a[NT*HD];
__device__ __align__(256) float g_h1b[NT*HD];
__device__ int g_cnt[NN];
__device__ int g_offs[NN+1];
__device__ int g_cur[NN];
__device__ int g_ssrc[NE];
__device__ float g_grub[512];
__device__ float g_l0bp[4*HD];
__device__ float g_l1bp[4*HD];
#define WT_TOTAL 1330000
__device__ __align__(256) __nv_bfloat16 g_WThi[WT_TOTAL];
__device__ __align__(256) __nv_bfloat16 g_WTlo[WT_TOTAL];

__device__ __forceinline__ float sigf(float x){ return 1.f/(1.f+__expf(-x)); }
__device__ __forceinline__ float lk01(float x){ return x>=0.f? x : 0.1f*x; }

// ---------------- utility ----------------
__global__ void zero_f(float* __restrict__ p, long n){
    long i = (long)blockIdx.x*blockDim.x + threadIdx.x;
    if (i < n) p[i] = 0.f;
}
__global__ void zero_i(int* __restrict__ p, int n){
    int i = blockIdx.x*blockDim.x + threadIdx.x;
    if (i < n) p[i] = 0;
}

__global__ void wsplitp(const float* __restrict__ W, __nv_bfloat16* __restrict__ hi,
                        __nv_bfloat16* __restrict__ lo, int K, int N, int P,
                        int ldk, int kofs)
{
    int idx = blockIdx.x*blockDim.x + threadIdx.x;
    if (idx >= K*N) return;
    int k = idx / N, n = idx - k*N;
    int Gp = N / P;
    int np = (n % Gp)*P + n/Gp;
    float v = W[idx];
    __nv_bfloat16 h = __float2bfloat16(v);
    hi[(long)np*ldk + kofs + k] = h;
    lo[(long)np*ldk + kofs + k] = __float2bfloat16(v - __bfloat162float(h));
}

// GRU packed-weight scatter into [512][160]
__global__ void wscat_gru(const float* __restrict__ W, __nv_bfloat16* __restrict__ hi,
                          __nv_bfloat16* __restrict__ lo, int K, int kbase, int mode)
{
    int idx = blockIdx.x*blockDim.x + threadIdx.x;
    if (idx >= K*F3) return;
    int k = idx / F3, n = idx - k*F3;
    int g = n / HE, j = n - g*HE;
    int cp = 4*j + ((g < 2) ? g : (mode ? 3 : 2));
    float v = W[idx];
    __nv_bfloat16 h = __float2bfloat16(v);
    long o = (long)cp*160 + kbase + k;
    hi[o] = h;
    lo[o] = __float2bfloat16(v - __bfloat162float(h));
}

__global__ void grub_kernel(const float* __restrict__ gbx, const float* __restrict__ gbh)
{
    int j = threadIdx.x;
    if (j < HE) {
        g_grub[4*j+0] = gbx[j]       + gbh[j];
        g_grub[4*j+1] = gbx[HE+j]    + gbh[HE+j];
        g_grub[4*j+2] = gbh[2*HE+j];
        g_grub[4*j+3] = gbx[2*HE+j];
    }
}

__global__ void bperm(const float* __restrict__ b, float* __restrict__ bp, int N, int P)
{
    int n = blockIdx.x*blockDim.x + threadIdx.x;
    if (n >= N) return;
    int Gp = N / P;
    bp[(n % Gp)*P + n/Gp] = b[n];
}

typedef wmma::fragment<wmma::matrix_a, 16,16,16, __nv_bfloat16, wmma::row_major> FragA;
typedef wmma::fragment<wmma::matrix_b, 16,16,16, __nv_bfloat16, wmma::col_major> FragB;
typedef wmma::fragment<wmma::accumulator, 16,16,16, float> FragC;

#define WBM 128
#define WBN 64
#define WBK 32
#define SKA 40
#define SKB 40
#define SCC 72
#define MMA_SMEM 36864

// shared helpers for the pipelined GEMMs
__device__ __forceinline__ void splitstore_a(__nv_bfloat16* Ah, __nv_bfloat16* Al,
                                             int o, float4 v)
{
    __nv_bfloat16 hx = __float2bfloat16(v.x);
    __nv_bfloat16 hy = __float2bfloat16(v.y);
    __nv_bfloat16 hz = __float2bfloat16(v.z);
    __nv_bfloat16 hw = __float2bfloat16(v.w);
    Ah[o]   = hx; Ah[o+1] = hy; Ah[o+2] = hz; Ah[o+3] = hw;
    Al[o]   = __float2bfloat16(v.x - __bfloat162float(hx));
    Al[o+1] = __float2bfloat16(v.y - __bfloat162float(hy));
    Al[o+2] = __float2bfloat16(v.z - __bfloat162float(hz));
    Al[o+3] = __float2bfloat16(v.w - __bfloat162float(hw));
}

// ---------------- generic WMMA bf16x3 GEMM (register-prefetch pipelined) ----------------
template<int PRE, int ACT>
__global__ void __launch_bounds__(256,2)
mma_gemm(const float* __restrict__ A1, const __nv_bfloat16* __restrict__ W1h,
         const __nv_bfloat16* __restrict__ W1l, int K1,
         const float* __restrict__ bias, const int* __restrict__ rowidx,
         float* __restrict__ C, int M, int N)
{
    extern __shared__ char smc[];
    __nv_bfloat16* Ah = (__nv_bfloat16*)smc;
    __nv_bfloat16* Al = Ah + WBM*SKA;
    __nv_bfloat16* Bh = Al + WBM*SKA;
    __nv_bfloat16* Bl = Bh + WBN*SKB;
    float* Cs = (float*)smc;

    const int tid = threadIdx.x, wid = tid >> 5;
    const int warp_m = wid >> 1, warp_n = wid & 1;
    const long bm = (long)blockIdx.y * WBM;
    const int bn = blockIdx.x * WBN;

    const int ra0 = tid >> 3, ca = (tid & 7) << 2;
    const int rb  = tid >> 2, cb = (tid & 3) << 3;
    long arow[4];
    #pragma unroll
    for (int i = 0; i < 4; ++i) {
        long row = bm + ra0 + 32*i;
        arow[i] = (row < M) ? (rowidx ? (long)rowidx[row] : row) : -1;
    }

    FragC acc[2][2];
    #pragma unroll
    for (int mm = 0; mm < 2; ++mm)
        #pragma unroll
        for (int nn = 0; nn < 2; ++nn)
            wmma::fill_fragment(acc[mm][nn], 0.f);

    float4 va[4];
    uint4 vbh, vbl;
    // prefetch chunk 0
    #pragma unroll
    for (int i = 0; i < 4; ++i) {
        va[i] = make_float4(0.f,0.f,0.f,0.f);
        if (arow[i] >= 0) va[i] = *(const float4*)(A1 + arow[i]*K1 + ca);
    }
    {
        long go = (long)(bn + rb)*K1 + cb;
        vbh = *(const uint4*)(W1h + go);
        vbl = *(const uint4*)(W1l + go);
    }

    for (int k0 = 0; k0 < K1; k0 += WBK) {
        #pragma unroll
        for (int i = 0; i < 4; ++i) {
            float4 v = va[i];
            if (PRE) { v.x=lk01(v.x); v.y=lk01(v.y); v.z=lk01(v.z); v.w=lk01(v.w); }
            splitstore_a(Ah, Al, (ra0 + 32*i)*SKA + ca, v);
        }
        *(uint4*)&Bh[rb*SKB + cb] = vbh;
        *(uint4*)&Bl[rb*SKB + cb] = vbl;
        __syncthreads();

        const int kn = k0 + WBK;
        if (kn < K1) {
            #pragma unroll
            for (int i = 0; i < 4; ++i) {
                va[i] = make_float4(0.f,0.f,0.f,0.f);
                if (arow[i] >= 0) va[i] = *(const float4*)(A1 + arow[i]*K1 + kn + ca);
            }
            long go = (long)(bn + rb)*K1 + kn + cb;
            vbh = *(const uint4*)(W1h + go);
            vbl = *(const uint4*)(W1l + go);
        }

        #pragma unroll
        for (int kk = 0; kk < WBK; kk += 16) {
            FragA ah[2], al[2];
            FragB bh[2], bl[2];
            #pragma unroll
            for (int mm = 0; mm < 2; ++mm) {
                int ro = (warp_m*32 + mm*16)*SKA + kk;
                wmma::load_matrix_sync(ah[mm], Ah + ro, SKA);
                wmma::load_matrix_sync(al[mm], Al + ro, SKA);
            }
            #pragma unroll
            for (int nn = 0; nn < 2; ++nn) {
                int no = (warp_n*32 + nn*16)*SKB + kk;
                wmma::load_matrix_sync(bh[nn], Bh + no, SKB);
                wmma::load_matrix_sync(bl[nn], Bl + no, SKB);
            }
            #pragma unroll
            for (int mm = 0; mm < 2; ++mm)
                #pragma unroll
                for (int nn = 0; nn < 2; ++nn) {
                    wmma::mma_sync(acc[mm][nn], ah[mm], bh[nn], acc[mm][nn]);
                    wmma::mma_sync(acc[mm][nn], ah[mm], bl[nn], acc[mm][nn]);
                    wmma::mma_sync(acc[mm][nn], al[mm], bh[nn], acc[mm][nn]);
                }
        }
        __syncthreads();
    }

    #pragma unroll
    for (int mm = 0; mm < 2; ++mm)
        #pragma unroll
        for (int nn = 0; nn < 2; ++nn)
            wmma::store_matrix_sync(Cs + (warp_m*32 + mm*16)*SCC + warp_n*32 + nn*16,
                                    acc[mm][nn], SCC, wmma::mem_row_major);
    __syncthreads();

    #pragma unroll
    for (int i = 0; i < 8; ++i) {
        int li = tid + (i << 8);
        int r = li >> 4, c = (li & 15) << 2;
        long row = bm + r;
        if (row >= M) continue;
        float4 v = *(float4*)&Cs[r*SCC + c];
        int col = bn + c;
        if (bias) {
            float4 bb = *(const float4*)(bias + col);
            v.x += bb.x; v.y += bb.y; v.z += bb.z; v.w += bb.w;
        }
        if (ACT) { v.x=lk01(v.x); v.y=lk01(v.y); v.z=lk01(v.z); v.w=lk01(v.w); }
        *(float4*)(C + row*(long)N + col) = v;
    }
}

// ---------------- GRU step (pipelined, K=160 = Hin|EMB_t), fused gates ----------------
__global__ void __launch_bounds__(256,2)
gru_step2(const float* __restrict__ Hin, const __nv_bfloat16* __restrict__ Wh,
          const __nv_bfloat16* __restrict__ Wl, float* __restrict__ Hout, int t)
{
    extern __shared__ char sm[];
    __nv_bfloat16* Ah = (__nv_bfloat16*)sm;
    __nv_bfloat16* Al = Ah + 128*SKA;
    __nv_bfloat16* Bh = Al + 128*SKA;
    __nv_bfloat16* Bl = Bh + 64*SKB;
    float* Cs = (float*)sm;

    const int tid = threadIdx.x, wid = tid >> 5;
    const int warp_m = wid >> 1, warp_n = wid & 1;
    const long bm = (long)blockIdx.y * 128;
    const int bn = blockIdx.x * 64;

    const int ra0 = tid >> 3, ca = (tid & 7) << 2;
    const int rb  = tid >> 2, cb = (tid & 3) << 3;
    long nodei[4];
    #pragma unroll
    for (int i = 0; i < 4; ++i) {
        long node = bm + ra0 + 32*i;
        nodei[i] = (node < NN) ? node : -1;
    }

    FragC acc[2][2];
    #pragma unroll
    for (int mm = 0; mm < 2; ++mm)
        #pragma unroll
        for (int nn = 0; nn < 2; ++nn)
            wmma::fill_fragment(acc[mm][nn], 0.f);

    float4 va[4];
    uint4 vbh, vbl;
    #pragma unroll
    for (int i = 0; i < 4; ++i) {
        va[i] = make_float4(0.f,0.f,0.f,0.f);
        if (nodei[i] >= 0) va[i] = *(const float4*)(Hin + nodei[i]*HE + ca);
    }
    {
        long go = (long)(bn + rb)*160 + cb;
        vbh = *(const uint4*)(Wh + go);
        vbl = *(const uint4*)(Wl + go);
    }

    #pragma unroll
    for (int ch = 0; ch < 5; ++ch) {
        #pragma unroll
        for (int i = 0; i < 4; ++i)
            splitstore_a(Ah, Al, (ra0 + 32*i)*SKA + ca, va[i]);
        *(uint4*)&Bh[rb*SKB + cb] = vbh;
        *(uint4*)&Bl[rb*SKB + cb] = vbl;
        __syncthreads();

        if (ch + 1 < 5) {
            const int cn = ch + 1;
            #pragma unroll
            for (int i = 0; i < 4; ++i) {
                va[i] = make_float4(0.f,0.f,0.f,0.f);
                if (nodei[i] >= 0) {
                    if (cn < 4) va[i] = *(const float4*)(Hin + nodei[i]*HE + (cn<<5) + ca);
                    else        va[i] = *(const float4*)(g_EMB + (nodei[i]*TT + t)*DE + ca);
                }
            }
            long go = (long)(bn + rb)*160 + (cn<<5) + cb;
            vbh = *(const uint4*)(Wh + go);
            vbl = *(const uint4*)(Wl + go);
        }

        #pragma unroll
        for (int kk = 0; kk < WBK; kk += 16) {
            FragA ah[2], al[2];
            FragB bh[2], bl[2];
            #pragma unroll
            for (int mm = 0; mm < 2; ++mm) {
                int ro = (warp_m*32 + mm*16)*SKA + kk;
                wmma::load_matrix_sync(ah[mm], Ah + ro, SKA);
                wmma::load_matrix_sync(al[mm], Al + ro, SKA);
            }
            #pragma unroll
            for (int nn = 0; nn < 2; ++nn) {
                int no = (warp_n*32 + nn*16)*SKB + kk;
                wmma::load_matrix_sync(bh[nn], Bh + no, SKB);
                wmma::load_matrix_sync(bl[nn], Bl + no, SKB);
            }
            #pragma unroll
            for (int mm = 0; mm < 2; ++mm)
                #pragma unroll
                for (int nn = 0; nn < 2; ++nn) {
                    wmma::mma_sync(acc[mm][nn], ah[mm], bh[nn], acc[mm][nn]);
                    wmma::mma_sync(acc[mm][nn], ah[mm], bl[nn], acc[mm][nn]);
                    wmma::mma_sync(acc[mm][nn], al[mm], bh[nn], acc[mm][nn]);
                }
        }
        __syncthreads();
    }

    #pragma unroll
    for (int mm = 0; mm < 2; ++mm)
        #pragma unroll
        for (int nn = 0; nn < 2; ++nn)
            wmma::store_matrix_sync(Cs + (warp_m*32 + mm*16)*68 + warp_n*32 + nn*16,
                                    acc[mm][nn], 68, wmma::mem_row_major);
    __syncthreads();

    #pragma unroll
    for (int i = 0; i < 8; ++i) {
        int li = tid + (i << 8);
        int r = li >> 4, q = li & 15;
        long node = bm + r;
        if (node < NN) {
            int j = blockIdx.x*16 + q;
            const float* gs = Cs + r*68 + 4*q;
            float rr  = sigf(gs[0] + g_grub[4*j+0]);
            float zz  = sigf(gs[1] + g_grub[4*j+1]);
            float ghn = gs[2] + g_grub[4*j+2];
            float gxn = gs[3] + g_grub[4*j+3];
            float nn2 = tanhf(gxn + rr*ghn);
            float hold = Hin[node*HE + j];
            Hout[node*HE + j] = (1.f - zz)*nn2 + zz*hold;
        }
    }
}

// ---------------- decoder step GEMM (pipelined) with fused LSTM gates ----------------
template<int L1>
__global__ void __launch_bounds__(256,2)
dec_gemm(const float* __restrict__ A1, const float* __restrict__ A2,
         const __nv_bfloat16* __restrict__ Wh, const __nv_bfloat16* __restrict__ Wl,
         const float* __restrict__ pre, float* __restrict__ cbuf,
         float* __restrict__ hout, int first)
{
    extern __shared__ char sm[];
    __nv_bfloat16* Ah = (__nv_bfloat16*)sm;
    __nv_bfloat16* Al = Ah + 128*SKA;
    __nv_bfloat16* Bh = Al + 128*SKA;
    __nv_bfloat16* Bl = Bh + 64*SKB;
    float* Cs = (float*)sm;

    const int tid = threadIdx.x, wid = tid >> 5;
    const int warp_m = wid >> 1, warp_n = wid & 1;
    const long bm = (long)blockIdx.y * 128;
    const int bn = blockIdx.x * 64;
    const int KTOT = L1 ? 2*HD : HD;

    const int ra0 = tid >> 3, ca = (tid & 7) << 2;
    const int rb  = tid >> 2, cb = (tid & 3) << 3;
    long rowi[4];
    #pragma unroll
    for (int i = 0; i < 4; ++i) {
        long row = bm + ra0 + 32*i;
        rowi[i] = (row < NT) ? row : -1;
    }

    FragC acc[2][2];
    #pragma unroll
    for (int mm = 0; mm < 2; ++mm)
        #pragma unroll
        for (int nn = 0; nn < 2; ++nn)
            wmma::fill_fragment(acc[mm][nn], 0.f);

    float4 va[4];
    uint4 vbh, vbl;
    #pragma unroll
    for (int i = 0; i < 4; ++i) {
        va[i] = make_float4(0.f,0.f,0.f,0.f);
        if (rowi[i] >= 0) va[i] = *(const float4*)(A1 + rowi[i]*HD + ca);
    }
    {
        long go = (long)(bn + rb)*KTOT + cb;
        vbh = *(const uint4*)(Wh + go);
        vbl = *(const uint4*)(Wl + go);
    }

    for (int k0 = 0; k0 < KTOT; k0 += WBK) {
        #pragma unroll
        for (int i = 0; i < 4; ++i)
            splitstore_a(Ah, Al, (ra0 + 32*i)*SKA + ca, va[i]);
        *(uint4*)&Bh[rb*SKB + cb] = vbh;
        *(uint4*)&Bl[rb*SKB + cb] = vbl;
        __syncthreads();

        const int kn = k0 + WBK;
        if (kn < KTOT) {
            const float* A = (L1 && kn >= HD) ? A2 : A1;
            const int ka = kn & (HD-1);
            #pragma unroll
            for (int i = 0; i < 4; ++i) {
                va[i] = make_float4(0.f,0.f,0.f,0.f);
                if (rowi[i] >= 0) va[i] = *(const float4*)(A + rowi[i]*HD + ka + ca);
            }
            long go = (long)(bn + rb)*KTOT + kn + cb;
            vbh = *(const uint4*)(Wh + go);
            vbl = *(const uint4*)(Wl + go);
        }

        #pragma unroll
        for (int kk = 0; kk < WBK; kk += 16) {
            FragA ah[2], al[2];
            FragB bh[2], bl[2];
            #pragma unroll
            for (int mm = 0; mm < 2; ++mm) {
                int ro = (warp_m*32 + mm*16)*SKA + kk;
                wmma::load_matrix_sync(ah[mm], Ah + ro, SKA);
                wmma::load_matrix_sync(al[mm], Al + ro, SKA);
            }
            #pragma unroll
            for (int nn = 0; nn < 2; ++nn) {
                int no = (warp_n*32 + nn*16)*SKB + kk;
                wmma::load_matrix_sync(bh[nn], Bh + no, SKB);
                wmma::load_matrix_sync(bl[nn], Bl + no, SKB);
            }
            #pragma unroll
            for (int mm = 0; mm < 2; ++mm)
                #pragma unroll
                for (int nn = 0; nn < 2; ++nn) {
                    wmma::mma_sync(acc[mm][nn], ah[mm], bh[nn], acc[mm][nn]);
                    wmma::mma_sync(acc[mm][nn], ah[mm], bl[nn], acc[mm][nn]);
                    wmma::mma_sync(acc[mm][nn], al[mm], bh[nn], acc[mm][nn]);
                }
        }
        __syncthreads();
    }

    #pragma unroll
    for (int mm = 0; mm < 2; ++mm)
        #pragma unroll
        for (int nn = 0; nn < 2; ++nn)
            wmma::store_matrix_sync(Cs + (warp_m*32 + mm*16)*68 + warp_n*32 + nn*16,
                                    acc[mm][nn], 68, wmma::mem_row_major);
    __syncthreads();

    #pragma unroll
    for (int i = 0; i < 8; ++i) {
        int li = tid + (i << 8);
        int r = li >> 4, q = li & 15;
        long row = bm + r;
        if (row < NT) {
            int j = blockIdx.x*16 + q;
            const float* gs = Cs + r*68 + 4*q;
            const float* pp = L1 ? (pre + bn + 4*q) : (pre + row*(4*HD) + bn + 4*q);
            float ig = sigf(gs[0] + pp[0]);
            float fg = sigf(gs[1] + pp[1]);
            float gg = tanhf(gs[2] + pp[2]);
            float og = sigf(gs[3] + pp[3]);
            float c = first ? 0.f : cbuf[row*HD + j];
            c = fg*c + ig*gg;
            cbuf[row*HD + j] = c;
            hout[row*HD + j] = og*tanhf(c);
        }
    }
}

// ---------------- encoder embedding ----------------
__global__ void emb_kernel(const float* __restrict__ x, const float* __restrict__ ipW,
                           const float* __restrict__ ipb)
{
    long i = (long)blockIdx.x*blockDim.x + threadIdx.x;
    if (i >= (long)NN*TT*DE) return;
    long row = i >> 5; int j = (int)(i & 31);
    float v = x[row*2]*ipW[j] + x[row*2+1]*ipW[DE+j] + ipb[j];
    g_EMB[i] = lk01(v);
}

// ---------------- CSR build ----------------
__global__ void edge_count(const int* __restrict__ ei){
    int e = blockIdx.x*blockDim.x + threadIdx.x;
    if (e >= NE) return;
    int d = (e < NE0) ? ei[NE0+e] : (e - NE0);
    atomicAdd(&g_cnt[d], 1);
}
__global__ void scan_kernel(){
    __shared__ int sh[1024];
    __shared__ int run;
    int tid = threadIdx.x;
    if (tid == 0) run = 0;
    __syncthreads();
    for (int base = 0; base < NN; base += 1024) {
        int v = (base + tid < NN) ? g_cnt[base + tid] : 0;
        sh[tid] = v; __syncthreads();
        for (int off = 1; off < 1024; off <<= 1) {
            int tv = (tid >= off) ? sh[tid-off] : 0;
            __syncthreads();
            sh[tid] += tv;
            __syncthreads();
        }
        if (base + tid < NN) g_offs[base + tid + 1] = run + sh[tid];
        __syncthreads();
        if (tid == 0) run += sh[1023];
        __syncthreads();
    }
    if (tid == 0) g_offs[0] = 0;
}
__global__ void copy_cur(){
    int i = blockIdx.x*blockDim.x + threadIdx.x;
    if (i < NN) g_cur[i] = g_offs[i];
}
__global__ void edge_scatter(const int* __restrict__ ei){
    int e = blockIdx.x*blockDim.x + threadIdx.x;
    if (e >= NE) return;
    int s, d;
    if (e < NE0) { s = ei[e]; d = ei[NE0+e]; } else { s = e - NE0; d = s; }
    int pos = atomicAdd(&g_cur[d], 1);
    g_ssrc[pos] = s;
}

// ---------------- GAT ----------------
__global__ void attn_coef(const float* __restrict__ F, const float* __restrict__ a_s,
                          const float* __restrict__ a_d)
{
    int w = (blockIdx.x*blockDim.x + threadIdx.x) >> 5;
    if (w >= NN*3) return;
    int lane = threadIdx.x & 31;
    int node = w / 3, h = w - node*3;
    const float* f = F + (long)node*F3 + h*HE;
    const float* As_ = a_s + h*HE;
    const float* Ad_ = a_d + h*HE;
    float s1 = 0.f, s2 = 0.f;
    #pragma unroll
    for (int c = lane; c < HE; c += 32) { float fv = f[c]; s1 += fv*As_[c]; s2 += fv*Ad_[c]; }
    #pragma unroll
    for (int o = 16; o; o >>= 1) {
        s1 += __shfl_down_sync(0xffffffffu, s1, o);
        s2 += __shfl_down_sync(0xffffffffu, s2, o);
    }
    if (lane == 0) { g_asv[w] = s1; g_adv[w] = s2; }
}

__global__ void gat_agg(const float* __restrict__ F, const float* __restrict__ bias,
                        float* __restrict__ O)
{
    int w = (blockIdx.x*blockDim.x + threadIdx.x) >> 5;
    if (w >= NN) return;
    int lane = threadIdx.x & 31;
    int beg = g_offs[w], end = g_offs[w+1];
    float ad0 = g_adv[w*3], ad1 = g_adv[w*3+1], ad2 = g_adv[w*3+2];
    float m0 = -1e30f, m1 = -1e30f, m2 = -1e30f;
    float d0 = 0.f, d1 = 0.f, d2 = 0.f;
    float acc[12];
    #pragma unroll
    for (int q = 0; q < 12; ++q) acc[q] = 0.f;

    for (int p = beg; p < end; ++p) {
        int s = g_ssrc[p];
        float e0 = g_asv[s*3]   + ad0; e0 = (e0 >= 0.f) ? e0 : 0.2f*e0;
        float e1 = g_asv[s*3+1] + ad1; e1 = (e1 >= 0.f) ? e1 : 0.2f*e1;
        float e2 = g_asv[s*3+2] + ad2; e2 = (e2 >= 0.f) ? e2 : 0.2f*e2;
        const float* f = F + (long)s*F3;
        {
            float nm = fmaxf(m0, e0); float sc = __expf(m0-nm); float wv = __expf(e0-nm);
            d0 = d0*sc + wv;
            #pragma unroll
            for (int q = 0; q < 4; ++q) acc[q] = acc[q]*sc + wv*f[q*32 + lane];
            m0 = nm;
        }
        {
            float nm = fmaxf(m1, e1); float sc = __expf(m1-nm); float wv = __expf(e1-nm);
            d1 = d1*sc + wv;
            #pragma unroll
            for (int q = 0; q < 4; ++q) acc[4+q] = acc[4+q]*sc + wv*f[HE + q*32 + lane];
            m1 = nm;
        }
        {
            float nm = fmaxf(m2, e2); float sc = __expf(m2-nm); float wv = __expf(e2-nm);
            d2 = d2*sc + wv;
            #pragma unroll
            for (int q = 0; q < 4; ++q) acc[8+q] = acc[8+q]*sc + wv*f[2*HE + q*32 + lane];
            m2 = nm;
        }
    }
    float* o = O + (long)w*F3;
    #pragma unroll
    for (int q = 0; q < 4; ++q) {
        int c0 = q*32 + lane;
        o[c0]        = acc[q]  /d0 + bias[c0];
        o[HE + c0]   = acc[4+q]/d1 + bias[HE + c0];
        o[2*HE + c0] = acc[8+q]/d2 + bias[2*HE + c0];
    }
}

// ---------------- output head ----------------
__global__ void out_head(const float* __restrict__ h1, const float* __restrict__ opW,
                         const float* __restrict__ opb, float* __restrict__ out, int t)
{
    int w = (blockIdx.x*blockDim.x + threadIdx.x) >> 5;
    if (w >= NT) return;
    int lane = threadIdx.x & 31;
    const float* h = h1 + (long)w*HD;
    float s0 = 0.f, s1 = 0.f;
    #pragma unroll
    for (int k = lane; k < HD; k += 32) {
        float hv = h[k];
        s0 += hv*opW[k*2];
        s1 += hv*opW[k*2+1];
    }
    #pragma unroll
    for (int o = 16; o; o >>= 1) {
        s0 += __shfl_down_sync(0xffffffffu, s0, o);
        s1 += __shfl_down_sync(0xffffffffu, s1, o);
    }
    if (lane == 0) {
        long base = ((long)w*OUTL + t)*2;
        out[base]   = s0 + opb[0];
        out[base+1] = s1 + opb[1];
    }
}

// ---------------- host ----------------
template<int PRE, int ACT>
static inline void mmagemm(const float* A, const __nv_bfloat16* Wh, const __nv_bfloat16* Wl, int K,
                           const float* bias, const int* ridx, float* C, long M, int N)
{
    dim3 g(N/WBN, (unsigned)((M + WBM - 1)/WBM));
    mma_gemm<PRE,ACT><<<g, 256, MMA_SMEM>>>(A, Wh, Wl, K, bias, ridx, C, (int)M, N);
}

extern "C" void kernel_launch(void* const* d_in, const int* in_sizes, int n_in,
                              void* d_out, int out_size)
{
    const float* x    = (const float*)d_in[0];
    const int*   ei   = (const int*)  d_in[1];
    const int*   tgt  = (const int*)  d_in[2];
    const float* ipW  = (const float*)d_in[3];
    const float* ipb  = (const float*)d_in[4];
    const float* gWx  = (const float*)d_in[5];
    const float* gWh  = (const float*)d_in[6];
    const float* gbx  = (const float*)d_in[7];
    const float* gbh  = (const float*)d_in[8];
    const float* dynW = (const float*)d_in[9];
    const float* dynb = (const float*)d_in[10];
    const float* g1W  = (const float*)d_in[11];
    const float* g1as = (const float*)d_in[12];
    const float* g1ad = (const float*)d_in[13];
    const float* g1b  = (const float*)d_in[14];
    const float* g2W  = (const float*)d_in[15];
    const float* g2as = (const float*)d_in[16];
    const float* g2ad = (const float*)d_in[17];
    const float* g2b  = (const float*)d_in[18];
    const float* fcW  = (const float*)d_in[19];
    const float* fcb  = (const float*)d_in[20];
    const float* l0Wx = (const float*)d_in[21];
    const float* l0Wh = (const float*)d_in[22];
    const float* l0b  = (const float*)d_in[23];
    const float* l1Wx = (const float*)d_in[24];
    const float* l1Wh = (const float*)d_in[25];
    const float* l1b  = (const float*)d_in[26];
    const float* opW  = (const float*)d_in[27];
    const float* opb  = (const float*)d_in[28];
    float* out = (float*)d_out;
    (void)in_sizes; (void)n_in; (void)out_size;

    float *H,*H2,*HENC,*F1,*O1,*F2,*O2,*ENC,*X0,*c0,*c1,*h0a,*h0b,*h1a,*h1b;
    float *l0bp,*l1bp;
    __nv_bfloat16 *WTh,*WTl;
    cudaGetSymbolAddress((void**)&H,    g_H);
    cudaGetSymbolAddress((void**)&H2,   g_H2);
    cudaGetSymbolAddress((void**)&HENC, g_HENC);
    cudaGetSymbolAddress((void**)&F1,   g_F1);
    cudaGetSymbolAddress((void**)&O1,   g_O1);
    cudaGetSymbolAddress((void**)&F2,   g_F2);
    cudaGetSymbolAddress((void**)&O2,   g_O2);
    cudaGetSymbolAddress((void**)&ENC,  g_ENC);
    cudaGetSymbolAddress((void**)&X0,   g_X0);
    cudaGetSymbolAddress((void**)&c0,   g_c0);
    cudaGetSymbolAddress((void**)&c1,   g_c1);
    cudaGetSymbolAddress((void**)&h0a,  g_h0a);
    cudaGetSymbolAddress((void**)&h0b,  g_h0b);
    cudaGetSymbolAddress((void**)&h1a,  g_h1a);
    cudaGetSymbolAddress((void**)&h1b,  g_h1b);
    cudaGetSymbolAddress((void**)&l0bp, g_l0bp);
    cudaGetSymbolAddress((void**)&l1bp, g_l1bp);
    cudaGetSymbolAddress((void**)&WTh,  g_WThi);
    cudaGetSymbolAddress((void**)&WTl,  g_WTlo);
    int *cntp;
    cudaGetSymbolAddress((void**)&cntp, g_cnt);

    // weight offsets (elements)
    const int o_g1W  = 61440;
    const int o_g2W  = 110592;
    const int o_l0Wx = 258048;
    const int o_l0Wh = 389120;
    const int o_l1   = 651264;
    const int o_dyn  = 1175552;
    const int o_fc   = 1191936;
    const int o_gru  = 1241088;

    // ---- weight prep ----
    zero_f<<<(40960+255)/256,256>>>((float*)(WTh+o_gru), 40960);
    zero_f<<<(40960+255)/256,256>>>((float*)(WTl+o_gru), 40960);
    wscat_gru<<<(128*F3+255)/256,256>>>(gWh, WTh+o_gru, WTl+o_gru, 128, 0,   0);
    wscat_gru<<<(32*F3+255)/256,256>>>(gWx,  WTh+o_gru, WTl+o_gru, 32,  128, 1);
    grub_kernel<<<1,128>>>(gbx, gbh);
    wsplitp<<<(128*384+255)/256,256>>>(g1W,  WTh+o_g1W,  WTl+o_g1W,  128, 384, 1, 128, 0);
    wsplitp<<<(384*384+255)/256,256>>>(g2W,  WTh+o_g2W,  WTl+o_g2W,  384, 384, 1, 384, 0);
    wsplitp<<<(128*1024+255)/256,256>>>(l0Wx, WTh+o_l0Wx, WTl+o_l0Wx, 128, 1024, 4, 128, 0);
    wsplitp<<<(256*1024+255)/256,256>>>(l0Wh, WTh+o_l0Wh, WTl+o_l0Wh, 256, 1024, 4, 256, 0);
    wsplitp<<<(256*1024+255)/256,256>>>(l1Wx, WTh+o_l1,   WTl+o_l1,   256, 1024, 4, 512, 0);
    wsplitp<<<(256*1024+255)/256,256>>>(l1Wh, WTh+o_l1,   WTl+o_l1,   256, 1024, 4, 512, 256);
    wsplitp<<<(128*128+255)/256,256>>>(dynW, WTh+o_dyn,  WTl+o_dyn,  128, 128, 1, 128, 0);
    wsplitp<<<(384*128+255)/256,256>>>(fcW,  WTh+o_fc,   WTl+o_fc,   384, 128, 1, 384, 0);
    bperm<<<4,256>>>(l0b, l0bp, 1024, 4);
    bperm<<<4,256>>>(l1b, l1bp, 1024, 4);

    // ---- CSR build ----
    zero_i<<<(NN+255)/256,256>>>(cntp, NN);
    edge_count<<<(NE+255)/256,256>>>(ei);
    scan_kernel<<<1,1024>>>();
    copy_cur<<<(NN+255)/256,256>>>();
    edge_scatter<<<(NE+255)/256,256>>>(ei);

    // ---- encoder ----
    emb_kernel<<<(int)(((long)NN*TT*DE + 255)/256),256>>>(x, ipW, ipb);
    zero_f<<<(int)(((long)NN*HE + 255)/256),256>>>(H, (long)NN*HE);
    {
        dim3 gg(8, (NN+127)/128);
        for (int t = 0; t < TT; ++t) {
            const float* hin  = (t & 1) ? H2 : H;
            float*       hout = (t & 1) ? H  : H2;
            gru_step2<<<gg, 256, MMA_SMEM>>>(hin, WTh+o_gru, WTl+o_gru, hout, t);
        }
    }

    // hist_enc
    mmagemm<1,1>(H, WTh+o_dyn, WTl+o_dyn, HE, dynb, nullptr, HENC, NN, HE);

    // ---- GAT layer 1 ----
    mmagemm<0,0>(HENC, WTh+o_g1W, WTl+o_g1W, HE, nullptr, nullptr, F1, NN, F3);
    attn_coef<<<(NN*3*32+255)/256,256>>>(F1, g1as, g1ad);
    gat_agg<<<(NN*32+255)/256,256>>>(F1, g1b, O1);

    // ---- GAT layer 2 ----
    mmagemm<0,0>(O1, WTh+o_g2W, WTl+o_g2W, F3, nullptr, nullptr, F2, NN, F3);
    attn_coef<<<(NN*3*32+255)/256,256>>>(F2, g2as, g2ad);
    gat_agg<<<(NN*32+255)/256,256>>>(F2, g2b, O2);

    // ---- target gather + fc + X0 ----
    mmagemm<0,1>(O2, WTh+o_fc, WTl+o_fc, F3, fcb, tgt, ENC, NT, HE);
    mmagemm<0,0>(ENC, WTh+o_l0Wx, WTl+o_l0Wx, HE, l0bp, nullptr, X0, NT, 4*HD);
    zero_f<<<((NT*HD)+255)/256,256>>>(h0a, (long)NT*HD);
    zero_f<<<((NT*HD)+255)/256,256>>>(h1a, (long)NT*HD);

    // ---- decoder ----
    {
        dim3 gd(16, (NT+127)/128);
        for (int t = 0; t < OUTL; ++t) {
            float* h0in  = (t & 1) ? h0b : h0a;
            float* h0out = (t & 1) ? h0a : h0b;
            float* h1in  = (t & 1) ? h1b : h1a;
            float* h1out = (t & 1) ? h1a : h1b;
            dec_gemm<0><<<gd, 256, MMA_SMEM>>>(h0in, nullptr, WTh+o_l0Wh, WTl+o_l0Wh,
                                               X0, c0, h0out, t == 0);
            dec_gemm<1><<<gd, 256, MMA_SMEM>>>(h0out, h1in, WTh+o_l1, WTl+o_l1,
                                               l1bp, c1, h1out, t == 0);
            out_head<<<(NT*32+255)/256,256>>>(h1out, opW, opb, out, t);
        }
    }
}

// round 15
// speedup vs baseline: 1.2174x; 1.0378x over previous
#include <cuda_runtime.h>
#include <cuda_bf16.h>
#include <mma.h>
#include <math.h>
#include <stdint.h>

using namespace nvcuda;

#define NN   30000
#define TT   16
#define DE   32
#define HE   128
#define F3   384
#define NE0  300000
#define NE   330000
#define NT   3000
#define HD   256
#define OUTL 25

// ---------------- scratch ----------------
__device__ __align__(256) float g_EMB[NN*TT*DE];
__device__ __align__(256) float g_H[NN*HE];
__device__ __align__(256) float g_H2[NN*HE];
__device__ __align__(256) float g_HENC[NN*HE];
__device__ __align__(256) float g_F1[NN*F3];
__device__ __align__(256) float g_O1[NN*F3];
__device__ __align__(256) float g_F2[NN*F3];
__device__ __align__(256) float g_O2[NN*F3];
__device__ __align__(256) float g_asv[NN*3];
__device__ __align__(256) float g_adv[NN*3];
__device__ __align__(256) float g_ENC[NT*HE];
__device__ __align__(256) float g_X0[NT*4*HD];
__device__ __align__(256) float g_c0[NT*HD];
__device__ __align__(256) float g_c1[NT*HD];
__device__ __align__(256) float g_h0a[NT*HD];
__device__ __align__(256) float g_h0b[NT*HD];
__device__ __align__(256) float g_h1z[NT*HD];
__device__ __align__(256) float g_H1ALL[(long)OUTL*NT*HD];
__device__ int g_cnt[NN];
__device__ int g_offs[NN+1];
__device__ int g_cur[NN];
__device__ int g_ssrc[NE];
__device__ float g_grub[512];
__device__ float g_l0bp[4*HD];
__device__ float g_l1bp[4*HD];
#define WT_TOTAL 1330000
__device__ __align__(256) __nv_bfloat16 g_WThi[WT_TOTAL];
__device__ __align__(256) __nv_bfloat16 g_WTlo[WT_TOTAL];

__device__ __forceinline__ float sigf(float x){ return 1.f/(1.f+__expf(-x)); }
__device__ __forceinline__ float lk01(float x){ return x>=0.f? x : 0.1f*x; }

// ---------------- utility ----------------
__global__ void zero_f(float* __restrict__ p, long n){
    long i = (long)blockIdx.x*blockDim.x + threadIdx.x;
    if (i < n) p[i] = 0.f;
}
__global__ void zero_i(int* __restrict__ p, int n){
    int i = blockIdx.x*blockDim.x + threadIdx.x;
    if (i < n) p[i] = 0;
}

__global__ void wsplitp(const float* __restrict__ W, __nv_bfloat16* __restrict__ hi,
                        __nv_bfloat16* __restrict__ lo, int K, int N, int P,
                        int ldk, int kofs)
{
    int idx = blockIdx.x*blockDim.x + threadIdx.x;
    if (idx >= K*N) return;
    int k = idx / N, n = idx - k*N;
    int Gp = N / P;
    int np = (n % Gp)*P + n/Gp;
    float v = W[idx];
    __nv_bfloat16 h = __float2bfloat16(v);
    hi[(long)np*ldk + kofs + k] = h;
    lo[(long)np*ldk + kofs + k] = __float2bfloat16(v - __bfloat162float(h));
}

// GRU packed-weight scatter into [512][160]
__global__ void wscat_gru(const float* __restrict__ W, __nv_bfloat16* __restrict__ hi,
                          __nv_bfloat16* __restrict__ lo, int K, int kbase, int mode)
{
    int idx = blockIdx.x*blockDim.x + threadIdx.x;
    if (idx >= K*F3) return;
    int k = idx / F3, n = idx - k*F3;
    int g = n / HE, j = n - g*HE;
    int cp = 4*j + ((g < 2) ? g : (mode ? 3 : 2));
    float v = W[idx];
    __nv_bfloat16 h = __float2bfloat16(v);
    long o = (long)cp*160 + kbase + k;
    hi[o] = h;
    lo[o] = __float2bfloat16(v - __bfloat162float(h));
}

__global__ void grub_kernel(const float* __restrict__ gbx, const float* __restrict__ gbh)
{
    int j = threadIdx.x;
    if (j < HE) {
        g_grub[4*j+0] = gbx[j]       + gbh[j];
        g_grub[4*j+1] = gbx[HE+j]    + gbh[HE+j];
        g_grub[4*j+2] = gbh[2*HE+j];
        g_grub[4*j+3] = gbx[2*HE+j];
    }
}

__global__ void bperm(const float* __restrict__ b, float* __restrict__ bp, int N, int P)
{
    int n = blockIdx.x*blockDim.x + threadIdx.x;
    if (n >= N) return;
    int Gp = N / P;
    bp[(n % Gp)*P + n/Gp] = b[n];
}

typedef wmma::fragment<wmma::matrix_a, 16,16,16, __nv_bfloat16, wmma::row_major> FragA;
typedef wmma::fragment<wmma::matrix_b, 16,16,16, __nv_bfloat16, wmma::col_major> FragB;
typedef wmma::fragment<wmma::accumulator, 16,16,16, float> FragC;

#define WBM 128
#define WBN 64
// BK=64 layout (mma_gemm, dec_gemm)
#define SKA2 72
#define SKB2 72
#define GEMM_SMEM 55296
// BK=32 layout (gru)
#define SKA 40
#define SKB 40
#define GRU_SMEM2 36864

__device__ __forceinline__ void splitstore_a(__nv_bfloat16* Ah, __nv_bfloat16* Al,
                                             int o, float4 v)
{
    __nv_bfloat16 hx = __float2bfloat16(v.x);
    __nv_bfloat16 hy = __float2bfloat16(v.y);
    __nv_bfloat16 hz = __float2bfloat16(v.z);
    __nv_bfloat16 hw = __float2bfloat16(v.w);
    Ah[o]   = hx; Ah[o+1] = hy; Ah[o+2] = hz; Ah[o+3] = hw;
    Al[o]   = __float2bfloat16(v.x - __bfloat162float(hx));
    Al[o+1] = __float2bfloat16(v.y - __bfloat162float(hy));
    Al[o+2] = __float2bfloat16(v.z - __bfloat162float(hz));
    Al[o+3] = __float2bfloat16(v.w - __bfloat162float(hw));
}

// ---------------- generic WMMA bf16x3 GEMM (BK=64, register-prefetch) ----------------
// requires K1 % 64 == 0
template<int PRE, int ACT>
__global__ void __launch_bounds__(256,2)
mma_gemm(const float* __restrict__ A1, const __nv_bfloat16* __restrict__ W1h,
         const __nv_bfloat16* __restrict__ W1l, int K1,
         const float* __restrict__ bias, const int* __restrict__ rowidx,
         float* __restrict__ C, int M, int N)
{
    extern __shared__ char smc[];
    __nv_bfloat16* Ah = (__nv_bfloat16*)smc;           // [128][72]
    __nv_bfloat16* Al = Ah + WBM*SKA2;
    __nv_bfloat16* Bh = Al + WBM*SKA2;                 // [64][72]
    __nv_bfloat16* Bl = Bh + WBN*SKB2;
    float* Cs = (float*)smc;

    const int tid = threadIdx.x, wid = tid >> 5;
    const int warp_m = wid >> 1, warp_n = wid & 1;
    const long bm = (long)blockIdx.y * WBM;
    const int bn = blockIdx.x * WBN;

    const int ra0 = tid >> 4, ca = (tid & 15) << 2;
    const int rb0 = tid >> 3, cbb = (tid & 7) << 3;
    long arow[8];
    #pragma unroll
    for (int i = 0; i < 8; ++i) {
        long row = bm + ra0 + 16*i;
        arow[i] = (row < M) ? (rowidx ? (long)rowidx[row] : row) : -1;
    }

    FragC acc[2][2];
    #pragma unroll
    for (int mm = 0; mm < 2; ++mm)
        #pragma unroll
        for (int nn = 0; nn < 2; ++nn)
            wmma::fill_fragment(acc[mm][nn], 0.f);

    float4 va[8];
    uint4 vbh[2], vbl[2];
    #pragma unroll
    for (int i = 0; i < 8; ++i) {
        va[i] = make_float4(0.f,0.f,0.f,0.f);
        if (arow[i] >= 0) va[i] = *(const float4*)(A1 + arow[i]*K1 + ca);
    }
    #pragma unroll
    for (int i = 0; i < 2; ++i) {
        long go = (long)(bn + rb0 + 32*i)*K1 + cbb;
        vbh[i] = *(const uint4*)(W1h + go);
        vbl[i] = *(const uint4*)(W1l + go);
    }

    for (int k0 = 0; k0 < K1; k0 += 64) {
        #pragma unroll
        for (int i = 0; i < 8; ++i) {
            float4 v = va[i];
            if (PRE) { v.x=lk01(v.x); v.y=lk01(v.y); v.z=lk01(v.z); v.w=lk01(v.w); }
            splitstore_a(Ah, Al, (ra0 + 16*i)*SKA2 + ca, v);
        }
        #pragma unroll
        for (int i = 0; i < 2; ++i) {
            *(uint4*)&Bh[(rb0 + 32*i)*SKB2 + cbb] = vbh[i];
            *(uint4*)&Bl[(rb0 + 32*i)*SKB2 + cbb] = vbl[i];
        }
        __syncthreads();

        const int kn = k0 + 64;
        if (kn < K1) {
            #pragma unroll
            for (int i = 0; i < 8; ++i) {
                va[i] = make_float4(0.f,0.f,0.f,0.f);
                if (arow[i] >= 0) va[i] = *(const float4*)(A1 + arow[i]*K1 + kn + ca);
            }
            #pragma unroll
            for (int i = 0; i < 2; ++i) {
                long go = (long)(bn + rb0 + 32*i)*K1 + kn + cbb;
                vbh[i] = *(const uint4*)(W1h + go);
                vbl[i] = *(const uint4*)(W1l + go);
            }
        }

        #pragma unroll
        for (int kk = 0; kk < 64; kk += 16) {
            FragA ah[2], al[2];
            FragB bh[2], bl[2];
            #pragma unroll
            for (int mm = 0; mm < 2; ++mm) {
                int ro = (warp_m*32 + mm*16)*SKA2 + kk;
                wmma::load_matrix_sync(ah[mm], Ah + ro, SKA2);
                wmma::load_matrix_sync(al[mm], Al + ro, SKA2);
            }
            #pragma unroll
            for (int nn = 0; nn < 2; ++nn) {
                int no = (warp_n*32 + nn*16)*SKB2 + kk;
                wmma::load_matrix_sync(bh[nn], Bh + no, SKB2);
                wmma::load_matrix_sync(bl[nn], Bl + no, SKB2);
            }
            #pragma unroll
            for (int mm = 0; mm < 2; ++mm)
                #pragma unroll
                for (int nn = 0; nn < 2; ++nn) {
                    wmma::mma_sync(acc[mm][nn], ah[mm], bh[nn], acc[mm][nn]);
                    wmma::mma_sync(acc[mm][nn], ah[mm], bl[nn], acc[mm][nn]);
                    wmma::mma_sync(acc[mm][nn], al[mm], bh[nn], acc[mm][nn]);
                }
        }
        __syncthreads();
    }

    #pragma unroll
    for (int mm = 0; mm < 2; ++mm)
        #pragma unroll
        for (int nn = 0; nn < 2; ++nn)
            wmma::store_matrix_sync(Cs + (warp_m*32 + mm*16)*68 + warp_n*32 + nn*16,
                                    acc[mm][nn], 68, wmma::mem_row_major);
    __syncthreads();

    #pragma unroll
    for (int i = 0; i < 8; ++i) {
        int li = tid + (i << 8);
        int r = li >> 4, c = (li & 15) << 2;
        long row = bm + r;
        if (row >= M) continue;
        float4 v = *(float4*)&Cs[r*68 + c];
        int col = bn + c;
        if (bias) {
            float4 bb = *(const float4*)(bias + col);
            v.x += bb.x; v.y += bb.y; v.z += bb.z; v.w += bb.w;
        }
        if (ACT) { v.x=lk01(v.x); v.y=lk01(v.y); v.z=lk01(v.z); v.w=lk01(v.w); }
        *(float4*)(C + row*(long)N + col) = v;
    }
}

// ---------------- GRU step (BK=32 pipelined, K=160), fused gates ----------------
__global__ void __launch_bounds__(256,2)
gru_step2(const float* __restrict__ Hin, const __nv_bfloat16* __restrict__ Wh,
          const __nv_bfloat16* __restrict__ Wl, float* __restrict__ Hout, int t)
{
    extern __shared__ char sm[];
    __nv_bfloat16* Ah = (__nv_bfloat16*)sm;
    __nv_bfloat16* Al = Ah + 128*SKA;
    __nv_bfloat16* Bh = Al + 128*SKA;
    __nv_bfloat16* Bl = Bh + 64*SKB;
    float* Cs = (float*)sm;

    const int tid = threadIdx.x, wid = tid >> 5;
    const int warp_m = wid >> 1, warp_n = wid & 1;
    const long bm = (long)blockIdx.y * 128;
    const int bn = blockIdx.x * 64;

    const int ra0 = tid >> 3, ca = (tid & 7) << 2;
    const int rb  = tid >> 2, cb = (tid & 3) << 3;
    long nodei[4];
    #pragma unroll
    for (int i = 0; i < 4; ++i) {
        long node = bm + ra0 + 32*i;
        nodei[i] = (node < NN) ? node : -1;
    }

    FragC acc[2][2];
    #pragma unroll
    for (int mm = 0; mm < 2; ++mm)
        #pragma unroll
        for (int nn = 0; nn < 2; ++nn)
            wmma::fill_fragment(acc[mm][nn], 0.f);

    float4 va[4];
    uint4 vbh, vbl;
    #pragma unroll
    for (int i = 0; i < 4; ++i) {
        va[i] = make_float4(0.f,0.f,0.f,0.f);
        if (nodei[i] >= 0) va[i] = *(const float4*)(Hin + nodei[i]*HE + ca);
    }
    {
        long go = (long)(bn + rb)*160 + cb;
        vbh = *(const uint4*)(Wh + go);
        vbl = *(const uint4*)(Wl + go);
    }

    #pragma unroll
    for (int ch = 0; ch < 5; ++ch) {
        #pragma unroll
        for (int i = 0; i < 4; ++i)
            splitstore_a(Ah, Al, (ra0 + 32*i)*SKA + ca, va[i]);
        *(uint4*)&Bh[rb*SKB + cb] = vbh;
        *(uint4*)&Bl[rb*SKB + cb] = vbl;
        __syncthreads();

        if (ch + 1 < 5) {
            const int cn = ch + 1;
            #pragma unroll
            for (int i = 0; i < 4; ++i) {
                va[i] = make_float4(0.f,0.f,0.f,0.f);
                if (nodei[i] >= 0) {
                    if (cn < 4) va[i] = *(const float4*)(Hin + nodei[i]*HE + (cn<<5) + ca);
                    else        va[i] = *(const float4*)(g_EMB + (nodei[i]*TT + t)*DE + ca);
                }
            }
            long go = (long)(bn + rb)*160 + (cn<<5) + cb;
            vbh = *(const uint4*)(Wh + go);
            vbl = *(const uint4*)(Wl + go);
        }

        #pragma unroll
        for (int kk = 0; kk < 32; kk += 16) {
            FragA ah[2], al[2];
            FragB bh[2], bl[2];
            #pragma unroll
            for (int mm = 0; mm < 2; ++mm) {
                int ro = (warp_m*32 + mm*16)*SKA + kk;
                wmma::load_matrix_sync(ah[mm], Ah + ro, SKA);
                wmma::load_matrix_sync(al[mm], Al + ro, SKA);
            }
            #pragma unroll
            for (int nn = 0; nn < 2; ++nn) {
                int no = (warp_n*32 + nn*16)*SKB + kk;
                wmma::load_matrix_sync(bh[nn], Bh + no, SKB);
                wmma::load_matrix_sync(bl[nn], Bl + no, SKB);
            }
            #pragma unroll
            for (int mm = 0; mm < 2; ++mm)
                #pragma unroll
                for (int nn = 0; nn < 2; ++nn) {
                    wmma::mma_sync(acc[mm][nn], ah[mm], bh[nn], acc[mm][nn]);
                    wmma::mma_sync(acc[mm][nn], ah[mm], bl[nn], acc[mm][nn]);
                    wmma::mma_sync(acc[mm][nn], al[mm], bh[nn], acc[mm][nn]);
                }
        }
        __syncthreads();
    }

    #pragma unroll
    for (int mm = 0; mm < 2; ++mm)
        #pragma unroll
        for (int nn = 0; nn < 2; ++nn)
            wmma::store_matrix_sync(Cs + (warp_m*32 + mm*16)*68 + warp_n*32 + nn*16,
                                    acc[mm][nn], 68, wmma::mem_row_major);
    __syncthreads();

    #pragma unroll
    for (int i = 0; i < 8; ++i) {
        int li = tid + (i << 8);
        int r = li >> 4, q = li & 15;
        long node = bm + r;
        if (node < NN) {
            int j = blockIdx.x*16 + q;
            const float* gs = Cs + r*68 + 4*q;
            float rr  = sigf(gs[0] + g_grub[4*j+0]);
            float zz  = sigf(gs[1] + g_grub[4*j+1]);
            float ghn = gs[2] + g_grub[4*j+2];
            float gxn = gs[3] + g_grub[4*j+3];
            float nn2 = tanhf(gxn + rr*ghn);
            float hold = Hin[node*HE + j];
            Hout[node*HE + j] = (1.f - zz)*nn2 + zz*hold;
        }
    }
}

// ---------------- decoder step GEMM (BK=64 pipelined) with fused LSTM gates ----------------
template<int L1>
__global__ void __launch_bounds__(256,2)
dec_gemm(const float* __restrict__ A1, const float* __restrict__ A2,
         const __nv_bfloat16* __restrict__ Wh, const __nv_bfloat16* __restrict__ Wl,
         const float* __restrict__ pre, float* __restrict__ cbuf,
         float* __restrict__ hout, int first)
{
    extern __shared__ char sm[];
    __nv_bfloat16* Ah = (__nv_bfloat16*)sm;
    __nv_bfloat16* Al = Ah + WBM*SKA2;
    __nv_bfloat16* Bh = Al + WBM*SKA2;
    __nv_bfloat16* Bl = Bh + WBN*SKB2;
    float* Cs = (float*)sm;

    const int tid = threadIdx.x, wid = tid >> 5;
    const int warp_m = wid >> 1, warp_n = wid & 1;
    const long bm = (long)blockIdx.y * WBM;
    const int bn = blockIdx.x * WBN;
    const int KTOT = L1 ? 2*HD : HD;

    const int ra0 = tid >> 4, ca = (tid & 15) << 2;
    const int rb0 = tid >> 3, cbb = (tid & 7) << 3;
    long rowi[8];
    #pragma unroll
    for (int i = 0; i < 8; ++i) {
        long row = bm + ra0 + 16*i;
        rowi[i] = (row < NT) ? row : -1;
    }

    FragC acc[2][2];
    #pragma unroll
    for (int mm = 0; mm < 2; ++mm)
        #pragma unroll
        for (int nn = 0; nn < 2; ++nn)
            wmma::fill_fragment(acc[mm][nn], 0.f);

    float4 va[8];
    uint4 vbh[2], vbl[2];
    #pragma unroll
    for (int i = 0; i < 8; ++i) {
        va[i] = make_float4(0.f,0.f,0.f,0.f);
        if (rowi[i] >= 0) va[i] = *(const float4*)(A1 + rowi[i]*HD + ca);
    }
    #pragma unroll
    for (int i = 0; i < 2; ++i) {
        long go = (long)(bn + rb0 + 32*i)*KTOT + cbb;
        vbh[i] = *(const uint4*)(Wh + go);
        vbl[i] = *(const uint4*)(Wl + go);
    }

    for (int k0 = 0; k0 < KTOT; k0 += 64) {
        #pragma unroll
        for (int i = 0; i < 8; ++i)
            splitstore_a(Ah, Al, (ra0 + 16*i)*SKA2 + ca, va[i]);
        #pragma unroll
        for (int i = 0; i < 2; ++i) {
            *(uint4*)&Bh[(rb0 + 32*i)*SKB2 + cbb] = vbh[i];
            *(uint4*)&Bl[(rb0 + 32*i)*SKB2 + cbb] = vbl[i];
        }
        __syncthreads();

        const int kn = k0 + 64;
        if (kn < KTOT) {
            const float* A = (L1 && kn >= HD) ? A2 : A1;
            const int ka = kn & (HD-1);
            #pragma unroll
            for (int i = 0; i < 8; ++i) {
                va[i] = make_float4(0.f,0.f,0.f,0.f);
                if (rowi[i] >= 0) va[i] = *(const float4*)(A + rowi[i]*HD + ka + ca);
            }
            #pragma unroll
            for (int i = 0; i < 2; ++i) {
                long go = (long)(bn + rb0 + 32*i)*KTOT + kn + cbb;
                vbh[i] = *(const uint4*)(Wh + go);
                vbl[i] = *(const uint4*)(Wl + go);
            }
        }

        #pragma unroll
        for (int kk = 0; kk < 64; kk += 16) {
            FragA ah[2], al[2];
            FragB bh[2], bl[2];
            #pragma unroll
            for (int mm = 0; mm < 2; ++mm) {
                int ro = (warp_m*32 + mm*16)*SKA2 + kk;
                wmma::load_matrix_sync(ah[mm], Ah + ro, SKA2);
                wmma::load_matrix_sync(al[mm], Al + ro, SKA2);
            }
            #pragma unroll
            for (int nn = 0; nn < 2; ++nn) {
                int no = (warp_n*32 + nn*16)*SKB2 + kk;
                wmma::load_matrix_sync(bh[nn], Bh + no, SKB2);
                wmma::load_matrix_sync(bl[nn], Bl + no, SKB2);
            }
            #pragma unroll
            for (int mm = 0; mm < 2; ++mm)
                #pragma unroll
                for (int nn = 0; nn < 2; ++nn) {
                    wmma::mma_sync(acc[mm][nn], ah[mm], bh[nn], acc[mm][nn]);
                    wmma::mma_sync(acc[mm][nn], ah[mm], bl[nn], acc[mm][nn]);
                    wmma::mma_sync(acc[mm][nn], al[mm], bh[nn], acc[mm][nn]);
                }
        }
        __syncthreads();
    }

    #pragma unroll
    for (int mm = 0; mm < 2; ++mm)
        #pragma unroll
        for (int nn = 0; nn < 2; ++nn)
            wmma::store_matrix_sync(Cs + (warp_m*32 + mm*16)*68 + warp_n*32 + nn*16,
                                    acc[mm][nn], 68, wmma::mem_row_major);
    __syncthreads();

    #pragma unroll
    for (int i = 0; i < 8; ++i) {
        int li = tid + (i << 8);
        int r = li >> 4, q = li & 15;
        long row = bm + r;
        if (row < NT) {
            int j = blockIdx.x*16 + q;
            const float* gs = Cs + r*68 + 4*q;
            const float* pp = L1 ? (pre + bn + 4*q) : (pre + row*(4*HD) + bn + 4*q);
            float ig = sigf(gs[0] + pp[0]);
            float fg = sigf(gs[1] + pp[1]);
            float gg = tanhf(gs[2] + pp[2]);
            float og = sigf(gs[3] + pp[3]);
            float c = first ? 0.f : cbuf[row*HD + j];
            c = fg*c + ig*gg;
            cbuf[row*HD + j] = c;
            hout[row*HD + j] = og*tanhf(c);
        }
    }
}

// ---------------- encoder embedding ----------------
__global__ void emb_kernel(const float* __restrict__ x, const float* __restrict__ ipW,
                           const float* __restrict__ ipb)
{
    long i = (long)blockIdx.x*blockDim.x + threadIdx.x;
    if (i >= (long)NN*TT*DE) return;
    long row = i >> 5; int j = (int)(i & 31);
    float v = x[row*2]*ipW[j] + x[row*2+1]*ipW[DE+j] + ipb[j];
    g_EMB[i] = lk01(v);
}

// ---------------- CSR build ----------------
__global__ void edge_count(const int* __restrict__ ei){
    int e = blockIdx.x*blockDim.x + threadIdx.x;
    if (e >= NE) return;
    int d = (e < NE0) ? ei[NE0+e] : (e - NE0);
    atomicAdd(&g_cnt[d], 1);
}
__global__ void scan_kernel(){
    __shared__ int sh[1024];
    __shared__ int run;
    int tid = threadIdx.x;
    if (tid == 0) run = 0;
    __syncthreads();
    for (int base = 0; base < NN; base += 1024) {
        int v = (base + tid < NN) ? g_cnt[base + tid] : 0;
        sh[tid] = v; __syncthreads();
        for (int off = 1; off < 1024; off <<= 1) {
            int tv = (tid >= off) ? sh[tid-off] : 0;
            __syncthreads();
            sh[tid] += tv;
            __syncthreads();
        }
        if (base + tid < NN) g_offs[base + tid + 1] = run + sh[tid];
        __syncthreads();
        if (tid == 0) run += sh[1023];
        __syncthreads();
    }
    if (tid == 0) g_offs[0] = 0;
}
__global__ void copy_cur(){
    int i = blockIdx.x*blockDim.x + threadIdx.x;
    if (i < NN) g_cur[i] = g_offs[i];
}
__global__ void edge_scatter(const int* __restrict__ ei){
    int e = blockIdx.x*blockDim.x + threadIdx.x;
    if (e >= NE) return;
    int s, d;
    if (e < NE0) { s = ei[e]; d = ei[NE0+e]; } else { s = e - NE0; d = s; }
    int pos = atomicAdd(&g_cur[d], 1);
    g_ssrc[pos] = s;
}

// ---------------- GAT ----------------
__global__ void attn_coef(const float* __restrict__ F, const float* __restrict__ a_s,
                          const float* __restrict__ a_d)
{
    int w = (blockIdx.x*blockDim.x + threadIdx.x) >> 5;
    if (w >= NN*3) return;
    int lane = threadIdx.x & 31;
    int node = w / 3, h = w - node*3;
    const float* f = F + (long)node*F3 + h*HE;
    const float* As_ = a_s + h*HE;
    const float* Ad_ = a_d + h*HE;
    float s1 = 0.f, s2 = 0.f;
    #pragma unroll
    for (int c = lane; c < HE; c += 32) { float fv = f[c]; s1 += fv*As_[c]; s2 += fv*Ad_[c]; }
    #pragma unroll
    for (int o = 16; o; o >>= 1) {
        s1 += __shfl_down_sync(0xffffffffu, s1, o);
        s2 += __shfl_down_sync(0xffffffffu, s2, o);
    }
    if (lane == 0) { g_asv[w] = s1; g_adv[w] = s2; }
}

__global__ void gat_agg(const float* __restrict__ F, const float* __restrict__ bias,
                        float* __restrict__ O)
{
    int w = (blockIdx.x*blockDim.x + threadIdx.x) >> 5;
    if (w >= NN) return;
    int lane = threadIdx.x & 31;
    int beg = g_offs[w], end = g_offs[w+1];
    float ad0 = g_adv[w*3], ad1 = g_adv[w*3+1], ad2 = g_adv[w*3+2];
    float m0 = -1e30f, m1 = -1e30f, m2 = -1e30f;
    float d0 = 0.f, d1 = 0.f, d2 = 0.f;
    float acc[12];
    #pragma unroll
    for (int q = 0; q < 12; ++q) acc[q] = 0.f;

    for (int p = beg; p < end; ++p) {
        int s = g_ssrc[p];
        float e0 = g_asv[s*3]   + ad0; e0 = (e0 >= 0.f) ? e0 : 0.2f*e0;
        float e1 = g_asv[s*3+1] + ad1; e1 = (e1 >= 0.f) ? e1 : 0.2f*e1;
        float e2 = g_asv[s*3+2] + ad2; e2 = (e2 >= 0.f) ? e2 : 0.2f*e2;
        const float* f = F + (long)s*F3;
        {
            float nm = fmaxf(m0, e0); float sc = __expf(m0-nm); float wv = __expf(e0-nm);
            d0 = d0*sc + wv;
            #pragma unroll
            for (int q = 0; q < 4; ++q) acc[q] = acc[q]*sc + wv*f[q*32 + lane];
            m0 = nm;
        }
        {
            float nm = fmaxf(m1, e1); float sc = __expf(m1-nm); float wv = __expf(e1-nm);
            d1 = d1*sc + wv;
            #pragma unroll
            for (int q = 0; q < 4; ++q) acc[4+q] = acc[4+q]*sc + wv*f[HE + q*32 + lane];
            m1 = nm;
        }
        {
            float nm = fmaxf(m2, e2); float sc = __expf(m2-nm); float wv = __expf(e2-nm);
            d2 = d2*sc + wv;
            #pragma unroll
            for (int q = 0; q < 4; ++q) acc[8+q] = acc[8+q]*sc + wv*f[2*HE + q*32 + lane];
            m2 = nm;
        }
    }
    float* o = O + (long)w*F3;
    #pragma unroll
    for (int q = 0; q < 4; ++q) {
        int c0 = q*32 + lane;
        o[c0]        = acc[q]  /d0 + bias[c0];
        o[HE + c0]   = acc[4+q]/d1 + bias[HE + c0];
        o[2*HE + c0] = acc[8+q]/d2 + bias[2*HE + c0];
    }
}

// ---------------- batched output head (all timesteps) ----------------
__global__ void out_all(const float* __restrict__ opW, const float* __restrict__ opb,
                        float* __restrict__ out)
{
    long w = (long)(blockIdx.x*blockDim.x + threadIdx.x) >> 5;
    if (w >= (long)OUTL*NT) return;
    int lane = threadIdx.x & 31;
    long t = w / NT, row = w - t*NT;
    const float* h = g_H1ALL + (t*NT + row)*HD;
    float s0 = 0.f, s1 = 0.f;
    #pragma unroll
    for (int k = lane; k < HD; k += 32) {
        float hv = h[k];
        s0 += hv*opW[k*2];
        s1 += hv*opW[k*2+1];
    }
    #pragma unroll
    for (int o = 16; o; o >>= 1) {
        s0 += __shfl_down_sync(0xffffffffu, s0, o);
        s1 += __shfl_down_sync(0xffffffffu, s1, o);
    }
    if (lane == 0) {
        long base = (row*OUTL + t)*2;
        out[base]   = s0 + opb[0];
        out[base+1] = s1 + opb[1];
    }
}

// ---------------- host ----------------
template<int PRE, int ACT>
static inline void mmagemm(const float* A, const __nv_bfloat16* Wh, const __nv_bfloat16* Wl, int K,
                           const float* bias, const int* ridx, float* C, long M, int N)
{
    dim3 g(N/WBN, (unsigned)((M + WBM - 1)/WBM));
    mma_gemm<PRE,ACT><<<g, 256, GEMM_SMEM>>>(A, Wh, Wl, K, bias, ridx, C, (int)M, N);
}

extern "C" void kernel_launch(void* const* d_in, const int* in_sizes, int n_in,
                              void* d_out, int out_size)
{
    const float* x    = (const float*)d_in[0];
    const int*   ei   = (const int*)  d_in[1];
    const int*   tgt  = (const int*)  d_in[2];
    const float* ipW  = (const float*)d_in[3];
    const float* ipb  = (const float*)d_in[4];
    const float* gWx  = (const float*)d_in[5];
    const float* gWh  = (const float*)d_in[6];
    const float* gbx  = (const float*)d_in[7];
    const float* gbh  = (const float*)d_in[8];
    const float* dynW = (const float*)d_in[9];
    const float* dynb = (const float*)d_in[10];
    const float* g1W  = (const float*)d_in[11];
    const float* g1as = (const float*)d_in[12];
    const float* g1ad = (const float*)d_in[13];
    const float* g1b  = (const float*)d_in[14];
    const float* g2W  = (const float*)d_in[15];
    const float* g2as = (const float*)d_in[16];
    const float* g2ad = (const float*)d_in[17];
    const float* g2b  = (const float*)d_in[18];
    const float* fcW  = (const float*)d_in[19];
    const float* fcb  = (const float*)d_in[20];
    const float* l0Wx = (const float*)d_in[21];
    const float* l0Wh = (const float*)d_in[22];
    const float* l0b  = (const float*)d_in[23];
    const float* l1Wx = (const float*)d_in[24];
    const float* l1Wh = (const float*)d_in[25];
    const float* l1b  = (const float*)d_in[26];
    const float* opW  = (const float*)d_in[27];
    const float* opb  = (const float*)d_in[28];
    float* out = (float*)d_out;
    (void)in_sizes; (void)n_in; (void)out_size;

    float *H,*H2,*HENC,*F1,*O1,*F2,*O2,*ENC,*X0,*c0,*c1,*h0a,*h0b,*h1z,*H1ALL;
    float *l0bp,*l1bp;
    __nv_bfloat16 *WTh,*WTl;
    cudaGetSymbolAddress((void**)&H,    g_H);
    cudaGetSymbolAddress((void**)&H2,   g_H2);
    cudaGetSymbolAddress((void**)&HENC, g_HENC);
    cudaGetSymbolAddress((void**)&F1,   g_F1);
    cudaGetSymbolAddress((void**)&O1,   g_O1);
    cudaGetSymbolAddress((void**)&F2,   g_F2);
    cudaGetSymbolAddress((void**)&O2,   g_O2);
    cudaGetSymbolAddress((void**)&ENC,  g_ENC);
    cudaGetSymbolAddress((void**)&X0,   g_X0);
    cudaGetSymbolAddress((void**)&c0,   g_c0);
    cudaGetSymbolAddress((void**)&c1,   g_c1);
    cudaGetSymbolAddress((void**)&h0a,  g_h0a);
    cudaGetSymbolAddress((void**)&h0b,  g_h0b);
    cudaGetSymbolAddress((void**)&h1z,  g_h1z);
    cudaGetSymbolAddress((void**)&H1ALL,g_H1ALL);
    cudaGetSymbolAddress((void**)&l0bp, g_l0bp);
    cudaGetSymbolAddress((void**)&l1bp, g_l1bp);
    cudaGetSymbolAddress((void**)&WTh,  g_WThi);
    cudaGetSymbolAddress((void**)&WTl,  g_WTlo);
    int *cntp;
    cudaGetSymbolAddress((void**)&cntp, g_cnt);

    static int attr_set = 0;
    if (!attr_set) {
        cudaFuncSetAttribute(mma_gemm<0,0>, cudaFuncAttributeMaxDynamicSharedMemorySize, GEMM_SMEM);
        cudaFuncSetAttribute(mma_gemm<0,1>, cudaFuncAttributeMaxDynamicSharedMemorySize, GEMM_SMEM);
        cudaFuncSetAttribute(mma_gemm<1,1>, cudaFuncAttributeMaxDynamicSharedMemorySize, GEMM_SMEM);
        cudaFuncSetAttribute(dec_gemm<0>, cudaFuncAttributeMaxDynamicSharedMemorySize, GEMM_SMEM);
        cudaFuncSetAttribute(dec_gemm<1>, cudaFuncAttributeMaxDynamicSharedMemorySize, GEMM_SMEM);
        attr_set = 1;
    }

    // weight offsets (elements)
    const int o_g1W  = 61440;
    const int o_g2W  = 110592;
    const int o_l0Wx = 258048;
    const int o_l0Wh = 389120;
    const int o_l1   = 651264;
    const int o_dyn  = 1175552;
    const int o_fc   = 1191936;
    const int o_gru  = 1241088;

    // ---- weight prep ----
    zero_f<<<(40960+255)/256,256>>>((float*)(WTh+o_gru), 40960);
    zero_f<<<(40960+255)/256,256>>>((float*)(WTl+o_gru), 40960);
    wscat_gru<<<(128*F3+255)/256,256>>>(gWh, WTh+o_gru, WTl+o_gru, 128, 0,   0);
    wscat_gru<<<(32*F3+255)/256,256>>>(gWx,  WTh+o_gru, WTl+o_gru, 32,  128, 1);
    grub_kernel<<<1,128>>>(gbx, gbh);
    wsplitp<<<(128*384+255)/256,256>>>(g1W,  WTh+o_g1W,  WTl+o_g1W,  128, 384, 1, 128, 0);
    wsplitp<<<(384*384+255)/256,256>>>(g2W,  WTh+o_g2W,  WTl+o_g2W,  384, 384, 1, 384, 0);
    wsplitp<<<(128*1024+255)/256,256>>>(l0Wx, WTh+o_l0Wx, WTl+o_l0Wx, 128, 1024, 4, 128, 0);
    wsplitp<<<(256*1024+255)/256,256>>>(l0Wh, WTh+o_l0Wh, WTl+o_l0Wh, 256, 1024, 4, 256, 0);
    wsplitp<<<(256*1024+255)/256,256>>>(l1Wx, WTh+o_l1,   WTl+o_l1,   256, 1024, 4, 512, 0);
    wsplitp<<<(256*1024+255)/256,256>>>(l1Wh, WTh+o_l1,   WTl+o_l1,   256, 1024, 4, 512, 256);
    wsplitp<<<(128*128+255)/256,256>>>(dynW, WTh+o_dyn,  WTl+o_dyn,  128, 128, 1, 128, 0);
    wsplitp<<<(384*128+255)/256,256>>>(fcW,  WTh+o_fc,   WTl+o_fc,   384, 128, 1, 384, 0);
    bperm<<<4,256>>>(l0b, l0bp, 1024, 4);
    bperm<<<4,256>>>(l1b, l1bp, 1024, 4);

    // ---- CSR build ----
    zero_i<<<(NN+255)/256,256>>>(cntp, NN);
    edge_count<<<(NE+255)/256,256>>>(ei);
    scan_kernel<<<1,1024>>>();
    copy_cur<<<(NN+255)/256,256>>>();
    edge_scatter<<<(NE+255)/256,256>>>(ei);

    // ---- encoder ----
    emb_kernel<<<(int)(((long)NN*TT*DE + 255)/256),256>>>(x, ipW, ipb);
    zero_f<<<(int)(((long)NN*HE + 255)/256),256>>>(H, (long)NN*HE);
    {
        dim3 gg(8, (NN+127)/128);
        for (int t = 0; t < TT; ++t) {
            const float* hin  = (t & 1) ? H2 : H;
            float*       hout = (t & 1) ? H  : H2;
            gru_step2<<<gg, 256, GRU_SMEM2>>>(hin, WTh+o_gru, WTl+o_gru, hout, t);
        }
    }

    // hist_enc
    mmagemm<1,1>(H, WTh+o_dyn, WTl+o_dyn, HE, dynb, nullptr, HENC, NN, HE);

    // ---- GAT layer 1 ----
    mmagemm<0,0>(HENC, WTh+o_g1W, WTl+o_g1W, HE, nullptr, nullptr, F1, NN, F3);
    attn_coef<<<(NN*3*32+255)/256,256>>>(F1, g1as, g1ad);
    gat_agg<<<(NN*32+255)/256,256>>>(F1, g1b, O1);

    // ---- GAT layer 2 ----
    mmagemm<0,0>(O1, WTh+o_g2W, WTl+o_g2W, F3, nullptr, nullptr, F2, NN, F3);
    attn_coef<<<(NN*3*32+255)/256,256>>>(F2, g2as, g2ad);
    gat_agg<<<(NN*32+255)/256,256>>>(F2, g2b, O2);

    // ---- target gather + fc + X0 ----
    mmagemm<0,1>(O2, WTh+o_fc, WTl+o_fc, F3, fcb, tgt, ENC, NT, HE);
    mmagemm<0,0>(ENC, WTh+o_l0Wx, WTl+o_l0Wx, HE, l0bp, nullptr, X0, NT, 4*HD);
    zero_f<<<((NT*HD)+255)/256,256>>>(h0a, (long)NT*HD);
    zero_f<<<((NT*HD)+255)/256,256>>>(h1z, (long)NT*HD);

    // ---- decoder: h1 written per-step into H1ALL; single out kernel at end ----
    {
        dim3 gd(16, (NT+127)/128);
        for (int t = 0; t < OUTL; ++t) {
            float* h0in  = (t & 1) ? h0b : h0a;
            float* h0out = (t & 1) ? h0a : h0b;
            const float* h1in = (t == 0) ? h1z : (H1ALL + (long)(t-1)*NT*HD);
            float* h1out = H1ALL + (long)t*NT*HD;
            dec_gemm<0><<<gd, 256, GEMM_SMEM>>>(h0in, nullptr, WTh+o_l0Wh, WTl+o_l0Wh,
                                                X0, c0, h0out, t == 0);
            dec_gemm<1><<<gd, 256, GEMM_SMEM>>>(h0out, h1in, WTh+o_l1, WTl+o_l1,
                                                l1bp, c1, h1out, t == 0);
        }
        out_all<<<((long)OUTL*NT*32 + 255)/256, 256>>>(opW, opb, out);
    }
}

// round 16
// speedup vs baseline: 1.2239x; 1.0053x over previous
#include <cuda_runtime.h>
#include <cuda_bf16.h>
#include <mma.h>
#include <math.h>
#include <stdint.h>

using namespace nvcuda;

#define NN   30000
#define TT   16
#define DE   32
#define HE   128
#define F3   384
#define NE0  300000
#define NE   330000
#define NT   3000
#define HD   256
#define OUTL 25

// ---------------- scratch ----------------
__device__ __align__(256) float g_EMB[NN*TT*DE];
__device__ __align__(256) float g_H[NN*HE];
__device__ __align__(256) float g_H2[NN*HE];
__device__ __align__(256) float g_HENC[NN*HE];
__device__ __align__(256) float g_F1[NN*F3];
__device__ __align__(256) float g_O1[NN*F3];
__device__ __align__(256) float g_F2[NN*F3];
__device__ __align__(256) float g_O2[NN*F3];
__device__ __align__(256) float g_asv[NN*3];
__device__ __align__(256) float g_adv[NN*3];
__device__ __align__(256) float g_ENC[NT*HE];
__device__ __align__(256) float g_X0[NT*4*HD];
__device__ __align__(256) float g_c0[NT*HD];
__device__ __align__(256) float g_c1[NT*HD];
__device__ __align__(256) float g_h0a[NT*HD];
__device__ __align__(256) float g_h0b[NT*HD];
__device__ __align__(256) float g_h1z[NT*HD];
__device__ __align__(256) float g_H1ALL[(long)OUTL*NT*HD];
__device__ int g_cnt[NN];
__device__ int g_offs[NN+1];
__device__ int g_cur[NN];
__device__ int g_ssrc[NE];
__device__ float g_grub[512];
__device__ float g_l0bp[4*HD];
__device__ float g_l1bp[4*HD];
#define WT_TOTAL 1330000
__device__ __align__(256) __nv_bfloat16 g_WThi[WT_TOTAL];
__device__ __align__(256) __nv_bfloat16 g_WTlo[WT_TOTAL];

// weight offsets (elements)
#define O_G1W  61440
#define O_G2W  110592
#define O_L0WX 258048
#define O_L0WH 389120
#define O_L1   651264
#define O_DYN  1175552
#define O_FC   1191936
#define O_GRU  1241088

__device__ __forceinline__ float sigf(float x){ return 1.f/(1.f+__expf(-x)); }
__device__ __forceinline__ float lk01(float x){ return x>=0.f? x : 0.1f*x; }

// ---------------- fused zero (cnt, H, h0a, h1z) ----------------
#define ZT ((long)NN + (long)NN*HE + 2L*NT*HD)
__global__ void zero_all(){
    long i = (long)blockIdx.x*blockDim.x + threadIdx.x;
    if (i < NN) { g_cnt[i] = 0; return; }
    i -= NN;
    if (i < (long)NN*HE) { g_H[i] = 0.f; return; }
    i -= (long)NN*HE;
    if (i < (long)NT*HD) { g_h0a[i] = 0.f; return; }
    i -= (long)NT*HD;
    if (i < (long)NT*HD) { g_h1z[i] = 0.f; return; }
}

// ---------------- fused weight prep ----------------
__device__ __forceinline__ void wsp_one(const float* __restrict__ W, long idx,
                                        int N, int P, int ldk, int kofs, long base)
{
    int k = (int)(idx / N), n = (int)(idx - (long)k*N);
    int Gp = N / P;
    int np = (n % Gp)*P + n/Gp;
    float v = W[idx];
    __nv_bfloat16 h = __float2bfloat16(v);
    long o = base + (long)np*ldk + kofs + k;
    g_WThi[o] = h;
    g_WTlo[o] = __float2bfloat16(v - __bfloat162float(h));
}

__device__ __forceinline__ void wscat_one(const float* __restrict__ W, long idx,
                                          int kbase, int mode)
{
    int k = (int)(idx / F3), n = (int)(idx - (long)k*F3);
    int g = n / HE, j = n - g*HE;
    int cp = 4*j + ((g < 2) ? g : (mode ? 3 : 2));
    float v = W[idx];
    __nv_bfloat16 h = __float2bfloat16(v);
    long o = O_GRU + (long)cp*160 + kbase + k;
    g_WThi[o] = h;
    g_WTlo[o] = __float2bfloat16(v - __bfloat162float(h));
}

// segment sizes
#define SZ_ZC   20480L     // zero complement of GRU pack
#define SZ_S1   49152L     // wscat gWh
#define SZ_S2   12288L     // wscat gWx
#define SZ_W1   49152L     // g1W
#define SZ_W2   147456L    // g2W
#define SZ_W3   131072L    // l0Wx
#define SZ_W4   262144L    // l0Wh
#define SZ_W5   262144L    // l1Wx
#define SZ_W6   262144L    // l1Wh
#define SZ_W7   16384L     // dynW
#define SZ_W8   49152L     // fcW
#define SZ_B1   1024L      // l0b
#define SZ_B2   1024L      // l1b
#define SZ_G    128L       // grub
#define PREP_TOTAL (SZ_ZC+SZ_S1+SZ_S2+SZ_W1+SZ_W2+SZ_W3+SZ_W4+SZ_W5+SZ_W6+SZ_W7+SZ_W8+SZ_B1+SZ_B2+SZ_G)

__global__ void prep_all(const float* __restrict__ gWx, const float* __restrict__ gWh,
                         const float* __restrict__ gbx, const float* __restrict__ gbh,
                         const float* __restrict__ g1W, const float* __restrict__ g2W,
                         const float* __restrict__ l0Wx, const float* __restrict__ l0Wh,
                         const float* __restrict__ l1Wx, const float* __restrict__ l1Wh,
                         const float* __restrict__ dynW, const float* __restrict__ fcW,
                         const float* __restrict__ l0b, const float* __restrict__ l1b)
{
    long r = (long)blockIdx.x*blockDim.x + threadIdx.x;
    if (r >= PREP_TOTAL) return;
    if (r < SZ_ZC) {
        // zero the GRU-pack entries not written by wscat:
        // col 4j+2 (gh_n): k in [128,160); col 4j+3 (gx_n): k in [0,128)
        int j = (int)(r / 160), q = (int)(r % 160);
        int cp, k;
        if (q < 32) { cp = 4*j + 2; k = 128 + q; }
        else        { cp = 4*j + 3; k = q - 32; }
        long o = O_GRU + (long)cp*160 + k;
        __nv_bfloat16 z = __float2bfloat16(0.f);
        g_WThi[o] = z; g_WTlo[o] = z;
        return;
    }
    r -= SZ_ZC;
    if (r < SZ_S1) { wscat_one(gWh, r, 0, 0); return; }
    r -= SZ_S1;
    if (r < SZ_S2) { wscat_one(gWx, r, 128, 1); return; }
    r -= SZ_S2;
    if (r < SZ_W1) { wsp_one(g1W,  r, 384, 1, 128, 0, O_G1W); return; }
    r -= SZ_W1;
    if (r < SZ_W2) { wsp_one(g2W,  r, 384, 1, 384, 0, O_G2W); return; }
    r -= SZ_W2;
    if (r < SZ_W3) { wsp_one(l0Wx, r, 1024, 4, 128, 0, O_L0WX); return; }
    r -= SZ_W3;
    if (r < SZ_W4) { wsp_one(l0Wh, r, 1024, 4, 256, 0, O_L0WH); return; }
    r -= SZ_W4;
    if (r < SZ_W5) { wsp_one(l1Wx, r, 1024, 4, 512, 0, O_L1); return; }
    r -= SZ_W5;
    if (r < SZ_W6) { wsp_one(l1Wh, r, 1024, 4, 512, 256, O_L1); return; }
    r -= SZ_W6;
    if (r < SZ_W7) { wsp_one(dynW, r, 128, 1, 128, 0, O_DYN); return; }
    r -= SZ_W7;
    if (r < SZ_W8) { wsp_one(fcW,  r, 128, 1, 384, 0, O_FC); return; }
    r -= SZ_W8;
    if (r < SZ_B1) { int n = (int)r; g_l0bp[(n % 256)*4 + n/256] = l0b[n]; return; }
    r -= SZ_B1;
    if (r < SZ_B2) { int n = (int)r; g_l1bp[(n % 256)*4 + n/256] = l1b[n]; return; }
    r -= SZ_B2;
    {
        int j = (int)r;
        g_grub[4*j+0] = gbx[j]       + gbh[j];
        g_grub[4*j+1] = gbx[HE+j]    + gbh[HE+j];
        g_grub[4*j+2] = gbh[2*HE+j];
        g_grub[4*j+3] = gbx[2*HE+j];
    }
}

typedef wmma::fragment<wmma::matrix_a, 16,16,16, __nv_bfloat16, wmma::row_major> FragA;
typedef wmma::fragment<wmma::matrix_b, 16,16,16, __nv_bfloat16, wmma::col_major> FragB;
typedef wmma::fragment<wmma::accumulator, 16,16,16, float> FragC;

#define WBM 128
#define WBN 64
#define SKA2 72
#define SKB2 72
#define GEMM_SMEM 55296
#define SKA 40
#define SKB 40
#define GRU_SMEM2 36864

__device__ __forceinline__ void splitstore_a(__nv_bfloat16* Ah, __nv_bfloat16* Al,
                                             int o, float4 v)
{
    __nv_bfloat16 hx = __float2bfloat16(v.x);
    __nv_bfloat16 hy = __float2bfloat16(v.y);
    __nv_bfloat16 hz = __float2bfloat16(v.z);
    __nv_bfloat16 hw = __float2bfloat16(v.w);
    Ah[o]   = hx; Ah[o+1] = hy; Ah[o+2] = hz; Ah[o+3] = hw;
    Al[o]   = __float2bfloat16(v.x - __bfloat162float(hx));
    Al[o+1] = __float2bfloat16(v.y - __bfloat162float(hy));
    Al[o+2] = __float2bfloat16(v.z - __bfloat162float(hz));
    Al[o+3] = __float2bfloat16(v.w - __bfloat162float(hw));
}

// ---------------- generic WMMA bf16x3 GEMM (BK=64, register-prefetch) ----------------
template<int PRE, int ACT>
__global__ void __launch_bounds__(256,2)
mma_gemm(const float* __restrict__ A1, const __nv_bfloat16* __restrict__ W1h,
         const __nv_bfloat16* __restrict__ W1l, int K1,
         const float* __restrict__ bias, const int* __restrict__ rowidx,
         float* __restrict__ C, int M, int N)
{
    extern __shared__ char smc[];
    __nv_bfloat16* Ah = (__nv_bfloat16*)smc;
    __nv_bfloat16* Al = Ah + WBM*SKA2;
    __nv_bfloat16* Bh = Al + WBM*SKA2;
    __nv_bfloat16* Bl = Bh + WBN*SKB2;
    float* Cs = (float*)smc;

    const int tid = threadIdx.x, wid = tid >> 5;
    const int warp_m = wid >> 1, warp_n = wid & 1;
    const long bm = (long)blockIdx.y * WBM;
    const int bn = blockIdx.x * WBN;

    const int ra0 = tid >> 4, ca = (tid & 15) << 2;
    const int rb0 = tid >> 3, cbb = (tid & 7) << 3;
    long arow[8];
    #pragma unroll
    for (int i = 0; i < 8; ++i) {
        long row = bm + ra0 + 16*i;
        arow[i] = (row < M) ? (rowidx ? (long)rowidx[row] : row) : -1;
    }

    FragC acc[2][2];
    #pragma unroll
    for (int mm = 0; mm < 2; ++mm)
        #pragma unroll
        for (int nn = 0; nn < 2; ++nn)
            wmma::fill_fragment(acc[mm][nn], 0.f);

    float4 va[8];
    uint4 vbh[2], vbl[2];
    #pragma unroll
    for (int i = 0; i < 8; ++i) {
        va[i] = make_float4(0.f,0.f,0.f,0.f);
        if (arow[i] >= 0) va[i] = *(const float4*)(A1 + arow[i]*K1 + ca);
    }
    #pragma unroll
    for (int i = 0; i < 2; ++i) {
        long go = (long)(bn + rb0 + 32*i)*K1 + cbb;
        vbh[i] = *(const uint4*)(W1h + go);
        vbl[i] = *(const uint4*)(W1l + go);
    }

    for (int k0 = 0; k0 < K1; k0 += 64) {
        #pragma unroll
        for (int i = 0; i < 8; ++i) {
            float4 v = va[i];
            if (PRE) { v.x=lk01(v.x); v.y=lk01(v.y); v.z=lk01(v.z); v.w=lk01(v.w); }
            splitstore_a(Ah, Al, (ra0 + 16*i)*SKA2 + ca, v);
        }
        #pragma unroll
        for (int i = 0; i < 2; ++i) {
            *(uint4*)&Bh[(rb0 + 32*i)*SKB2 + cbb] = vbh[i];
            *(uint4*)&Bl[(rb0 + 32*i)*SKB2 + cbb] = vbl[i];
        }
        __syncthreads();

        const int kn = k0 + 64;
        if (kn < K1) {
            #pragma unroll
            for (int i = 0; i < 8; ++i) {
                va[i] = make_float4(0.f,0.f,0.f,0.f);
                if (arow[i] >= 0) va[i] = *(const float4*)(A1 + arow[i]*K1 + kn + ca);
            }
            #pragma unroll
            for (int i = 0; i < 2; ++i) {
                long go = (long)(bn + rb0 + 32*i)*K1 + kn + cbb;
                vbh[i] = *(const uint4*)(W1h + go);
                vbl[i] = *(const uint4*)(W1l + go);
            }
        }

        #pragma unroll
        for (int kk = 0; kk < 64; kk += 16) {
            FragA ah[2], al[2];
            FragB bh[2], bl[2];
            #pragma unroll
            for (int mm = 0; mm < 2; ++mm) {
                int ro = (warp_m*32 + mm*16)*SKA2 + kk;
                wmma::load_matrix_sync(ah[mm], Ah + ro, SKA2);
                wmma::load_matrix_sync(al[mm], Al + ro, SKA2);
            }
            #pragma unroll
            for (int nn = 0; nn < 2; ++nn) {
                int no = (warp_n*32 + nn*16)*SKB2 + kk;
                wmma::load_matrix_sync(bh[nn], Bh + no, SKB2);
                wmma::load_matrix_sync(bl[nn], Bl + no, SKB2);
            }
            #pragma unroll
            for (int mm = 0; mm < 2; ++mm)
                #pragma unroll
                for (int nn = 0; nn < 2; ++nn) {
                    wmma::mma_sync(acc[mm][nn], ah[mm], bh[nn], acc[mm][nn]);
                    wmma::mma_sync(acc[mm][nn], ah[mm], bl[nn], acc[mm][nn]);
                    wmma::mma_sync(acc[mm][nn], al[mm], bh[nn], acc[mm][nn]);
                }
        }
        __syncthreads();
    }

    #pragma unroll
    for (int mm = 0; mm < 2; ++mm)
        #pragma unroll
        for (int nn = 0; nn < 2; ++nn)
            wmma::store_matrix_sync(Cs + (warp_m*32 + mm*16)*68 + warp_n*32 + nn*16,
                                    acc[mm][nn], 68, wmma::mem_row_major);
    __syncthreads();

    #pragma unroll
    for (int i = 0; i < 8; ++i) {
        int li = tid + (i << 8);
        int r = li >> 4, c = (li & 15) << 2;
        long row = bm + r;
        if (row >= M) continue;
        float4 v = *(float4*)&Cs[r*68 + c];
        int col = bn + c;
        if (bias) {
            float4 bb = *(const float4*)(bias + col);
            v.x += bb.x; v.y += bb.y; v.z += bb.z; v.w += bb.w;
        }
        if (ACT) { v.x=lk01(v.x); v.y=lk01(v.y); v.z=lk01(v.z); v.w=lk01(v.w); }
        *(float4*)(C + row*(long)N + col) = v;
    }
}

// ---------------- GRU step (BK=32 pipelined, K=160), fused gates ----------------
__global__ void __launch_bounds__(256,2)
gru_step2(const float* __restrict__ Hin, const __nv_bfloat16* __restrict__ Wh,
          const __nv_bfloat16* __restrict__ Wl, float* __restrict__ Hout, int t)
{
    extern __shared__ char sm[];
    __nv_bfloat16* Ah = (__nv_bfloat16*)sm;
    __nv_bfloat16* Al = Ah + 128*SKA;
    __nv_bfloat16* Bh = Al + 128*SKA;
    __nv_bfloat16* Bl = Bh + 64*SKB;
    float* Cs = (float*)sm;

    const int tid = threadIdx.x, wid = tid >> 5;
    const int warp_m = wid >> 1, warp_n = wid & 1;
    const long bm = (long)blockIdx.y * 128;
    const int bn = blockIdx.x * 64;

    const int ra0 = tid >> 3, ca = (tid & 7) << 2;
    const int rb  = tid >> 2, cb = (tid & 3) << 3;
    long nodei[4];
    #pragma unroll
    for (int i = 0; i < 4; ++i) {
        long node = bm + ra0 + 32*i;
        nodei[i] = (node < NN) ? node : -1;
    }

    FragC acc[2][2];
    #pragma unroll
    for (int mm = 0; mm < 2; ++mm)
        #pragma unroll
        for (int nn = 0; nn < 2; ++nn)
            wmma::fill_fragment(acc[mm][nn], 0.f);

    float4 va[4];
    uint4 vbh, vbl;
    #pragma unroll
    for (int i = 0; i < 4; ++i) {
        va[i] = make_float4(0.f,0.f,0.f,0.f);
        if (nodei[i] >= 0) va[i] = *(const float4*)(Hin + nodei[i]*HE + ca);
    }
    {
        long go = (long)(bn + rb)*160 + cb;
        vbh = *(const uint4*)(Wh + go);
        vbl = *(const uint4*)(Wl + go);
    }

    #pragma unroll
    for (int ch = 0; ch < 5; ++ch) {
        #pragma unroll
        for (int i = 0; i < 4; ++i)
            splitstore_a(Ah, Al, (ra0 + 32*i)*SKA + ca, va[i]);
        *(uint4*)&Bh[rb*SKB + cb] = vbh;
        *(uint4*)&Bl[rb*SKB + cb] = vbl;
        __syncthreads();

        if (ch + 1 < 5) {
            const int cn = ch + 1;
            #pragma unroll
            for (int i = 0; i < 4; ++i) {
                va[i] = make_float4(0.f,0.f,0.f,0.f);
                if (nodei[i] >= 0) {
                    if (cn < 4) va[i] = *(const float4*)(Hin + nodei[i]*HE + (cn<<5) + ca);
                    else        va[i] = *(const float4*)(g_EMB + (nodei[i]*TT + t)*DE + ca);
                }
            }
            long go = (long)(bn + rb)*160 + (cn<<5) + cb;
            vbh = *(const uint4*)(Wh + go);
            vbl = *(const uint4*)(Wl + go);
        }

        #pragma unroll
        for (int kk = 0; kk < 32; kk += 16) {
            FragA ah[2], al[2];
            FragB bh[2], bl[2];
            #pragma unroll
            for (int mm = 0; mm < 2; ++mm) {
                int ro = (warp_m*32 + mm*16)*SKA + kk;
                wmma::load_matrix_sync(ah[mm], Ah + ro, SKA);
                wmma::load_matrix_sync(al[mm], Al + ro, SKA);
            }
            #pragma unroll
            for (int nn = 0; nn < 2; ++nn) {
                int no = (warp_n*32 + nn*16)*SKB + kk;
                wmma::load_matrix_sync(bh[nn], Bh + no, SKB);
                wmma::load_matrix_sync(bl[nn], Bl + no, SKB);
            }
            #pragma unroll
            for (int mm = 0; mm < 2; ++mm)
                #pragma unroll
                for (int nn = 0; nn < 2; ++nn) {
                    wmma::mma_sync(acc[mm][nn], ah[mm], bh[nn], acc[mm][nn]);
                    wmma::mma_sync(acc[mm][nn], ah[mm], bl[nn], acc[mm][nn]);
                    wmma::mma_sync(acc[mm][nn], al[mm], bh[nn], acc[mm][nn]);
                }
        }
        __syncthreads();
    }

    #pragma unroll
    for (int mm = 0; mm < 2; ++mm)
        #pragma unroll
        for (int nn = 0; nn < 2; ++nn)
            wmma::store_matrix_sync(Cs + (warp_m*32 + mm*16)*68 + warp_n*32 + nn*16,
                                    acc[mm][nn], 68, wmma::mem_row_major);
    __syncthreads();

    #pragma unroll
    for (int i = 0; i < 8; ++i) {
        int li = tid + (i << 8);
        int r = li >> 4, q = li & 15;
        long node = bm + r;
        if (node < NN) {
            int j = blockIdx.x*16 + q;
            const float* gs = Cs + r*68 + 4*q;
            float rr  = sigf(gs[0] + g_grub[4*j+0]);
            float zz  = sigf(gs[1] + g_grub[4*j+1]);
            float ghn = gs[2] + g_grub[4*j+2];
            float gxn = gs[3] + g_grub[4*j+3];
            float nn2 = tanhf(gxn + rr*ghn);
            float hold = Hin[node*HE + j];
            Hout[node*HE + j] = (1.f - zz)*nn2 + zz*hold;
        }
    }
}

// ---------------- decoder step GEMM (BK=64 pipelined) with fused LSTM gates ----------------
template<int L1>
__global__ void __launch_bounds__(256,2)
dec_gemm(const float* __restrict__ A1, const float* __restrict__ A2,
         const __nv_bfloat16* __restrict__ Wh, const __nv_bfloat16* __restrict__ Wl,
         const float* __restrict__ pre, float* __restrict__ cbuf,
         float* __restrict__ hout, int first)
{
    extern __shared__ char sm[];
    __nv_bfloat16* Ah = (__nv_bfloat16*)sm;
    __nv_bfloat16* Al = Ah + WBM*SKA2;
    __nv_bfloat16* Bh = Al + WBM*SKA2;
    __nv_bfloat16* Bl = Bh + WBN*SKB2;
    float* Cs = (float*)sm;

    const int tid = threadIdx.x, wid = tid >> 5;
    const int warp_m = wid >> 1, warp_n = wid & 1;
    const long bm = (long)blockIdx.y * WBM;
    const int bn = blockIdx.x * WBN;
    const int KTOT = L1 ? 2*HD : HD;

    const int ra0 = tid >> 4, ca = (tid & 15) << 2;
    const int rb0 = tid >> 3, cbb = (tid & 7) << 3;
    long rowi[8];
    #pragma unroll
    for (int i = 0; i < 8; ++i) {
        long row = bm + ra0 + 16*i;
        rowi[i] = (row < NT) ? row : -1;
    }

    FragC acc[2][2];
    #pragma unroll
    for (int mm = 0; mm < 2; ++mm)
        #pragma unroll
        for (int nn = 0; nn < 2; ++nn)
            wmma::fill_fragment(acc[mm][nn], 0.f);

    float4 va[8];
    uint4 vbh[2], vbl[2];
    #pragma unroll
    for (int i = 0; i < 8; ++i) {
        va[i] = make_float4(0.f,0.f,0.f,0.f);
        if (rowi[i] >= 0) va[i] = *(const float4*)(A1 + rowi[i]*HD + ca);
    }
    #pragma unroll
    for (int i = 0; i < 2; ++i) {
        long go = (long)(bn + rb0 + 32*i)*KTOT + cbb;
        vbh[i] = *(const uint4*)(Wh + go);
        vbl[i] = *(const uint4*)(Wl + go);
    }

    for (int k0 = 0; k0 < KTOT; k0 += 64) {
        #pragma unroll
        for (int i = 0; i < 8; ++i)
            splitstore_a(Ah, Al, (ra0 + 16*i)*SKA2 + ca, va[i]);
        #pragma unroll
        for (int i = 0; i < 2; ++i) {
            *(uint4*)&Bh[(rb0 + 32*i)*SKB2 + cbb] = vbh[i];
            *(uint4*)&Bl[(rb0 + 32*i)*SKB2 + cbb] = vbl[i];
        }
        __syncthreads();

        const int kn = k0 + 64;
        if (kn < KTOT) {
            const float* A = (L1 && kn >= HD) ? A2 : A1;
            const int ka = kn & (HD-1);
            #pragma unroll
            for (int i = 0; i < 8; ++i) {
                va[i] = make_float4(0.f,0.f,0.f,0.f);
                if (rowi[i] >= 0) va[i] = *(const float4*)(A + rowi[i]*HD + ka + ca);
            }
            #pragma unroll
            for (int i = 0; i < 2; ++i) {
                long go = (long)(bn + rb0 + 32*i)*KTOT + kn + cbb;
                vbh[i] = *(const uint4*)(Wh + go);
                vbl[i] = *(const uint4*)(Wl + go);
            }
        }

        #pragma unroll
        for (int kk = 0; kk < 64; kk += 16) {
            FragA ah[2], al[2];
            FragB bh[2], bl[2];
            #pragma unroll
            for (int mm = 0; mm < 2; ++mm) {
                int ro = (warp_m*32 + mm*16)*SKA2 + kk;
                wmma::load_matrix_sync(ah[mm], Ah + ro, SKA2);
                wmma::load_matrix_sync(al[mm], Al + ro, SKA2);
            }
            #pragma unroll
            for (int nn = 0; nn < 2; ++nn) {
                int no = (warp_n*32 + nn*16)*SKB2 + kk;
                wmma::load_matrix_sync(bh[nn], Bh + no, SKB2);
                wmma::load_matrix_sync(bl[nn], Bl + no, SKB2);
            }
            #pragma unroll
            for (int mm = 0; mm < 2; ++mm)
                #pragma unroll
                for (int nn = 0; nn < 2; ++nn) {
                    wmma::mma_sync(acc[mm][nn], ah[mm], bh[nn], acc[mm][nn]);
                    wmma::mma_sync(acc[mm][nn], ah[mm], bl[nn], acc[mm][nn]);
                    wmma::mma_sync(acc[mm][nn], al[mm], bh[nn], acc[mm][nn]);
                }
        }
        __syncthreads();
    }

    #pragma unroll
    for (int mm = 0; mm < 2; ++mm)
        #pragma unroll
        for (int nn = 0; nn < 2; ++nn)
            wmma::store_matrix_sync(Cs + (warp_m*32 + mm*16)*68 + warp_n*32 + nn*16,
                                    acc[mm][nn], 68, wmma::mem_row_major);
    __syncthreads();

    #pragma unroll
    for (int i = 0; i < 8; ++i) {
        int li = tid + (i << 8);
        int r = li >> 4, q = li & 15;
        long row = bm + r;
        if (row < NT) {
            int j = blockIdx.x*16 + q;
            const float* gs = Cs + r*68 + 4*q;
            const float* pp = L1 ? (pre + bn + 4*q) : (pre + row*(4*HD) + bn + 4*q);
            float ig = sigf(gs[0] + pp[0]);
            float fg = sigf(gs[1] + pp[1]);
            float gg = tanhf(gs[2] + pp[2]);
            float og = sigf(gs[3] + pp[3]);
            float c = first ? 0.f : cbuf[row*HD + j];
            c = fg*c + ig*gg;
            cbuf[row*HD + j] = c;
            hout[row*HD + j] = og*tanhf(c);
        }
    }
}

// ---------------- encoder embedding ----------------
__global__ void emb_kernel(const float* __restrict__ x, const float* __restrict__ ipW,
                           const float* __restrict__ ipb)
{
    long i = (long)blockIdx.x*blockDim.x + threadIdx.x;
    if (i >= (long)NN*TT*DE) return;
    long row = i >> 5; int j = (int)(i & 31);
    float v = x[row*2]*ipW[j] + x[row*2+1]*ipW[DE+j] + ipb[j];
    g_EMB[i] = lk01(v);
}

// ---------------- CSR build ----------------
__global__ void edge_count(const int* __restrict__ ei){
    int e = blockIdx.x*blockDim.x + threadIdx.x;
    if (e >= NE) return;
    int d = (e < NE0) ? ei[NE0+e] : (e - NE0);
    atomicAdd(&g_cnt[d], 1);
}
__global__ void scan_kernel(){
    __shared__ int sh[1024];
    __shared__ int run;
    int tid = threadIdx.x;
    if (tid == 0) run = 0;
    __syncthreads();
    for (int base = 0; base < NN; base += 1024) {
        int v = (base + tid < NN) ? g_cnt[base + tid] : 0;
        sh[tid] = v; __syncthreads();
        for (int off = 1; off < 1024; off <<= 1) {
            int tv = (tid >= off) ? sh[tid-off] : 0;
            __syncthreads();
            sh[tid] += tv;
            __syncthreads();
        }
        if (base + tid < NN) {
            int val = run + sh[tid];
            g_offs[base + tid + 1] = val;
            if (base + tid + 1 < NN) g_cur[base + tid + 1] = val;
        }
        __syncthreads();
        if (tid == 0) run += sh[1023];
        __syncthreads();
    }
    if (tid == 0) { g_offs[0] = 0; g_cur[0] = 0; }
}
__global__ void edge_scatter(const int* __restrict__ ei){
    int e = blockIdx.x*blockDim.x + threadIdx.x;
    if (e >= NE) return;
    int s, d;
    if (e < NE0) { s = ei[e]; d = ei[NE0+e]; } else { s = e - NE0; d = s; }
    int pos = atomicAdd(&g_cur[d], 1);
    g_ssrc[pos] = s;
}

// ---------------- GAT ----------------
__global__ void attn_coef(const float* __restrict__ F, const float* __restrict__ a_s,
                          const float* __restrict__ a_d)
{
    int w = (blockIdx.x*blockDim.x + threadIdx.x) >> 5;
    if (w >= NN*3) return;
    int lane = threadIdx.x & 31;
    int node = w / 3, h = w - node*3;
    const float* f = F + (long)node*F3 + h*HE;
    const float* As_ = a_s + h*HE;
    const float* Ad_ = a_d + h*HE;
    float s1 = 0.f, s2 = 0.f;
    #pragma unroll
    for (int c = lane; c < HE; c += 32) { float fv = f[c]; s1 += fv*As_[c]; s2 += fv*Ad_[c]; }
    #pragma unroll
    for (int o = 16; o; o >>= 1) {
        s1 += __shfl_down_sync(0xffffffffu, s1, o);
        s2 += __shfl_down_sync(0xffffffffu, s2, o);
    }
    if (lane == 0) { g_asv[w] = s1; g_adv[w] = s2; }
}

// one warp per dst node; edge prefetch pipeline hides ssrc->asv load chain
__global__ void gat_agg(const float* __restrict__ F, const float* __restrict__ bias,
                        float* __restrict__ O)
{
    int w = (blockIdx.x*blockDim.x + threadIdx.x) >> 5;
    if (w >= NN) return;
    int lane = threadIdx.x & 31;
    int beg = g_offs[w], end = g_offs[w+1];
    float ad0 = g_adv[w*3], ad1 = g_adv[w*3+1], ad2 = g_adv[w*3+2];
    float m0 = -1e30f, m1 = -1e30f, m2 = -1e30f;
    float d0 = 0.f, d1 = 0.f, d2 = 0.f;
    float acc[12];
    #pragma unroll
    for (int q = 0; q < 12; ++q) acc[q] = 0.f;

    int s_nx = 0; float b0 = 0.f, b1 = 0.f, b2 = 0.f;
    if (beg < end) {
        s_nx = g_ssrc[beg];
        b0 = g_asv[s_nx*3]; b1 = g_asv[s_nx*3+1]; b2 = g_asv[s_nx*3+2];
    }

    for (int p = beg; p < end; ++p) {
        int s = s_nx;
        float e0 = b0 + ad0, e1 = b1 + ad1, e2 = b2 + ad2;
        if (p + 1 < end) {
            s_nx = g_ssrc[p+1];
            b0 = g_asv[s_nx*3]; b1 = g_asv[s_nx*3+1]; b2 = g_asv[s_nx*3+2];
        }
        e0 = (e0 >= 0.f) ? e0 : 0.2f*e0;
        e1 = (e1 >= 0.f) ? e1 : 0.2f*e1;
        e2 = (e2 >= 0.f) ? e2 : 0.2f*e2;
        const float* f = F + (long)s*F3;
        {
            float nm = fmaxf(m0, e0); float sc = __expf(m0-nm); float wv = __expf(e0-nm);
            d0 = d0*sc + wv;
            #pragma unroll
            for (int q = 0; q < 4; ++q) acc[q] = acc[q]*sc + wv*f[q*32 + lane];
            m0 = nm;
        }
        {
            float nm = fmaxf(m1, e1); float sc = __expf(m1-nm); float wv = __expf(e1-nm);
            d1 = d1*sc + wv;
            #pragma unroll
            for (int q = 0; q < 4; ++q) acc[4+q] = acc[4+q]*sc + wv*f[HE + q*32 + lane];
            m1 = nm;
        }
        {
            float nm = fmaxf(m2, e2); float sc = __expf(m2-nm); float wv = __expf(e2-nm);
            d2 = d2*sc + wv;
            #pragma unroll
            for (int q = 0; q < 4; ++q) acc[8+q] = acc[8+q]*sc + wv*f[2*HE + q*32 + lane];
            m2 = nm;
        }
    }
    float* o = O + (long)w*F3;
    #pragma unroll
    for (int q = 0; q < 4; ++q) {
        int c0 = q*32 + lane;
        o[c0]        = acc[q]  /d0 + bias[c0];
        o[HE + c0]   = acc[4+q]/d1 + bias[HE + c0];
        o[2*HE + c0] = acc[8+q]/d2 + bias[2*HE + c0];
    }
}

// ---------------- batched output head ----------------
__global__ void out_all(const float* __restrict__ opW, const float* __restrict__ opb,
                        float* __restrict__ out)
{
    long w = (long)(blockIdx.x*blockDim.x + threadIdx.x) >> 5;
    if (w >= (long)OUTL*NT) return;
    int lane = threadIdx.x & 31;
    long t = w / NT, row = w - t*NT;
    const float* h = g_H1ALL + (t*NT + row)*HD;
    float s0 = 0.f, s1 = 0.f;
    #pragma unroll
    for (int k = lane; k < HD; k += 32) {
        float hv = h[k];
        s0 += hv*opW[k*2];
        s1 += hv*opW[k*2+1];
    }
    #pragma unroll
    for (int o = 16; o; o >>= 1) {
        s0 += __shfl_down_sync(0xffffffffu, s0, o);
        s1 += __shfl_down_sync(0xffffffffu, s1, o);
    }
    if (lane == 0) {
        long base = (row*OUTL + t)*2;
        out[base]   = s0 + opb[0];
        out[base+1] = s1 + opb[1];
    }
}

// ---------------- host ----------------
template<int PRE, int ACT>
static inline void mmagemm(const float* A, const __nv_bfloat16* Wh, const __nv_bfloat16* Wl, int K,
                           const float* bias, const int* ridx, float* C, long M, int N)
{
    dim3 g(N/WBN, (unsigned)((M + WBM - 1)/WBM));
    mma_gemm<PRE,ACT><<<g, 256, GEMM_SMEM>>>(A, Wh, Wl, K, bias, ridx, C, (int)M, N);
}

extern "C" void kernel_launch(void* const* d_in, const int* in_sizes, int n_in,
                              void* d_out, int out_size)
{
    const float* x    = (const float*)d_in[0];
    const int*   ei   = (const int*)  d_in[1];
    const int*   tgt  = (const int*)  d_in[2];
    const float* ipW  = (const float*)d_in[3];
    const float* ipb  = (const float*)d_in[4];
    const float* gWx  = (const float*)d_in[5];
    const float* gWh  = (const float*)d_in[6];
    const float* gbx  = (const float*)d_in[7];
    const float* gbh  = (const float*)d_in[8];
    const float* dynW = (const float*)d_in[9];
    const float* dynb = (const float*)d_in[10];
    const float* g1W  = (const float*)d_in[11];
    const float* g1as = (const float*)d_in[12];
    const float* g1ad = (const float*)d_in[13];
    const float* g1b  = (const float*)d_in[14];
    const float* g2W  = (const float*)d_in[15];
    const float* g2as = (const float*)d_in[16];
    const float* g2ad = (const float*)d_in[17];
    const float* g2b  = (const float*)d_in[18];
    const float* fcW  = (const float*)d_in[19];
    const float* fcb  = (const float*)d_in[20];
    const float* l0Wx = (const float*)d_in[21];
    const float* l0Wh = (const float*)d_in[22];
    const float* l0b  = (const float*)d_in[23];
    const float* l1Wx = (const float*)d_in[24];
    const float* l1Wh = (const float*)d_in[25];
    const float* l1b  = (const float*)d_in[26];
    const float* opW  = (const float*)d_in[27];
    const float* opb  = (const float*)d_in[28];
    float* out = (float*)d_out;
    (void)in_sizes; (void)n_in; (void)out_size;

    float *H,*H2,*HENC,*F1,*O1,*F2,*O2,*ENC,*X0,*c0,*c1,*h0a,*h0b,*h1z,*H1ALL;
    float *l0bp,*l1bp;
    __nv_bfloat16 *WTh,*WTl;
    cudaGetSymbolAddress((void**)&H,    g_H);
    cudaGetSymbolAddress((void**)&H2,   g_H2);
    cudaGetSymbolAddress((void**)&HENC, g_HENC);
    cudaGetSymbolAddress((void**)&F1,   g_F1);
    cudaGetSymbolAddress((void**)&O1,   g_O1);
    cudaGetSymbolAddress((void**)&F2,   g_F2);
    cudaGetSymbolAddress((void**)&O2,   g_O2);
    cudaGetSymbolAddress((void**)&ENC,  g_ENC);
    cudaGetSymbolAddress((void**)&X0,   g_X0);
    cudaGetSymbolAddress((void**)&c0,   g_c0);
    cudaGetSymbolAddress((void**)&c1,   g_c1);
    cudaGetSymbolAddress((void**)&h0a,  g_h0a);
    cudaGetSymbolAddress((void**)&h0b,  g_h0b);
    cudaGetSymbolAddress((void**)&h1z,  g_h1z);
    cudaGetSymbolAddress((void**)&H1ALL,g_H1ALL);
    cudaGetSymbolAddress((void**)&l0bp, g_l0bp);
    cudaGetSymbolAddress((void**)&l1bp, g_l1bp);
    cudaGetSymbolAddress((void**)&WTh,  g_WThi);
    cudaGetSymbolAddress((void**)&WTl,  g_WTlo);

    static int attr_set = 0;
    if (!attr_set) {
        cudaFuncSetAttribute(mma_gemm<0,0>, cudaFuncAttributeMaxDynamicSharedMemorySize, GEMM_SMEM);
        cudaFuncSetAttribute(mma_gemm<0,1>, cudaFuncAttributeMaxDynamicSharedMemorySize, GEMM_SMEM);
        cudaFuncSetAttribute(mma_gemm<1,1>, cudaFuncAttributeMaxDynamicSharedMemorySize, GEMM_SMEM);
        cudaFuncSetAttribute(dec_gemm<0>, cudaFuncAttributeMaxDynamicSharedMemorySize, GEMM_SMEM);
        cudaFuncSetAttribute(dec_gemm<1>, cudaFuncAttributeMaxDynamicSharedMemorySize, GEMM_SMEM);
        attr_set = 1;
    }

    // ---- fused prep + zero ----
    prep_all<<<(int)((PREP_TOTAL + 255)/256), 256>>>(gWx, gWh, gbx, gbh, g1W, g2W,
                                                     l0Wx, l0Wh, l1Wx, l1Wh, dynW, fcW,
                                                     l0b, l1b);
    zero_all<<<(int)((ZT + 255)/256), 256>>>();

    // ---- CSR build ----
    edge_count<<<(NE+255)/256,256>>>(ei);
    scan_kernel<<<1,1024>>>();
    edge_scatter<<<(NE+255)/256,256>>>(ei);

    // ---- encoder ----
    emb_kernel<<<(int)(((long)NN*TT*DE + 255)/256),256>>>(x, ipW, ipb);
    {
        dim3 gg(8, (NN+127)/128);
        for (int t = 0; t < TT; ++t) {
            const float* hin  = (t & 1) ? H2 : H;
            float*       hout = (t & 1) ? H  : H2;
            gru_step2<<<gg, 256, GRU_SMEM2>>>(hin, WTh+O_GRU, WTl+O_GRU, hout, t);
        }
    }

    // hist_enc
    mmagemm<1,1>(H, WTh+O_DYN, WTl+O_DYN, HE, dynb, nullptr, HENC, NN, HE);

    // ---- GAT layer 1 ----
    mmagemm<0,0>(HENC, WTh+O_G1W, WTl+O_G1W, HE, nullptr, nullptr, F1, NN, F3);
    attn_coef<<<(NN*3*32+255)/256,256>>>(F1, g1as, g1ad);
    gat_agg<<<(NN*32+255)/256,256>>>(F1, g1b, O1);

    // ---- GAT layer 2 ----
    mmagemm<0,0>(O1, WTh+O_G2W, WTl+O_G2W, F3, nullptr, nullptr, F2, NN, F3);
    attn_coef<<<(NN*3*32+255)/256,256>>>(F2, g2as, g2ad);
    gat_agg<<<(NN*32+255)/256,256>>>(F2, g2b, O2);

    // ---- target gather + fc + X0 ----
    mmagemm<0,1>(O2, WTh+O_FC, WTl+O_FC, F3, fcb, tgt, ENC, NT, HE);
    mmagemm<0,0>(ENC, WTh+O_L0WX, WTl+O_L0WX, HE, l0bp, nullptr, X0, NT, 4*HD);

    // ---- decoder ----
    {
        dim3 gd(16, (NT+127)/128);
        for (int t = 0; t < OUTL; ++t) {
            float* h0in  = (t & 1) ? h0b : h0a;
            float* h0out = (t & 1) ? h0a : h0b;
            const float* h1in = (t == 0) ? h1z : (H1ALL + (long)(t-1)*NT*HD);
            float* h1out = H1ALL + (long)t*NT*HD;
            dec_gemm<0><<<gd, 256, GEMM_SMEM>>>(h0in, nullptr, WTh+O_L0WH, WTl+O_L0WH,
                                                X0, c0, h0out, t == 0);
            dec_gemm<1><<<gd, 256, GEMM_SMEM>>>(h0out, h1in, WTh+O_L1, WTl+O_L1,
                                                l1bp, c1, h1out, t == 0);
        }
        out_all<<<((long)OUTL*NT*32 + 255)/256, 256>>>(opW, opb, out);
    }
}

// round 17
// speedup vs baseline: 1.2248x; 1.0007x over previous
#include <cuda_runtime.h>
#include <cuda_bf16.h>
#include <mma.h>
#include <math.h>
#include <stdint.h>

using namespace nvcuda;

#define NN   30000
#define TT   16
#define DE   32
#define HE   128
#define F3   384
#define NE0  300000
#define NE   330000
#define NT   3000
#define HD   256
#define OUTL 25

// ---------------- scratch ----------------
__device__ __align__(256) float g_EMB[NN*TT*DE];
__device__ __align__(256) float g_H[NN*HE];
__device__ __align__(256) float g_H2[NN*HE];
__device__ __align__(256) float g_HENC[NN*HE];
__device__ __align__(256) float g_F1[NN*F3];
__device__ __align__(256) float g_O1[NN*F3];
__device__ __align__(256) float g_F2[NN*F3];
__device__ __align__(256) float g_O2[NN*F3];
__device__ __align__(256) float g_asv1[NN*3];
__device__ __align__(256) float g_adv1[NN*3];
__device__ __align__(256) float g_asv2[NN*3];
__device__ __align__(256) float g_adv2[NN*3];
__device__ __align__(256) float g_ENC[NT*HE];
__device__ __align__(256) float g_X0[NT*4*HD];
__device__ __align__(256) float g_c0[NT*HD];
__device__ __align__(256) float g_c1[NT*HD];
__device__ __align__(256) float g_h0a[NT*HD];
__device__ __align__(256) float g_h0b[NT*HD];
__device__ __align__(256) float g_h1z[NT*HD];
__device__ __align__(256) float g_H1ALL[(long)OUTL*NT*HD];
__device__ int g_cnt[NN];
__device__ int g_offs[NN+1];
__device__ int g_cur[NN];
__device__ int g_ssrc[NE];
__device__ float g_grub[512];
__device__ float g_l0bp[4*HD];
__device__ float g_l1bp[4*HD];
#define WT_TOTAL 1330000
__device__ __align__(256) __nv_bfloat16 g_WThi[WT_TOTAL];
__device__ __align__(256) __nv_bfloat16 g_WTlo[WT_TOTAL];

// weight offsets (elements)
#define O_G1W  61440
#define O_G2W  110592
#define O_L0WX 258048
#define O_L0WH 389120
#define O_L1   651264
#define O_DYN  1175552
#define O_FC   1191936
#define O_GRU  1241088

__device__ __forceinline__ float sigf(float x){ return 1.f/(1.f+__expf(-x)); }
__device__ __forceinline__ float lk01(float x){ return x>=0.f? x : 0.1f*x; }

// ---------------- fused zero (cnt, H, h0a, h1z, asv/adv x2) ----------------
#define ZT ((long)NN + (long)NN*HE + 2L*NT*HD + 12L*NN)
__global__ void zero_all(){
    long i = (long)blockIdx.x*blockDim.x + threadIdx.x;
    if (i < NN) { g_cnt[i] = 0; return; }
    i -= NN;
    if (i < (long)NN*HE) { g_H[i] = 0.f; return; }
    i -= (long)NN*HE;
    if (i < (long)NT*HD) { g_h0a[i] = 0.f; return; }
    i -= (long)NT*HD;
    if (i < (long)NT*HD) { g_h1z[i] = 0.f; return; }
    i -= (long)NT*HD;
    if (i < 3L*NN) { g_asv1[i] = 0.f; return; }
    i -= 3L*NN;
    if (i < 3L*NN) { g_adv1[i] = 0.f; return; }
    i -= 3L*NN;
    if (i < 3L*NN) { g_asv2[i] = 0.f; return; }
    i -= 3L*NN;
    if (i < 3L*NN) { g_adv2[i] = 0.f; return; }
}

// ---------------- fused weight prep ----------------
__device__ __forceinline__ void wsp_one(const float* __restrict__ W, long idx,
                                        int N, int P, int ldk, int kofs, long base)
{
    int k = (int)(idx / N), n = (int)(idx - (long)k*N);
    int Gp = N / P;
    int np = (n % Gp)*P + n/Gp;
    float v = W[idx];
    __nv_bfloat16 h = __float2bfloat16(v);
    long o = base + (long)np*ldk + kofs + k;
    g_WThi[o] = h;
    g_WTlo[o] = __float2bfloat16(v - __bfloat162float(h));
}

__device__ __forceinline__ void wscat_one(const float* __restrict__ W, long idx,
                                          int kbase, int mode)
{
    int k = (int)(idx / F3), n = (int)(idx - (long)k*F3);
    int g = n / HE, j = n - g*HE;
    int cp = 4*j + ((g < 2) ? g : (mode ? 3 : 2));
    float v = W[idx];
    __nv_bfloat16 h = __float2bfloat16(v);
    long o = O_GRU + (long)cp*160 + kbase + k;
    g_WThi[o] = h;
    g_WTlo[o] = __float2bfloat16(v - __bfloat162float(h));
}

#define SZ_ZC   20480L
#define SZ_S1   49152L
#define SZ_S2   12288L
#define SZ_W1   49152L
#define SZ_W2   147456L
#define SZ_W3   131072L
#define SZ_W4   262144L
#define SZ_W5   262144L
#define SZ_W6   262144L
#define SZ_W7   16384L
#define SZ_W8   49152L
#define SZ_B1   1024L
#define SZ_B2   1024L
#define SZ_G    128L
#define PREP_TOTAL (SZ_ZC+SZ_S1+SZ_S2+SZ_W1+SZ_W2+SZ_W3+SZ_W4+SZ_W5+SZ_W6+SZ_W7+SZ_W8+SZ_B1+SZ_B2+SZ_G)

__global__ void prep_all(const float* __restrict__ gWx, const float* __restrict__ gWh,
                         const float* __restrict__ gbx, const float* __restrict__ gbh,
                         const float* __restrict__ g1W, const float* __restrict__ g2W,
                         const float* __restrict__ l0Wx, const float* __restrict__ l0Wh,
                         const float* __restrict__ l1Wx, const float* __restrict__ l1Wh,
                         const float* __restrict__ dynW, const float* __restrict__ fcW,
                         const float* __restrict__ l0b, const float* __restrict__ l1b)
{
    long r = (long)blockIdx.x*blockDim.x + threadIdx.x;
    if (r >= PREP_TOTAL) return;
    if (r < SZ_ZC) {
        int j = (int)(r / 160), q = (int)(r % 160);
        int cp, k;
        if (q < 32) { cp = 4*j + 2; k = 128 + q; }
        else        { cp = 4*j + 3; k = q - 32; }
        long o = O_GRU + (long)cp*160 + k;
        __nv_bfloat16 z = __float2bfloat16(0.f);
        g_WThi[o] = z; g_WTlo[o] = z;
        return;
    }
    r -= SZ_ZC;
    if (r < SZ_S1) { wscat_one(gWh, r, 0, 0); return; }
    r -= SZ_S1;
    if (r < SZ_S2) { wscat_one(gWx, r, 128, 1); return; }
    r -= SZ_S2;
    if (r < SZ_W1) { wsp_one(g1W,  r, 384, 1, 128, 0, O_G1W); return; }
    r -= SZ_W1;
    if (r < SZ_W2) { wsp_one(g2W,  r, 384, 1, 384, 0, O_G2W); return; }
    r -= SZ_W2;
    if (r < SZ_W3) { wsp_one(l0Wx, r, 1024, 4, 128, 0, O_L0WX); return; }
    r -= SZ_W3;
    if (r < SZ_W4) { wsp_one(l0Wh, r, 1024, 4, 256, 0, O_L0WH); return; }
    r -= SZ_W4;
    if (r < SZ_W5) { wsp_one(l1Wx, r, 1024, 4, 512, 0, O_L1); return; }
    r -= SZ_W5;
    if (r < SZ_W6) { wsp_one(l1Wh, r, 1024, 4, 512, 256, O_L1); return; }
    r -= SZ_W6;
    if (r < SZ_W7) { wsp_one(dynW, r, 128, 1, 128, 0, O_DYN); return; }
    r -= SZ_W7;
    if (r < SZ_W8) { wsp_one(fcW,  r, 128, 1, 384, 0, O_FC); return; }
    r -= SZ_W8;
    if (r < SZ_B1) { int n = (int)r; g_l0bp[(n % 256)*4 + n/256] = l0b[n]; return; }
    r -= SZ_B1;
    if (r < SZ_B2) { int n = (int)r; g_l1bp[(n % 256)*4 + n/256] = l1b[n]; return; }
    r -= SZ_B2;
    {
        int j = (int)r;
        g_grub[4*j+0] = gbx[j]       + gbh[j];
        g_grub[4*j+1] = gbx[HE+j]    + gbh[HE+j];
        g_grub[4*j+2] = gbh[2*HE+j];
        g_grub[4*j+3] = gbx[2*HE+j];
    }
}

typedef wmma::fragment<wmma::matrix_a, 16,16,16, __nv_bfloat16, wmma::row_major> FragA;
typedef wmma::fragment<wmma::matrix_b, 16,16,16, __nv_bfloat16, wmma::col_major> FragB;
typedef wmma::fragment<wmma::accumulator, 16,16,16, float> FragC;

#define WBM 128
#define WBN 64
#define SKA2 72
#define SKB2 72
#define GEMM_SMEM 55296
#define SKA 40
#define SKB 40
#define GRU_SMEM2 36864

__device__ __forceinline__ void splitstore_a(__nv_bfloat16* Ah, __nv_bfloat16* Al,
                                             int o, float4 v)
{
    __nv_bfloat16 hx = __float2bfloat16(v.x);
    __nv_bfloat16 hy = __float2bfloat16(v.y);
    __nv_bfloat16 hz = __float2bfloat16(v.z);
    __nv_bfloat16 hw = __float2bfloat16(v.w);
    Ah[o]   = hx; Ah[o+1] = hy; Ah[o+2] = hz; Ah[o+3] = hw;
    Al[o]   = __float2bfloat16(v.x - __bfloat162float(hx));
    Al[o+1] = __float2bfloat16(v.y - __bfloat162float(hy));
    Al[o+2] = __float2bfloat16(v.z - __bfloat162float(hz));
    Al[o+3] = __float2bfloat16(v.w - __bfloat162float(hw));
}

// ---------------- generic WMMA bf16x3 GEMM (BK=64, register-prefetch) ----------------
// Optional fused GAT attention coefficients: if as_ != nullptr, accumulate
// asv[row*3+head] += dot(Frow_slice, a_s), adv likewise (atomicAdd partials).
template<int PRE, int ACT>
__global__ void __launch_bounds__(256,2)
mma_gemm(const float* __restrict__ A1, const __nv_bfloat16* __restrict__ W1h,
         const __nv_bfloat16* __restrict__ W1l, int K1,
         const float* __restrict__ bias, const int* __restrict__ rowidx,
         float* __restrict__ C, int M, int N,
         const float* __restrict__ as_, const float* __restrict__ ad_,
         float* __restrict__ asv, float* __restrict__ adv)
{
    extern __shared__ char smc[];
    __nv_bfloat16* Ah = (__nv_bfloat16*)smc;
    __nv_bfloat16* Al = Ah + WBM*SKA2;
    __nv_bfloat16* Bh = Al + WBM*SKA2;
    __nv_bfloat16* Bl = Bh + WBN*SKB2;
    float* Cs = (float*)smc;

    const int tid = threadIdx.x, wid = tid >> 5;
    const int warp_m = wid >> 1, warp_n = wid & 1;
    const long bm = (long)blockIdx.y * WBM;
    const int bn = blockIdx.x * WBN;

    const int ra0 = tid >> 4, ca = (tid & 15) << 2;
    const int rb0 = tid >> 3, cbb = (tid & 7) << 3;
    long arow[8];
    #pragma unroll
    for (int i = 0; i < 8; ++i) {
        long row = bm + ra0 + 16*i;
        arow[i] = (row < M) ? (rowidx ? (long)rowidx[row] : row) : -1;
    }

    FragC acc[2][2];
    #pragma unroll
    for (int mm = 0; mm < 2; ++mm)
        #pragma unroll
        for (int nn = 0; nn < 2; ++nn)
            wmma::fill_fragment(acc[mm][nn], 0.f);

    float4 va[8];
    uint4 vbh[2], vbl[2];
    #pragma unroll
    for (int i = 0; i < 8; ++i) {
        va[i] = make_float4(0.f,0.f,0.f,0.f);
        if (arow[i] >= 0) va[i] = *(const float4*)(A1 + arow[i]*K1 + ca);
    }
    #pragma unroll
    for (int i = 0; i < 2; ++i) {
        long go = (long)(bn + rb0 + 32*i)*K1 + cbb;
        vbh[i] = *(const uint4*)(W1h + go);
        vbl[i] = *(const uint4*)(W1l + go);
    }

    for (int k0 = 0; k0 < K1; k0 += 64) {
        #pragma unroll
        for (int i = 0; i < 8; ++i) {
            float4 v = va[i];
            if (PRE) { v.x=lk01(v.x); v.y=lk01(v.y); v.z=lk01(v.z); v.w=lk01(v.w); }
            splitstore_a(Ah, Al, (ra0 + 16*i)*SKA2 + ca, v);
        }
        #pragma unroll
        for (int i = 0; i < 2; ++i) {
            *(uint4*)&Bh[(rb0 + 32*i)*SKB2 + cbb] = vbh[i];
            *(uint4*)&Bl[(rb0 + 32*i)*SKB2 + cbb] = vbl[i];
        }
        __syncthreads();

        const int kn = k0 + 64;
        if (kn < K1) {
            #pragma unroll
            for (int i = 0; i < 8; ++i) {
                va[i] = make_float4(0.f,0.f,0.f,0.f);
                if (arow[i] >= 0) va[i] = *(const float4*)(A1 + arow[i]*K1 + kn + ca);
            }
            #pragma unroll
            for (int i = 0; i < 2; ++i) {
                long go = (long)(bn + rb0 + 32*i)*K1 + kn + cbb;
                vbh[i] = *(const uint4*)(W1h + go);
                vbl[i] = *(const uint4*)(W1l + go);
            }
        }

        #pragma unroll
        for (int kk = 0; kk < 64; kk += 16) {
            FragA ah[2], al[2];
            FragB bh[2], bl[2];
            #pragma unroll
            for (int mm = 0; mm < 2; ++mm) {
                int ro = (warp_m*32 + mm*16)*SKA2 + kk;
                wmma::load_matrix_sync(ah[mm], Ah + ro, SKA2);
                wmma::load_matrix_sync(al[mm], Al + ro, SKA2);
            }
            #pragma unroll
            for (int nn = 0; nn < 2; ++nn) {
                int no = (warp_n*32 + nn*16)*SKB2 + kk;
                wmma::load_matrix_sync(bh[nn], Bh + no, SKB2);
                wmma::load_matrix_sync(bl[nn], Bl + no, SKB2);
            }
            #pragma unroll
            for (int mm = 0; mm < 2; ++mm)
                #pragma unroll
                for (int nn = 0; nn < 2; ++nn) {
                    wmma::mma_sync(acc[mm][nn], ah[mm], bh[nn], acc[mm][nn]);
                    wmma::mma_sync(acc[mm][nn], ah[mm], bl[nn], acc[mm][nn]);
                    wmma::mma_sync(acc[mm][nn], al[mm], bh[nn], acc[mm][nn]);
                }
        }
        __syncthreads();
    }

    #pragma unroll
    for (int mm = 0; mm < 2; ++mm)
        #pragma unroll
        for (int nn = 0; nn < 2; ++nn)
            wmma::store_matrix_sync(Cs + (warp_m*32 + mm*16)*68 + warp_n*32 + nn*16,
                                    acc[mm][nn], 68, wmma::mem_row_major);
    __syncthreads();

    // per-block head is constant: 64-col slice never crosses a 128-col head boundary
    const int head = bn >> 7;
    const int c128b = bn & 127;

    #pragma unroll
    for (int i = 0; i < 8; ++i) {
        int li = tid + (i << 8);
        int r = li >> 4, c = (li & 15) << 2;
        long row = bm + r;
        bool ok = (row < M);
        float4 v = make_float4(0.f,0.f,0.f,0.f);
        if (ok) {
            v = *(float4*)&Cs[r*68 + c];
            int col = bn + c;
            if (bias) {
                float4 bb = *(const float4*)(bias + col);
                v.x += bb.x; v.y += bb.y; v.z += bb.z; v.w += bb.w;
            }
            if (ACT) { v.x=lk01(v.x); v.y=lk01(v.y); v.z=lk01(v.z); v.w=lk01(v.w); }
            *(float4*)(C + row*(long)N + col) = v;
        }
        if (as_) {
            int cc = c128b + c;
            float pa = 0.f, pd = 0.f;
            if (ok) {
                pa = v.x*as_[head*HE+cc]   + v.y*as_[head*HE+cc+1]
                   + v.z*as_[head*HE+cc+2] + v.w*as_[head*HE+cc+3];
                pd = v.x*ad_[head*HE+cc]   + v.y*ad_[head*HE+cc+1]
                   + v.z*ad_[head*HE+cc+2] + v.w*ad_[head*HE+cc+3];
            }
            #pragma unroll
            for (int o = 8; o; o >>= 1) {
                pa += __shfl_down_sync(0xffffffffu, pa, o, 16);
                pd += __shfl_down_sync(0xffffffffu, pd, o, 16);
            }
            if ((tid & 15) == 0 && ok) {
                atomicAdd(&asv[row*3 + head], pa);
                atomicAdd(&adv[row*3 + head], pd);
            }
        }
    }
}

// ---------------- GRU step (BK=32 pipelined, K=160), fused gates ----------------
__global__ void __launch_bounds__(256,2)
gru_step2(const float* __restrict__ Hin, const __nv_bfloat16* __restrict__ Wh,
          const __nv_bfloat16* __restrict__ Wl, float* __restrict__ Hout, int t)
{
    extern __shared__ char sm[];
    __nv_bfloat16* Ah = (__nv_bfloat16*)sm;
    __nv_bfloat16* Al = Ah + 128*SKA;
    __nv_bfloat16* Bh = Al + 128*SKA;
    __nv_bfloat16* Bl = Bh + 64*SKB;
    float* Cs = (float*)sm;

    const int tid = threadIdx.x, wid = tid >> 5;
    const int warp_m = wid >> 1, warp_n = wid & 1;
    const long bm = (long)blockIdx.y * 128;
    const int bn = blockIdx.x * 64;

    const int ra0 = tid >> 3, ca = (tid & 7) << 2;
    const int rb  = tid >> 2, cb = (tid & 3) << 3;
    long nodei[4];
    #pragma unroll
    for (int i = 0; i < 4; ++i) {
        long node = bm + ra0 + 32*i;
        nodei[i] = (node < NN) ? node : -1;
    }

    FragC acc[2][2];
    #pragma unroll
    for (int mm = 0; mm < 2; ++mm)
        #pragma unroll
        for (int nn = 0; nn < 2; ++nn)
            wmma::fill_fragment(acc[mm][nn], 0.f);

    float4 va[4];
    uint4 vbh, vbl;
    #pragma unroll
    for (int i = 0; i < 4; ++i) {
        va[i] = make_float4(0.f,0.f,0.f,0.f);
        if (nodei[i] >= 0) va[i] = *(const float4*)(Hin + nodei[i]*HE + ca);
    }
    {
        long go = (long)(bn + rb)*160 + cb;
        vbh = *(const uint4*)(Wh + go);
        vbl = *(const uint4*)(Wl + go);
    }

    #pragma unroll
    for (int ch = 0; ch < 5; ++ch) {
        #pragma unroll
        for (int i = 0; i < 4; ++i)
            splitstore_a(Ah, Al, (ra0 + 32*i)*SKA + ca, va[i]);
        *(uint4*)&Bh[rb*SKB + cb] = vbh;
        *(uint4*)&Bl[rb*SKB + cb] = vbl;
        __syncthreads();

        if (ch + 1 < 5) {
            const int cn = ch + 1;
            #pragma unroll
            for (int i = 0; i < 4; ++i) {
                va[i] = make_float4(0.f,0.f,0.f,0.f);
                if (nodei[i] >= 0) {
                    if (cn < 4) va[i] = *(const float4*)(Hin + nodei[i]*HE + (cn<<5) + ca);
                    else        va[i] = *(const float4*)(g_EMB + (nodei[i]*TT + t)*DE + ca);
                }
            }
            long go = (long)(bn + rb)*160 + (cn<<5) + cb;
            vbh = *(const uint4*)(Wh + go);
            vbl = *(const uint4*)(Wl + go);
        }

        #pragma unroll
        for (int kk = 0; kk < 32; kk += 16) {
            FragA ah[2], al[2];
            FragB bh[2], bl[2];
            #pragma unroll
            for (int mm = 0; mm < 2; ++mm) {
                int ro = (warp_m*32 + mm*16)*SKA + kk;
                wmma::load_matrix_sync(ah[mm], Ah + ro, SKA);
                wmma::load_matrix_sync(al[mm], Al + ro, SKA);
            }
            #pragma unroll
            for (int nn = 0; nn < 2; ++nn) {
                int no = (warp_n*32 + nn*16)*SKB + kk;
                wmma::load_matrix_sync(bh[nn], Bh + no, SKB);
                wmma::load_matrix_sync(bl[nn], Bl + no, SKB);
            }
            #pragma unroll
            for (int mm = 0; mm < 2; ++mm)
                #pragma unroll
                for (int nn = 0; nn < 2; ++nn) {
                    wmma::mma_sync(acc[mm][nn], ah[mm], bh[nn], acc[mm][nn]);
                    wmma::mma_sync(acc[mm][nn], ah[mm], bl[nn], acc[mm][nn]);
                    wmma::mma_sync(acc[mm][nn], al[mm], bh[nn], acc[mm][nn]);
                }
        }
        __syncthreads();
    }

    #pragma unroll
    for (int mm = 0; mm < 2; ++mm)
        #pragma unroll
        for (int nn = 0; nn < 2; ++nn)
            wmma::store_matrix_sync(Cs + (warp_m*32 + mm*16)*68 + warp_n*32 + nn*16,
                                    acc[mm][nn], 68, wmma::mem_row_major);
    __syncthreads();

    #pragma unroll
    for (int i = 0; i < 8; ++i) {
        int li = tid + (i << 8);
        int r = li >> 4, q = li & 15;
        long node = bm + r;
        if (node < NN) {
            int j = blockIdx.x*16 + q;
            const float* gs = Cs + r*68 + 4*q;
            float rr  = sigf(gs[0] + g_grub[4*j+0]);
            float zz  = sigf(gs[1] + g_grub[4*j+1]);
            float ghn = gs[2] + g_grub[4*j+2];
            float gxn = gs[3] + g_grub[4*j+3];
            float nn2 = tanhf(gxn + rr*ghn);
            float hold = Hin[node*HE + j];
            Hout[node*HE + j] = (1.f - zz)*nn2 + zz*hold;
        }
    }
}

// ---------------- decoder step GEMM (BK=64 pipelined) with fused LSTM gates ----------------
template<int L1>
__global__ void __launch_bounds__(256,2)
dec_gemm(const float* __restrict__ A1, const float* __restrict__ A2,
         const __nv_bfloat16* __restrict__ Wh, const __nv_bfloat16* __restrict__ Wl,
         const float* __restrict__ pre, float* __restrict__ cbuf,
         float* __restrict__ hout, int first)
{
    extern __shared__ char sm[];
    __nv_bfloat16* Ah = (__nv_bfloat16*)sm;
    __nv_bfloat16* Al = Ah + WBM*SKA2;
    __nv_bfloat16* Bh = Al + WBM*SKA2;
    __nv_bfloat16* Bl = Bh + WBN*SKB2;
    float* Cs = (float*)sm;

    const int tid = threadIdx.x, wid = tid >> 5;
    const int warp_m = wid >> 1, warp_n = wid & 1;
    const long bm = (long)blockIdx.y * WBM;
    const int bn = blockIdx.x * WBN;
    const int KTOT = L1 ? 2*HD : HD;

    const int ra0 = tid >> 4, ca = (tid & 15) << 2;
    const int rb0 = tid >> 3, cbb = (tid & 7) << 3;
    long rowi[8];
    #pragma unroll
    for (int i = 0; i < 8; ++i) {
        long row = bm + ra0 + 16*i;
        rowi[i] = (row < NT) ? row : -1;
    }

    FragC acc[2][2];
    #pragma unroll
    for (int mm = 0; mm < 2; ++mm)
        #pragma unroll
        for (int nn = 0; nn < 2; ++nn)
            wmma::fill_fragment(acc[mm][nn], 0.f);

    float4 va[8];
    uint4 vbh[2], vbl[2];
    #pragma unroll
    for (int i = 0; i < 8; ++i) {
        va[i] = make_float4(0.f,0.f,0.f,0.f);
        if (rowi[i] >= 0) va[i] = *(const float4*)(A1 + rowi[i]*HD + ca);
    }
    #pragma unroll
    for (int i = 0; i < 2; ++i) {
        long go = (long)(bn + rb0 + 32*i)*KTOT + cbb;
        vbh[i] = *(const uint4*)(Wh + go);
        vbl[i] = *(const uint4*)(Wl + go);
    }

    for (int k0 = 0; k0 < KTOT; k0 += 64) {
        #pragma unroll
        for (int i = 0; i < 8; ++i)
            splitstore_a(Ah, Al, (ra0 + 16*i)*SKA2 + ca, va[i]);
        #pragma unroll
        for (int i = 0; i < 2; ++i) {
            *(uint4*)&Bh[(rb0 + 32*i)*SKB2 + cbb] = vbh[i];
            *(uint4*)&Bl[(rb0 + 32*i)*SKB2 + cbb] = vbl[i];
        }
        __syncthreads();

        const int kn = k0 + 64;
        if (kn < KTOT) {
            const float* A = (L1 && kn >= HD) ? A2 : A1;
            const int ka = kn & (HD-1);
            #pragma unroll
            for (int i = 0; i < 8; ++i) {
                va[i] = make_float4(0.f,0.f,0.f,0.f);
                if (rowi[i] >= 0) va[i] = *(const float4*)(A + rowi[i]*HD + ka + ca);
            }
            #pragma unroll
            for (int i = 0; i < 2; ++i) {
                long go = (long)(bn + rb0 + 32*i)*KTOT + kn + cbb;
                vbh[i] = *(const uint4*)(Wh + go);
                vbl[i] = *(const uint4*)(Wl + go);
            }
        }

        #pragma unroll
        for (int kk = 0; kk < 64; kk += 16) {
            FragA ah[2], al[2];
            FragB bh[2], bl[2];
            #pragma unroll
            for (int mm = 0; mm < 2; ++mm) {
                int ro = (warp_m*32 + mm*16)*SKA2 + kk;
                wmma::load_matrix_sync(ah[mm], Ah + ro, SKA2);
                wmma::load_matrix_sync(al[mm], Al + ro, SKA2);
            }
            #pragma unroll
            for (int nn = 0; nn < 2; ++nn) {
                int no = (warp_n*32 + nn*16)*SKB2 + kk;
                wmma::load_matrix_sync(bh[nn], Bh + no, SKB2);
                wmma::load_matrix_sync(bl[nn], Bl + no, SKB2);
            }
            #pragma unroll
            for (int mm = 0; mm < 2; ++mm)
                #pragma unroll
                for (int nn = 0; nn < 2; ++nn) {
                    wmma::mma_sync(acc[mm][nn], ah[mm], bh[nn], acc[mm][nn]);
                    wmma::mma_sync(acc[mm][nn], ah[mm], bl[nn], acc[mm][nn]);
                    wmma::mma_sync(acc[mm][nn], al[mm], bh[nn], acc[mm][nn]);
                }
        }
        __syncthreads();
    }

    #pragma unroll
    for (int mm = 0; mm < 2; ++mm)
        #pragma unroll
        for (int nn = 0; nn < 2; ++nn)
            wmma::store_matrix_sync(Cs + (warp_m*32 + mm*16)*68 + warp_n*32 + nn*16,
                                    acc[mm][nn], 68, wmma::mem_row_major);
    __syncthreads();

    #pragma unroll
    for (int i = 0; i < 8; ++i) {
        int li = tid + (i << 8);
        int r = li >> 4, q = li & 15;
        long row = bm + r;
        if (row < NT) {
            int j = blockIdx.x*16 + q;
            const float* gs = Cs + r*68 + 4*q;
            const float* pp = L1 ? (pre + bn + 4*q) : (pre + row*(4*HD) + bn + 4*q);
            float ig = sigf(gs[0] + pp[0]);
            float fg = sigf(gs[1] + pp[1]);
            float gg = tanhf(gs[2] + pp[2]);
            float og = sigf(gs[3] + pp[3]);
            float c = first ? 0.f : cbuf[row*HD + j];
            c = fg*c + ig*gg;
            cbuf[row*HD + j] = c;
            hout[row*HD + j] = og*tanhf(c);
        }
    }
}

// ---------------- encoder embedding ----------------
__global__ void emb_kernel(const float* __restrict__ x, const float* __restrict__ ipW,
                           const float* __restrict__ ipb)
{
    long i = (long)blockIdx.x*blockDim.x + threadIdx.x;
    if (i >= (long)NN*TT*DE) return;
    long row = i >> 5; int j = (int)(i & 31);
    float v = x[row*2]*ipW[j] + x[row*2+1]*ipW[DE+j] + ipb[j];
    g_EMB[i] = lk01(v);
}

// ---------------- CSR build ----------------
__global__ void edge_count(const int* __restrict__ ei){
    int e = blockIdx.x*blockDim.x + threadIdx.x;
    if (e >= NE) return;
    int d = (e < NE0) ? ei[NE0+e] : (e - NE0);
    atomicAdd(&g_cnt[d], 1);
}

// fast single-block scan: 1024 threads x 30 nodes each (covers 30720 >= NN)
#define SCH 30
__global__ void scan_kernel(){
    __shared__ int sh[1024];
    int tid = threadIdx.x;
    int base = tid*SCH;
    int loc[SCH];
    int sum = 0;
    #pragma unroll
    for (int i = 0; i < SCH; ++i) {
        int n = base + i;
        int v = (n < NN) ? g_cnt[n] : 0;
        sum += v;
        loc[i] = sum;         // inclusive within thread
    }
    sh[tid] = sum;
    __syncthreads();
    #pragma unroll
    for (int off = 1; off < 1024; off <<= 1) {
        int tv = (tid >= off) ? sh[tid-off] : 0;
        __syncthreads();
        sh[tid] += tv;
        __syncthreads();
    }
    int pre = (tid > 0) ? sh[tid-1] : 0;   // exclusive prefix of this thread's chunk
    #pragma unroll
    for (int i = 0; i < SCH; ++i) {
        int n = base + i;
        if (n < NN) {
            int val = pre + loc[i];
            g_offs[n+1] = val;
            if (n+1 < NN) g_cur[n+1] = val;
        }
    }
    if (tid == 0) { g_offs[0] = 0; g_cur[0] = 0; }
}

__global__ void edge_scatter(const int* __restrict__ ei){
    int e = blockIdx.x*blockDim.x + threadIdx.x;
    if (e >= NE) return;
    int s, d;
    if (e < NE0) { s = ei[e]; d = ei[NE0+e]; } else { s = e - NE0; d = s; }
    int pos = atomicAdd(&g_cur[d], 1);
    g_ssrc[pos] = s;
}

// ---------------- GAT aggregation ----------------
__global__ void gat_agg(const float* __restrict__ F, const float* __restrict__ bias,
                        const float* __restrict__ asv, const float* __restrict__ adv,
                        float* __restrict__ O)
{
    int w = (blockIdx.x*blockDim.x + threadIdx.x) >> 5;
    if (w >= NN) return;
    int lane = threadIdx.x & 31;
    int beg = g_offs[w], end = g_offs[w+1];
    float ad0 = adv[w*3], ad1 = adv[w*3+1], ad2 = adv[w*3+2];
    float m0 = -1e30f, m1 = -1e30f, m2 = -1e30f;
    float d0 = 0.f, d1 = 0.f, d2 = 0.f;
    float acc[12];
    #pragma unroll
    for (int q = 0; q < 12; ++q) acc[q] = 0.f;

    int s_nx = 0; float b0 = 0.f, b1 = 0.f, b2 = 0.f;
    if (beg < end) {
        s_nx = g_ssrc[beg];
        b0 = asv[s_nx*3]; b1 = asv[s_nx*3+1]; b2 = asv[s_nx*3+2];
    }

    for (int p = beg; p < end; ++p) {
        int s = s_nx;
        float e0 = b0 + ad0, e1 = b1 + ad1, e2 = b2 + ad2;
        if (p + 1 < end) {
            s_nx = g_ssrc[p+1];
            b0 = asv[s_nx*3]; b1 = asv[s_nx*3+1]; b2 = asv[s_nx*3+2];
        }
        e0 = (e0 >= 0.f) ? e0 : 0.2f*e0;
        e1 = (e1 >= 0.f) ? e1 : 0.2f*e1;
        e2 = (e2 >= 0.f) ? e2 : 0.2f*e2;
        const float* f = F + (long)s*F3;
        {
            float nm = fmaxf(m0, e0); float sc = __expf(m0-nm); float wv = __expf(e0-nm);
            d0 = d0*sc + wv;
            #pragma unroll
            for (int q = 0; q < 4; ++q) acc[q] = acc[q]*sc + wv*f[q*32 + lane];
            m0 = nm;
        }
        {
            float nm = fmaxf(m1, e1); float sc = __expf(m1-nm); float wv = __expf(e1-nm);
            d1 = d1*sc + wv;
            #pragma unroll
            for (int q = 0; q < 4; ++q) acc[4+q] = acc[4+q]*sc + wv*f[HE + q*32 + lane];
            m1 = nm;
        }
        {
            float nm = fmaxf(m2, e2); float sc = __expf(m2-nm); float wv = __expf(e2-nm);
            d2 = d2*sc + wv;
            #pragma unroll
            for (int q = 0; q < 4; ++q) acc[8+q] = acc[8+q]*sc + wv*f[2*HE + q*32 + lane];
            m2 = nm;
        }
    }
    float* o = O + (long)w*F3;
    #pragma unroll
    for (int q = 0; q < 4; ++q) {
        int c0 = q*32 + lane;
        o[c0]        = acc[q]  /d0 + bias[c0];
        o[HE + c0]   = acc[4+q]/d1 + bias[HE + c0];
        o[2*HE + c0] = acc[8+q]/d2 + bias[2*HE + c0];
    }
}

// ---------------- batched output head ----------------
__global__ void out_all(const float* __restrict__ opW, const float* __restrict__ opb,
                        float* __restrict__ out)
{
    long w = (long)(blockIdx.x*blockDim.x + threadIdx.x) >> 5;
    if (w >= (long)OUTL*NT) return;
    int lane = threadIdx.x & 31;
    long t = w / NT, row = w - t*NT;
    const float* h = g_H1ALL + (t*NT + row)*HD;
    float s0 = 0.f, s1 = 0.f;
    #pragma unroll
    for (int k = lane; k < HD; k += 32) {
        float hv = h[k];
        s0 += hv*opW[k*2];
        s1 += hv*opW[k*2+1];
    }
    #pragma unroll
    for (int o = 16; o; o >>= 1) {
        s0 += __shfl_down_sync(0xffffffffu, s0, o);
        s1 += __shfl_down_sync(0xffffffffu, s1, o);
    }
    if (lane == 0) {
        long base = (row*OUTL + t)*2;
        out[base]   = s0 + opb[0];
        out[base+1] = s1 + opb[1];
    }
}

// ---------------- host ----------------
template<int PRE, int ACT>
static inline void mmagemm(const float* A, const __nv_bfloat16* Wh, const __nv_bfloat16* Wl, int K,
                           const float* bias, const int* ridx, float* C, long M, int N,
                           const float* as_ = nullptr, const float* ad_ = nullptr,
                           float* asv = nullptr, float* adv = nullptr)
{
    dim3 g(N/WBN, (unsigned)((M + WBM - 1)/WBM));
    mma_gemm<PRE,ACT><<<g, 256, GEMM_SMEM>>>(A, Wh, Wl, K, bias, ridx, C, (int)M, N,
                                             as_, ad_, asv, adv);
}

extern "C" void kernel_launch(void* const* d_in, const int* in_sizes, int n_in,
                              void* d_out, int out_size)
{
    const float* x    = (const float*)d_in[0];
    const int*   ei   = (const int*)  d_in[1];
    const int*   tgt  = (const int*)  d_in[2];
    const float* ipW  = (const float*)d_in[3];
    const float* ipb  = (const float*)d_in[4];
    const float* gWx  = (const float*)d_in[5];
    const float* gWh  = (const float*)d_in[6];
    const float* gbx  = (const float*)d_in[7];
    const float* gbh  = (const float*)d_in[8];
    const float* dynW = (const float*)d_in[9];
    const float* dynb = (const float*)d_in[10];
    const float* g1W  = (const float*)d_in[11];
    const float* g1as = (const float*)d_in[12];
    const float* g1ad = (const float*)d_in[13];
    const float* g1b  = (const float*)d_in[14];
    const float* g2W  = (const float*)d_in[15];
    const float* g2as = (const float*)d_in[16];
    const float* g2ad = (const float*)d_in[17];
    const float* g2b  = (const float*)d_in[18];
    const float* fcW  = (const float*)d_in[19];
    const float* fcb  = (const float*)d_in[20];
    const float* l0Wx = (const float*)d_in[21];
    const float* l0Wh = (const float*)d_in[22];
    const float* l0b  = (const float*)d_in[23];
    const float* l1Wx = (const float*)d_in[24];
    const float* l1Wh = (const float*)d_in[25];
    const float* l1b  = (const float*)d_in[26];
    const float* opW  = (const float*)d_in[27];
    const float* opb  = (const float*)d_in[28];
    float* out = (float*)d_out;
    (void)in_sizes; (void)n_in; (void)out_size;

    float *H,*H2,*HENC,*F1,*O1,*F2,*O2,*ENC,*X0,*c0,*c1,*h0a,*h0b,*h1z,*H1ALL;
    float *asv1,*adv1,*asv2,*adv2,*l0bp,*l1bp;
    __nv_bfloat16 *WTh,*WTl;
    cudaGetSymbolAddress((void**)&H,    g_H);
    cudaGetSymbolAddress((void**)&H2,   g_H2);
    cudaGetSymbolAddress((void**)&HENC, g_HENC);
    cudaGetSymbolAddress((void**)&F1,   g_F1);
    cudaGetSymbolAddress((void**)&O1,   g_O1);
    cudaGetSymbolAddress((void**)&F2,   g_F2);
    cudaGetSymbolAddress((void**)&O2,   g_O2);
    cudaGetSymbolAddress((void**)&ENC,  g_ENC);
    cudaGetSymbolAddress((void**)&X0,   g_X0);
    cudaGetSymbolAddress((void**)&c0,   g_c0);
    cudaGetSymbolAddress((void**)&c1,   g_c1);
    cudaGetSymbolAddress((void**)&h0a,  g_h0a);
    cudaGetSymbolAddress((void**)&h0b,  g_h0b);
    cudaGetSymbolAddress((void**)&h1z,  g_h1z);
    cudaGetSymbolAddress((void**)&H1ALL,g_H1ALL);
    cudaGetSymbolAddress((void**)&asv1, g_asv1);
    cudaGetSymbolAddress((void**)&adv1, g_adv1);
    cudaGetSymbolAddress((void**)&asv2, g_asv2);
    cudaGetSymbolAddress((void**)&adv2, g_adv2);
    cudaGetSymbolAddress((void**)&l0bp, g_l0bp);
    cudaGetSymbolAddress((void**)&l1bp, g_l1bp);
    cudaGetSymbolAddress((void**)&WTh,  g_WThi);
    cudaGetSymbolAddress((void**)&WTl,  g_WTlo);

    static int attr_set = 0;
    if (!attr_set) {
        cudaFuncSetAttribute(mma_gemm<0,0>, cudaFuncAttributeMaxDynamicSharedMemorySize, GEMM_SMEM);
        cudaFuncSetAttribute(mma_gemm<0,1>, cudaFuncAttributeMaxDynamicSharedMemorySize, GEMM_SMEM);
        cudaFuncSetAttribute(mma_gemm<1,1>, cudaFuncAttributeMaxDynamicSharedMemorySize, GEMM_SMEM);
        cudaFuncSetAttribute(dec_gemm<0>, cudaFuncAttributeMaxDynamicSharedMemorySize, GEMM_SMEM);
        cudaFuncSetAttribute(dec_gemm<1>, cudaFuncAttributeMaxDynamicSharedMemorySize, GEMM_SMEM);
        attr_set = 1;
    }

    // ---- fused prep + zero ----
    prep_all<<<(int)((PREP_TOTAL + 255)/256), 256>>>(gWx, gWh, gbx, gbh, g1W, g2W,
                                                     l0Wx, l0Wh, l1Wx, l1Wh, dynW, fcW,
                                                     l0b, l1b);
    zero_all<<<(int)((ZT + 255)/256), 256>>>();

    // ---- CSR build ----
    edge_count<<<(NE+255)/256,256>>>(ei);
    scan_kernel<<<1,1024>>>();
    edge_scatter<<<(NE+255)/256,256>>>(ei);

    // ---- encoder ----
    emb_kernel<<<(int)(((long)NN*TT*DE + 255)/256),256>>>(x, ipW, ipb);
    {
        dim3 gg(8, (NN+127)/128);
        for (int t = 0; t < TT; ++t) {
            const float* hin  = (t & 1) ? H2 : H;
            float*       hout = (t & 1) ? H  : H2;
            gru_step2<<<gg, 256, GRU_SMEM2>>>(hin, WTh+O_GRU, WTl+O_GRU, hout, t);
        }
    }

    // hist_enc
    mmagemm<1,1>(H, WTh+O_DYN, WTl+O_DYN, HE, dynb, nullptr, HENC, NN, HE);

    // ---- GAT layer 1 (attn coefficients fused into GEMM epilogue) ----
    mmagemm<0,0>(HENC, WTh+O_G1W, WTl+O_G1W, HE, nullptr, nullptr, F1, NN, F3,
                 g1as, g1ad, asv1, adv1);
    gat_agg<<<(NN*32+255)/256,256>>>(F1, g1b, asv1, adv1, O1);

    // ---- GAT layer 2 ----
    mmagemm<0,0>(O1, WTh+O_G2W, WTl+O_G2W, F3, nullptr, nullptr, F2, NN, F3,
                 g2as, g2ad, asv2, adv2);
    gat_agg<<<(NN*32+255)/256,256>>>(F2, g2b, asv2, adv2, O2);

    // ---- target gather + fc + X0 ----
    mmagemm<0,1>(O2, WTh+O_FC, WTl+O_FC, F3, fcb, tgt, ENC, NT, HE);
    mmagemm<0,0>(ENC, WTh+O_L0WX, WTl+O_L0WX, HE, l0bp, nullptr, X0, NT, 4*HD);

    // ---- decoder ----
    {
        dim3 gd(16, (NT+127)/128);
        for (int t = 0; t < OUTL; ++t) {
            float* h0in  = (t & 1) ? h0b : h0a;
            float* h0out = (t & 1) ? h0a : h0b;
            const float* h1in = (t == 0) ? h1z : (H1ALL + (long)(t-1)*NT*HD);
            float* h1out = H1ALL + (long)t*NT*HD;
            dec_gemm<0><<<gd, 256, GEMM_SMEM>>>(h0in, nullptr, WTh+O_L0WH, WTl+O_L0WH,
                                                X0, c0, h0out, t == 0);
            dec_gemm<1><<<gd, 256, GEMM_SMEM>>>(h0out, h1in, WTh+O_L1, WTl+O_L1,
                                                l1bp, c1, h1out, t == 0);
        }
        out_all<<<((long)OUTL*NT*32 + 255)/256, 256>>>(opW, opb, out);
    }
}